// round 2
// baseline (speedup 1.0000x reference)
#include <cuda_runtime.h>
#include <math.h>

// ---------------- problem constants ----------------
#define NB      64
#define DMODEL  2048
#define DINNER  4096
#define DSTATE  16
#define DTRANK  128
#define FE      512

// ---------------- scratch layout (floats) ----------------
#define OFF_F     0          // 64*512      conv relu-sum accumulator
#define OFF_FC    32768      // 64*2048     fc split-K accumulator
#define OFF_U     163840     // 128*2048    mamba input u (rows = b*2+l)
#define OFF_XZ    425984     // 128*8192    xz = u @ W_in^T
#define OFF_XS    1474560    // 128*4096    silu(conv1d(x))
#define OFF_XDBL  1998848    // 128*160     x_dbl
#define OFF_DT    2019328    // 128*4096    dt (softplus)
#define OFF_Y     2543616    // 64*4096     gated scan output at l=1
#define OFF_FEAT  2805760    // 64*2048     y @ W_out^T
#define OFF_WT    2936832    // 147*512     transposed conv weights [k][co]
#define SCRATCH_TOTAL 3012096

__device__ float g_scratch[SCRATCH_TOTAL];

// ---------------- utility kernels ----------------
__global__ void zero_kernel(float* p, int n) {
    int i = blockIdx.x * blockDim.x + threadIdx.x;
    if (i < n) p[i] = 0.f;
}

// conv_w (512,3,7,7) -> wT[k][co], k = ci*49+kh*7+kw
__global__ void prep_wt_kernel(const float* __restrict__ w, float* __restrict__ wT) {
    int i = blockIdx.x * blockDim.x + threadIdx.x;
    if (i < 512 * 147) {
        int co = i / 147, k = i - co * 147;
        wT[k * 512 + co] = w[i];
    }
}

// ---------------- conv 7x7 s4 p3 + bias + relu + spatial-sum ----------------
// grid (49, 64), block 128.  Each block: 8x8 output tile of one image.
__global__ void __launch_bounds__(128)
conv_relu_mean_kernel(const float* __restrict__ x, const float* __restrict__ wT,
                      const float* __restrict__ bias, float* __restrict__ f_accum)
{
    // s_w MUST be 16B-aligned: it is read via float4. (s_in's size is not a
    // multiple of 16B, so declaration order + explicit alignment both matter.)
    __shared__ __align__(16) float s_w[147][32];   // 18.8 KB, [k][co_local]
    __shared__ float s_in[3][35][35];               // 14.7 KB

    const int b    = blockIdx.y;
    const int tile = blockIdx.x;
    const int oh_base = (tile / 7) * 8;
    const int ow_base = (tile % 7) * 8;
    const int ih0 = oh_base * 4 - 3;
    const int iw0 = ow_base * 4 - 3;
    const int t = threadIdx.x;

    // input tile (with zero padding at borders)
    for (int i = t; i < 3 * 1225; i += 128) {
        int ci  = i / 1225;
        int rem = i - ci * 1225;
        int r = rem / 35;
        int c = rem - r * 35;
        int ih = ih0 + r, iw = iw0 + c;
        float v = 0.f;
        if ((unsigned)ih < 224u && (unsigned)iw < 224u)
            v = x[((b * 3 + ci) * 224 + ih) * 224 + iw];
        s_in[ci][r][c] = v;
    }

    const int pp  = t & 31;          // position-pair id (lane)
    const int cg  = t >> 5;          // warp id -> channel group
    const int ohl = (2 * pp) >> 3;   // local output row
    const int owl = (2 * pp) & 7;    // local output col (even)

    for (int co0 = 0; co0 < 512; co0 += 32) {
        __syncthreads();
        for (int i = t; i < 147 * 32; i += 128) {
            int k = i >> 5, col = i & 31;
            s_w[k][col] = wT[k * 512 + co0 + col];
        }
        __syncthreads();

        float acc0[8], acc1[8];
        #pragma unroll
        for (int j = 0; j < 8; ++j) { acc0[j] = 0.f; acc1[j] = 0.f; }

        for (int ci = 0; ci < 3; ++ci) {
            for (int kh = 0; kh < 7; ++kh) {
                const float* row = &s_in[ci][ohl * 4 + kh][owl * 4];
                const float* wk  = &s_w[ci * 49 + kh * 7][cg * 8];
                #pragma unroll
                for (int kw = 0; kw < 7; ++kw) {
                    float i0 = row[kw];
                    float i1 = row[4 + kw];
                    const float4* wp = reinterpret_cast<const float4*>(wk + kw * 32);
                    float4 wa = wp[0];
                    float4 wb = wp[1];
                    acc0[0] += i0 * wa.x; acc0[1] += i0 * wa.y;
                    acc0[2] += i0 * wa.z; acc0[3] += i0 * wa.w;
                    acc0[4] += i0 * wb.x; acc0[5] += i0 * wb.y;
                    acc0[6] += i0 * wb.z; acc0[7] += i0 * wb.w;
                    acc1[0] += i1 * wa.x; acc1[1] += i1 * wa.y;
                    acc1[2] += i1 * wa.z; acc1[3] += i1 * wa.w;
                    acc1[4] += i1 * wb.x; acc1[5] += i1 * wb.y;
                    acc1[6] += i1 * wb.z; acc1[7] += i1 * wb.w;
                }
            }
        }

        #pragma unroll
        for (int j = 0; j < 8; ++j) {
            int co = co0 + cg * 8 + j;
            float bv = bias[co];
            float v = fmaxf(acc0[j] + bv, 0.f) + fmaxf(acc1[j] + bv, 0.f);
            #pragma unroll
            for (int off = 16; off; off >>= 1)
                v += __shfl_down_sync(0xffffffffu, v, off);
            if (pp == 0) atomicAdd(&f_accum[b * 512 + co], v);
        }
    }
}

// ---------------- generic tiled SGEMM:  C[M,N] = act(a_scale*A[M,K] @ W[N,K]^T + bias) ----------
// BM=BN=64, BK=16, 128 threads (16x8). grid.z = split-K factor (atomic=1 required if >1).
__global__ void __launch_bounds__(128)
gemm_kernel(const float* __restrict__ A, int lda,
            const float* __restrict__ W,
            const float* __restrict__ bias,
            float* __restrict__ C, int ldc,
            int M, int N, int K, float a_scale,
            int act, int atomic)
{
    __shared__ float As[64][17];
    __shared__ float Ws[64][17];

    const int bm = blockIdx.y * 64;
    const int bn = blockIdx.x * 64;
    const int t  = threadIdx.x;
    const int tx = t & 15;   // N dim
    const int ty = t >> 4;   // M dim

    const int nz   = gridDim.z;
    const int kPer = (K + nz - 1) / nz;
    const int kBeg = blockIdx.z * kPer;
    const int kEnd = min(K, kBeg + kPer);

    float acc[8][4];
    #pragma unroll
    for (int i = 0; i < 8; ++i)
        #pragma unroll
        for (int j = 0; j < 4; ++j) acc[i][j] = 0.f;

    for (int k0 = kBeg; k0 < kEnd; k0 += 16) {
        for (int i = t; i < 1024; i += 128) {
            int r = i >> 4, c = i & 15;
            int gm = bm + r, gk = k0 + c;
            As[r][c] = (gm < M && gk < kEnd) ? A[gm * lda + gk] * a_scale : 0.f;
        }
        for (int i = t; i < 1024; i += 128) {
            int r = i >> 4, c = i & 15;
            int gn = bn + r, gk = k0 + c;
            Ws[r][c] = (gn < N && gk < kEnd) ? W[gn * K + gk] : 0.f;
        }
        __syncthreads();

        #pragma unroll
        for (int kk = 0; kk < 16; ++kk) {
            float a[8], wv[4];
            #pragma unroll
            for (int i = 0; i < 8; ++i) a[i] = As[ty + 8 * i][kk];
            #pragma unroll
            for (int j = 0; j < 4; ++j) wv[j] = Ws[tx + 16 * j][kk];
            #pragma unroll
            for (int i = 0; i < 8; ++i)
                #pragma unroll
                for (int j = 0; j < 4; ++j)
                    acc[i][j] += a[i] * wv[j];
        }
        __syncthreads();
    }

    #pragma unroll
    for (int i = 0; i < 8; ++i) {
        int m = bm + ty + 8 * i;
        if (m >= M) continue;
        #pragma unroll
        for (int j = 0; j < 4; ++j) {
            int n = bn + tx + 16 * j;
            if (n >= N) continue;
            float v = acc[i][j];
            if (atomic) {
                atomicAdd(&C[m * ldc + n], v);
            } else {
                if (bias) v += bias[n];
                if (act == 1) v = fmaxf(v, 0.f);
                else if (act == 2) v = (v > 20.f) ? v : log1pf(expf(v));
                C[m * ldc + n] = v;
            }
        }
    }
}

// ---------------- fc bias + relu + sequence build (reversal at l=0) ----------------
__global__ void build_u_kernel(const float* __restrict__ fcacc, const float* __restrict__ fcb,
                               float* __restrict__ u)
{
    int idx = blockIdx.x * blockDim.x + threadIdx.x;
    if (idx >= NB * DMODEL) return;
    int b = idx >> 11, d = idx & 2047;
    float v = fmaxf(fcacc[idx] + fcb[d], 0.f);
    u[(2 * b + 1) * DMODEL + d] = v;                 // l=1: forward
    u[(2 * b) * DMODEL + (DMODEL - 1 - d)] = v;      // l=0: reversed features
}

// ---------------- depthwise conv1d (L=2, causal k=4) + silu ----------------
__global__ void conv1d_silu_kernel(const float* __restrict__ xz, const float* __restrict__ w,
                                   const float* __restrict__ bias, float* __restrict__ xs)
{
    int idx = blockIdx.x * blockDim.x + threadIdx.x;
    if (idx >= NB * DINNER) return;
    int b = idx >> 12, e = idx & 4095;
    float x0 = xz[(2 * b) * (2 * DINNER) + e];
    float x1 = xz[(2 * b + 1) * (2 * DINNER) + e];
    float w2 = w[e * 4 + 2], w3 = w[e * 4 + 3];
    float bv = bias[e];
    float v0 = x0 * w3 + bv;
    float v1 = x0 * w2 + x1 * w3 + bv;
    xs[(2 * b) * DINNER + e]     = v0 / (1.f + expf(-v0));
    xs[(2 * b + 1) * DINNER + e] = v1 / (1.f + expf(-v1));
}

// ---------------- selective scan (L=2, closed form) + D skip + silu(z) gating ----------------
__global__ void scan_kernel(const float* __restrict__ xz, const float* __restrict__ xs,
                            const float* __restrict__ xdbl, const float* __restrict__ dt,
                            const float* __restrict__ A_log, const float* __restrict__ Dv,
                            float* __restrict__ y)
{
    int idx = blockIdx.x * blockDim.x + threadIdx.x;
    if (idx >= NB * DINNER) return;
    int b = idx >> 12, e = idx & 4095;

    float dt0 = dt[(2 * b) * DINNER + e];
    float dt1 = dt[(2 * b + 1) * DINNER + e];
    float x0  = xs[(2 * b) * DINNER + e];
    float x1  = xs[(2 * b + 1) * DINNER + e];
    float z1  = xz[(2 * b + 1) * (2 * DINNER) + DINNER + e];

    const float* bc0 = xdbl + (2 * b) * 160;
    const float* bc1 = xdbl + (2 * b + 1) * 160;

    float acc = 0.f;
    #pragma unroll
    for (int n = 0; n < DSTATE; ++n) {
        float Ae = -expf(A_log[e * DSTATE + n]);
        float h = dt0 * bc0[DTRANK + n] * x0;                 // step l=0 (h0 = 0)
        h = h * expf(dt1 * Ae) + dt1 * bc1[DTRANK + n] * x1;  // step l=1
        acc += h * bc1[DTRANK + DSTATE + n];
    }
    float yv = acc + x1 * Dv[e];
    float sg = z1 / (1.f + expf(-z1));
    y[b * DINNER + e] = yv * sg;
}

// ---------------- output heads ----------------
__global__ void heads_kernel(const float* __restrict__ feat,
                             const float* __restrict__ wxyz, const float* __restrict__ bxyz,
                             const float* __restrict__ wpqr, const float* __restrict__ bpqr,
                             float* __restrict__ out)
{
    int b = blockIdx.x / 7, j = blockIdx.x % 7;
    const float* wrow = (j < 3) ? (wxyz + j * DMODEL) : (wpqr + (j - 3) * DMODEL);
    float bias = (j < 3) ? bxyz[j] : bpqr[j - 3];

    float s = 0.f;
    for (int i = threadIdx.x; i < DMODEL; i += 128)
        s += feat[b * DMODEL + i] * wrow[i];

    __shared__ float red[4];
    #pragma unroll
    for (int off = 16; off; off >>= 1) s += __shfl_down_sync(0xffffffffu, s, off);
    if ((threadIdx.x & 31) == 0) red[threadIdx.x >> 5] = s;
    __syncthreads();
    if (threadIdx.x == 0)
        out[b * 7 + j] = red[0] + red[1] + red[2] + red[3] + bias;
}

// ---------------- launcher ----------------
extern "C" void kernel_launch(void* const* d_in, const int* in_sizes, int n_in,
                              void* d_out, int out_size)
{
    const float* x       = (const float*)d_in[0];
    const float* conv_w  = (const float*)d_in[1];
    const float* conv_b  = (const float*)d_in[2];
    const float* fc_w    = (const float*)d_in[3];
    const float* fc_b    = (const float*)d_in[4];
    const float* W_in    = (const float*)d_in[5];
    const float* c1w     = (const float*)d_in[6];
    const float* c1b     = (const float*)d_in[7];
    const float* W_xproj = (const float*)d_in[8];
    const float* W_dt    = (const float*)d_in[9];
    const float* b_dt    = (const float*)d_in[10];
    const float* A_log   = (const float*)d_in[11];
    const float* Dv      = (const float*)d_in[12];
    const float* W_out   = (const float*)d_in[13];
    const float* wxyz    = (const float*)d_in[14];
    const float* bxyz    = (const float*)d_in[15];
    const float* wpqr    = (const float*)d_in[16];
    const float* bpqr    = (const float*)d_in[17];
    float* out = (float*)d_out;

    void* sp = nullptr;
    cudaGetSymbolAddress(&sp, g_scratch);
    float* S = (float*)sp;

    float* f     = S + OFF_F;
    float* fcacc = S + OFF_FC;
    float* u     = S + OFF_U;
    float* xz    = S + OFF_XZ;
    float* xs    = S + OFF_XS;
    float* xdbl  = S + OFF_XDBL;
    float* dtb   = S + OFF_DT;
    float* y     = S + OFF_Y;
    float* feat  = S + OFF_FEAT;
    float* wT    = S + OFF_WT;

    // zero the atomic accumulators
    zero_kernel<<<(32768 + 255) / 256, 256>>>(f, 32768);
    zero_kernel<<<(131072 + 255) / 256, 256>>>(fcacc, 131072);
    zero_kernel<<<(20480 + 255) / 256, 256>>>(xdbl, 20480);
    zero_kernel<<<(131072 + 255) / 256, 256>>>(feat, 131072);

    // conv weight transpose
    prep_wt_kernel<<<(75264 + 255) / 256, 256>>>(conv_w, wT);

    // conv + relu + spatial sum
    conv_relu_mean_kernel<<<dim3(49, 64), 128>>>(x, wT, conv_b, f);

    // fc (mean scale folded in), split-K atomic; bias+relu in build_u
    gemm_kernel<<<dim3(32, 1, 4), 128>>>(f, 512, fc_w, nullptr, fcacc, 2048,
                                         64, 2048, 512, 1.f / 3136.f, 0, 1);
    build_u_kernel<<<512, 256>>>(fcacc, fc_b, u);

    // xz = u @ W_in^T   (128 x 8192 x 2048)
    gemm_kernel<<<dim3(128, 2, 1), 128>>>(u, 2048, W_in, nullptr, xz, 8192,
                                          128, 8192, 2048, 1.f, 0, 0);

    // depthwise conv1d + silu
    conv1d_silu_kernel<<<1024, 256>>>(xz, c1w, c1b, xs);

    // x_dbl = xs @ W_xproj^T  (128 x 160 x 4096), split-K atomic
    gemm_kernel<<<dim3(3, 2, 16), 128>>>(xs, 4096, W_xproj, nullptr, xdbl, 160,
                                         128, 160, 4096, 1.f, 0, 1);

    // dt = softplus(dt_low @ W_dt^T + b_dt)  (128 x 4096 x 128)
    gemm_kernel<<<dim3(64, 2, 1), 128>>>(xdbl, 160, W_dt, b_dt, dtb, 4096,
                                         128, 4096, 128, 1.f, 2, 0);

    // scan + gating -> y (l=1 only)
    scan_kernel<<<1024, 256>>>(xz, xs, xdbl, dtb, A_log, Dv, y);

    // feat = y @ W_out^T  (64 x 2048 x 4096), split-K atomic
    gemm_kernel<<<dim3(32, 1, 4), 128>>>(y, 4096, W_out, nullptr, feat, 2048,
                                         64, 2048, 4096, 1.f, 0, 1);

    // heads
    heads_kernel<<<448, 128>>>(feat, wxyz, bxyz, wpqr, bpqr, out);
}

// round 3
// speedup vs baseline: 1.5624x; 1.5624x over previous
#include <cuda_runtime.h>
#include <math.h>

// ---------------- problem constants ----------------
#define NB      64
#define DMODEL  2048
#define DINNER  4096
#define DSTATE  16
#define DTRANK  128
#define FE      512

// ---------------- scratch layout (floats) ----------------
#define OFF_F     0          // 64*512      conv relu-sum accumulator
#define OFF_FC    32768      // 64*2048     fc split-K accumulator
#define OFF_U     163840     // 128*2048    mamba input u (rows = b*2+l)
#define OFF_XZ    425984     // 128*8192    xz = u @ W_in^T
#define OFF_XS    1474560    // 128*4096    silu(conv1d(x))
#define OFF_XDBL  1998848    // 128*160     x_dbl
#define OFF_DT    2019328    // 128*4096    dt (softplus)
#define OFF_Y     2543616    // 64*4096     gated scan output at l=1
#define OFF_FEAT  2805760    // 64*2048     y @ W_out^T
#define OFF_WT    2936832    // 147*512     transposed conv weights [k][co]
#define SCRATCH_TOTAL 3012096

__device__ float g_scratch[SCRATCH_TOTAL];

// ---------------- packed f32x2 helpers (Blackwell) ----------------
__device__ __forceinline__ void ffma2(unsigned long long& d,
                                      unsigned long long a, unsigned long long b) {
    asm volatile("fma.rn.f32x2 %0, %1, %2, %0;" : "+l"(d) : "l"(a), "l"(b));
}
__device__ __forceinline__ unsigned long long dup2(float x) {
    unsigned int u = __float_as_uint(x);
    unsigned long long r;
    asm("mov.b64 %0, {%1, %2};" : "=l"(r) : "r"(u), "r"(u));
    return r;
}
__device__ __forceinline__ float2 unpack2(unsigned long long v) {
    unsigned int lo, hi;
    asm("mov.b64 {%0, %1}, %2;" : "=r"(lo), "=r"(hi) : "l"(v));
    return make_float2(__uint_as_float(lo), __uint_as_float(hi));
}

// ---------------- utility kernels ----------------
__global__ void zero_kernel(float* p, int n) {
    int i = blockIdx.x * blockDim.x + threadIdx.x;
    if (i < n) p[i] = 0.f;
}

// conv_w (512,3,7,7) -> wT[k][co], k = ci*49+kh*7+kw
__global__ void prep_wt_kernel(const float* __restrict__ w, float* __restrict__ wT) {
    int i = blockIdx.x * blockDim.x + threadIdx.x;
    if (i < 512 * 147) {
        int co = i / 147, k = i - co * 147;
        wT[k * 512 + co] = w[i];
    }
}

// ---------------- conv 7x7 s4 p3 + bias + relu + spatial-sum ----------------
// grid (49, 64), block 128.  Each block: 8x8 output tile of one image.
// Inner loop uses fma.rn.f32x2 (2 fp32 FMA / instruction).
__global__ void __launch_bounds__(128)
conv_relu_mean_kernel(const float* __restrict__ x, const float* __restrict__ wT,
                      const float* __restrict__ bias, float* __restrict__ f_accum)
{
    __shared__ __align__(16) float s_w[147][32];   // 18.8 KB, [k][co_local]
    __shared__ float s_in[3][35][35];               // 14.7 KB

    const int b    = blockIdx.y;
    const int tile = blockIdx.x;
    const int oh_base = (tile / 7) * 8;
    const int ow_base = (tile % 7) * 8;
    const int ih0 = oh_base * 4 - 3;
    const int iw0 = ow_base * 4 - 3;
    const int t = threadIdx.x;

    // input tile (with zero padding at borders)
    for (int i = t; i < 3 * 1225; i += 128) {
        int ci  = i / 1225;
        int rem = i - ci * 1225;
        int r = rem / 35;
        int c = rem - r * 35;
        int ih = ih0 + r, iw = iw0 + c;
        float v = 0.f;
        if ((unsigned)ih < 224u && (unsigned)iw < 224u)
            v = x[((b * 3 + ci) * 224 + ih) * 224 + iw];
        s_in[ci][r][c] = v;
    }

    const int pp  = t & 31;          // position-pair id (lane)
    const int cg  = t >> 5;          // warp id -> channel group (8 channels)
    const int ohl = (2 * pp) >> 3;   // local output row
    const int owl = (2 * pp) & 7;    // local output col (even)

    for (int co0 = 0; co0 < 512; co0 += 32) {
        __syncthreads();
        for (int i = t; i < 147 * 32; i += 128) {
            int k = i >> 5, col = i & 31;
            s_w[k][col] = wT[k * 512 + co0 + col];
        }
        __syncthreads();

        // packed accumulators: 4 channel-pairs x 2 positions
        unsigned long long a0[4], a1[4];
        #pragma unroll
        for (int j = 0; j < 4; ++j) { a0[j] = 0ull; a1[j] = 0ull; }

        #pragma unroll
        for (int ci = 0; ci < 3; ++ci) {
            #pragma unroll
            for (int kh = 0; kh < 7; ++kh) {
                const float* row = &s_in[ci][ohl * 4 + kh][owl * 4];
                // hoist the 11 input values this (ci,kh) needs
                float rv[11];
                #pragma unroll
                for (int q = 0; q < 11; ++q) rv[q] = row[q];
                const float* wk = &s_w[ci * 49 + kh * 7][cg * 8];
                #pragma unroll
                for (int kw = 0; kw < 7; ++kw) {
                    unsigned long long pi0 = dup2(rv[kw]);
                    unsigned long long pi1 = dup2(rv[kw + 4]);
                    const ulonglong2* wp =
                        reinterpret_cast<const ulonglong2*>(wk + kw * 32);
                    ulonglong2 wlo = wp[0];   // channels 0-3 (2 pairs)
                    ulonglong2 whi = wp[1];   // channels 4-7 (2 pairs)
                    ffma2(a0[0], pi0, wlo.x); ffma2(a0[1], pi0, wlo.y);
                    ffma2(a0[2], pi0, whi.x); ffma2(a0[3], pi0, whi.y);
                    ffma2(a1[0], pi1, wlo.x); ffma2(a1[1], pi1, wlo.y);
                    ffma2(a1[2], pi1, whi.x); ffma2(a1[3], pi1, whi.y);
                }
            }
        }

        #pragma unroll
        for (int j = 0; j < 4; ++j) {
            float2 p0 = unpack2(a0[j]);
            float2 p1 = unpack2(a1[j]);
            int co = co0 + cg * 8 + 2 * j;
            float b0 = bias[co], b1 = bias[co + 1];
            float v0 = fmaxf(p0.x + b0, 0.f) + fmaxf(p1.x + b0, 0.f);
            float v1 = fmaxf(p0.y + b1, 0.f) + fmaxf(p1.y + b1, 0.f);
            #pragma unroll
            for (int off = 16; off; off >>= 1) {
                v0 += __shfl_down_sync(0xffffffffu, v0, off);
                v1 += __shfl_down_sync(0xffffffffu, v1, off);
            }
            if (pp == 0) {
                atomicAdd(&f_accum[b * 512 + co], v0);
                atomicAdd(&f_accum[b * 512 + co + 1], v1);
            }
        }
    }
}

// ---------------- tiled SGEMM with f32x2:  C[M,N] = act(a_scale*A[M,K] @ W[N,K]^T + bias)
// BM=BN=64, BK=16, 128 threads. k-major smem, float4 global loads.
// Requirements (all call sites satisfy): K % 16 == 0, lda % 4 == 0,
// M covered exactly by 64-row tiles. N guarded.
__global__ void __launch_bounds__(128)
gemm_kernel(const float* __restrict__ A, int lda,
            const float* __restrict__ W,
            const float* __restrict__ bias,
            float* __restrict__ C, int ldc,
            int M, int N, int K, float a_scale,
            int act, int atomic)
{
    __shared__ __align__(16) float As[16][68];   // k-major
    __shared__ __align__(16) float Ws[16][68];

    const int bm = blockIdx.y * 64;
    const int bn = blockIdx.x * 64;
    const int t  = threadIdx.x;
    const int tx = t & 15;   // n group (4 cols)
    const int ty = t >> 4;   // m group (8 rows)

    const int nz   = gridDim.z;
    const int kPer = K / nz;           // all call sites: K % nz == 0, kPer % 16 == 0
    const int kBeg = blockIdx.z * kPer;
    const int kEnd = kBeg + kPer;

    // acc[m-pair][n] : m pairs packed in f32x2
    unsigned long long acc[4][4];
    #pragma unroll
    for (int i = 0; i < 4; ++i)
        #pragma unroll
        for (int j = 0; j < 4; ++j) acc[i][j] = 0ull;

    for (int k0 = kBeg; k0 < kEnd; k0 += 16) {
        #pragma unroll
        for (int it = 0; it < 2; ++it) {
            int idx = t + it * 128;        // 0..255
            int r = idx >> 2, c4 = idx & 3;
            // A tile
            {
                float4 v = *reinterpret_cast<const float4*>(
                    A + (size_t)(bm + r) * lda + k0 + c4 * 4);
                As[c4 * 4 + 0][r] = v.x * a_scale;
                As[c4 * 4 + 1][r] = v.y * a_scale;
                As[c4 * 4 + 2][r] = v.z * a_scale;
                As[c4 * 4 + 3][r] = v.w * a_scale;
            }
            // W tile (row-guarded for N=160 case)
            {
                int gn = bn + r;
                float4 v = make_float4(0.f, 0.f, 0.f, 0.f);
                if (gn < N)
                    v = *reinterpret_cast<const float4*>(
                        W + (size_t)gn * K + k0 + c4 * 4);
                Ws[c4 * 4 + 0][r] = v.x;
                Ws[c4 * 4 + 1][r] = v.y;
                Ws[c4 * 4 + 2][r] = v.z;
                Ws[c4 * 4 + 3][r] = v.w;
            }
        }
        __syncthreads();

        #pragma unroll
        for (int kk = 0; kk < 16; ++kk) {
            const ulonglong2* ap =
                reinterpret_cast<const ulonglong2*>(&As[kk][ty * 8]);
            ulonglong2 am01 = ap[0];   // m pairs (0,1),(2,3)
            ulonglong2 am23 = ap[1];   // m pairs (4,5),(6,7)
            float4 wv = *reinterpret_cast<const float4*>(&Ws[kk][tx * 4]);
            unsigned long long pw0 = dup2(wv.x);
            unsigned long long pw1 = dup2(wv.y);
            unsigned long long pw2 = dup2(wv.z);
            unsigned long long pw3 = dup2(wv.w);
            ffma2(acc[0][0], am01.x, pw0); ffma2(acc[0][1], am01.x, pw1);
            ffma2(acc[0][2], am01.x, pw2); ffma2(acc[0][3], am01.x, pw3);
            ffma2(acc[1][0], am01.y, pw0); ffma2(acc[1][1], am01.y, pw1);
            ffma2(acc[1][2], am01.y, pw2); ffma2(acc[1][3], am01.y, pw3);
            ffma2(acc[2][0], am23.x, pw0); ffma2(acc[2][1], am23.x, pw1);
            ffma2(acc[2][2], am23.x, pw2); ffma2(acc[2][3], am23.x, pw3);
            ffma2(acc[3][0], am23.y, pw0); ffma2(acc[3][1], am23.y, pw1);
            ffma2(acc[3][2], am23.y, pw2); ffma2(acc[3][3], am23.y, pw3);
        }
        __syncthreads();
    }

    const int nbase = bn + tx * 4;
    #pragma unroll
    for (int i = 0; i < 4; ++i) {
        int m0 = bm + ty * 8 + 2 * i;     // pair rows m0, m0+1
        float2 c0 = unpack2(acc[i][0]);
        float2 c1 = unpack2(acc[i][1]);
        float2 c2 = unpack2(acc[i][2]);
        float2 c3 = unpack2(acc[i][3]);
        float lo[4] = {c0.x, c1.x, c2.x, c3.x};
        float hi[4] = {c0.y, c1.y, c2.y, c3.y};
        if (atomic) {
            #pragma unroll
            for (int j = 0; j < 4; ++j) {
                int n = nbase + j;
                if (n < N) {
                    atomicAdd(&C[(size_t)m0 * ldc + n], lo[j]);
                    atomicAdd(&C[(size_t)(m0 + 1) * ldc + n], hi[j]);
                }
            }
        } else {
            #pragma unroll
            for (int j = 0; j < 4; ++j) {
                int n = nbase + j;
                if (n >= N) continue;
                float bv = bias ? bias[n] : 0.f;
                float v0 = lo[j] + bv, v1 = hi[j] + bv;
                if (act == 1) { v0 = fmaxf(v0, 0.f); v1 = fmaxf(v1, 0.f); }
                else if (act == 2) {
                    v0 = (v0 > 20.f) ? v0 : log1pf(expf(v0));
                    v1 = (v1 > 20.f) ? v1 : log1pf(expf(v1));
                }
                C[(size_t)m0 * ldc + n] = v0;
                C[(size_t)(m0 + 1) * ldc + n] = v1;
            }
        }
    }
}

// ---------------- fc bias + relu + sequence build (reversal at l=0) ----------------
__global__ void build_u_kernel(const float* __restrict__ fcacc, const float* __restrict__ fcb,
                               float* __restrict__ u)
{
    int idx = blockIdx.x * blockDim.x + threadIdx.x;
    if (idx >= NB * DMODEL) return;
    int b = idx >> 11, d = idx & 2047;
    float v = fmaxf(fcacc[idx] + fcb[d], 0.f);
    u[(2 * b + 1) * DMODEL + d] = v;                 // l=1: forward
    u[(2 * b) * DMODEL + (DMODEL - 1 - d)] = v;      // l=0: reversed features
}

// ---------------- depthwise conv1d (L=2, causal k=4) + silu ----------------
__global__ void conv1d_silu_kernel(const float* __restrict__ xz, const float* __restrict__ w,
                                   const float* __restrict__ bias, float* __restrict__ xs)
{
    int idx = blockIdx.x * blockDim.x + threadIdx.x;
    if (idx >= NB * DINNER) return;
    int b = idx >> 12, e = idx & 4095;
    float x0 = xz[(2 * b) * (2 * DINNER) + e];
    float x1 = xz[(2 * b + 1) * (2 * DINNER) + e];
    float w2 = w[e * 4 + 2], w3 = w[e * 4 + 3];
    float bv = bias[e];
    float v0 = x0 * w3 + bv;
    float v1 = x0 * w2 + x1 * w3 + bv;
    xs[(2 * b) * DINNER + e]     = v0 / (1.f + expf(-v0));
    xs[(2 * b + 1) * DINNER + e] = v1 / (1.f + expf(-v1));
}

// ---------------- selective scan (L=2, closed form) + D skip + silu(z) gating ----------------
__global__ void scan_kernel(const float* __restrict__ xz, const float* __restrict__ xs,
                            const float* __restrict__ xdbl, const float* __restrict__ dt,
                            const float* __restrict__ A_log, const float* __restrict__ Dv,
                            float* __restrict__ y)
{
    int idx = blockIdx.x * blockDim.x + threadIdx.x;
    if (idx >= NB * DINNER) return;
    int b = idx >> 12, e = idx & 4095;

    float dt0 = dt[(2 * b) * DINNER + e];
    float dt1 = dt[(2 * b + 1) * DINNER + e];
    float x0  = xs[(2 * b) * DINNER + e];
    float x1  = xs[(2 * b + 1) * DINNER + e];
    float z1  = xz[(2 * b + 1) * (2 * DINNER) + DINNER + e];

    const float* bc0 = xdbl + (2 * b) * 160;
    const float* bc1 = xdbl + (2 * b + 1) * 160;

    float acc = 0.f;
    #pragma unroll
    for (int n = 0; n < DSTATE; ++n) {
        float Ae = -expf(A_log[e * DSTATE + n]);
        float h = dt0 * bc0[DTRANK + n] * x0;                 // step l=0 (h0 = 0)
        h = h * expf(dt1 * Ae) + dt1 * bc1[DTRANK + n] * x1;  // step l=1
        acc += h * bc1[DTRANK + DSTATE + n];
    }
    float yv = acc + x1 * Dv[e];
    float sg = z1 / (1.f + expf(-z1));
    y[b * DINNER + e] = yv * sg;
}

// ---------------- output heads ----------------
__global__ void heads_kernel(const float* __restrict__ feat,
                             const float* __restrict__ wxyz, const float* __restrict__ bxyz,
                             const float* __restrict__ wpqr, const float* __restrict__ bpqr,
                             float* __restrict__ out)
{
    int b = blockIdx.x / 7, j = blockIdx.x % 7;
    const float* wrow = (j < 3) ? (wxyz + j * DMODEL) : (wpqr + (j - 3) * DMODEL);
    float bias = (j < 3) ? bxyz[j] : bpqr[j - 3];

    float s = 0.f;
    for (int i = threadIdx.x; i < DMODEL; i += 128)
        s += feat[b * DMODEL + i] * wrow[i];

    __shared__ float red[4];
    #pragma unroll
    for (int off = 16; off; off >>= 1) s += __shfl_down_sync(0xffffffffu, s, off);
    if ((threadIdx.x & 31) == 0) red[threadIdx.x >> 5] = s;
    __syncthreads();
    if (threadIdx.x == 0)
        out[b * 7 + j] = red[0] + red[1] + red[2] + red[3] + bias;
}

// ---------------- launcher ----------------
extern "C" void kernel_launch(void* const* d_in, const int* in_sizes, int n_in,
                              void* d_out, int out_size)
{
    const float* x       = (const float*)d_in[0];
    const float* conv_w  = (const float*)d_in[1];
    const float* conv_b  = (const float*)d_in[2];
    const float* fc_w    = (const float*)d_in[3];
    const float* fc_b    = (const float*)d_in[4];
    const float* W_in    = (const float*)d_in[5];
    const float* c1w     = (const float*)d_in[6];
    const float* c1b     = (const float*)d_in[7];
    const float* W_xproj = (const float*)d_in[8];
    const float* W_dt    = (const float*)d_in[9];
    const float* b_dt    = (const float*)d_in[10];
    const float* A_log   = (const float*)d_in[11];
    const float* Dv      = (const float*)d_in[12];
    const float* W_out   = (const float*)d_in[13];
    const float* wxyz    = (const float*)d_in[14];
    const float* bxyz    = (const float*)d_in[15];
    const float* wpqr    = (const float*)d_in[16];
    const float* bpqr    = (const float*)d_in[17];
    float* out = (float*)d_out;

    void* sp = nullptr;
    cudaGetSymbolAddress(&sp, g_scratch);
    float* S = (float*)sp;

    float* f     = S + OFF_F;
    float* fcacc = S + OFF_FC;
    float* u     = S + OFF_U;
    float* xz    = S + OFF_XZ;
    float* xs    = S + OFF_XS;
    float* xdbl  = S + OFF_XDBL;
    float* dtb   = S + OFF_DT;
    float* y     = S + OFF_Y;
    float* feat  = S + OFF_FEAT;
    float* wT    = S + OFF_WT;

    // zero the atomic accumulators (f+fcacc contiguous)
    zero_kernel<<<(163840 + 255) / 256, 256>>>(f, 163840);
    zero_kernel<<<(20480 + 255) / 256, 256>>>(xdbl, 20480);
    zero_kernel<<<(131072 + 255) / 256, 256>>>(feat, 131072);

    // conv weight transpose
    prep_wt_kernel<<<(75264 + 255) / 256, 256>>>(conv_w, wT);

    // conv + relu + spatial sum
    conv_relu_mean_kernel<<<dim3(49, 64), 128>>>(x, wT, conv_b, f);

    // fc (mean scale folded in), split-K atomic; bias+relu in build_u
    gemm_kernel<<<dim3(32, 1, 4), 128>>>(f, 512, fc_w, nullptr, fcacc, 2048,
                                         64, 2048, 512, 1.f / 3136.f, 0, 1);
    build_u_kernel<<<512, 256>>>(fcacc, fc_b, u);

    // xz = u @ W_in^T   (128 x 8192 x 2048)
    gemm_kernel<<<dim3(128, 2, 1), 128>>>(u, 2048, W_in, nullptr, xz, 8192,
                                          128, 8192, 2048, 1.f, 0, 0);

    // depthwise conv1d + silu
    conv1d_silu_kernel<<<1024, 256>>>(xz, c1w, c1b, xs);

    // x_dbl = xs @ W_xproj^T  (128 x 160 x 4096), split-K atomic
    gemm_kernel<<<dim3(3, 2, 16), 128>>>(xs, 4096, W_xproj, nullptr, xdbl, 160,
                                         128, 160, 4096, 1.f, 0, 1);

    // dt = softplus(dt_low @ W_dt^T + b_dt)  (128 x 4096 x 128)
    gemm_kernel<<<dim3(64, 2, 1), 128>>>(xdbl, 160, W_dt, b_dt, dtb, 4096,
                                         128, 4096, 128, 1.f, 2, 0);

    // scan + gating -> y (l=1 only)
    scan_kernel<<<1024, 256>>>(xz, xs, xdbl, dtb, A_log, Dv, y);

    // feat = y @ W_out^T  (64 x 2048 x 4096), split-K atomic
    gemm_kernel<<<dim3(32, 1, 4), 128>>>(y, 4096, W_out, nullptr, feat, 2048,
                                         64, 2048, 4096, 1.f, 0, 1);

    // heads
    heads_kernel<<<448, 128>>>(feat, wxyz, bxyz, wpqr, bpqr, out);
}

// round 5
// speedup vs baseline: 2.0559x; 1.3158x over previous
#include <cuda_runtime.h>
#include <math.h>

// ---------------- problem constants ----------------
#define NB      64
#define DMODEL  2048
#define DINNER  4096
#define DSTATE  16
#define DTRANK  128
#define FE      512

// ---------------- scratch layout (floats) ----------------
#define OFF_F     0          // 64*512      conv relu-sum accumulator
#define OFF_FC    32768      // 64*2048     fc split-K accumulator
#define OFF_U     163840     // 128*2048    mamba input u (rows = b*2+l)
#define OFF_XZ    425984     // 128*8192    xz = u @ W_in^T
#define OFF_XS    1474560    // 128*4096    silu(conv1d(x))
#define OFF_XDBL  1998848    // 128*160     x_dbl
#define OFF_DT    2019328    // 128*4096    dt (softplus)
#define OFF_Y     2543616    // 64*4096     gated scan output at l=1
#define OFF_FEAT  2805760    // 64*2048     y @ W_out^T
#define OFF_WT    2936832    // 147*512     transposed conv weights [k][co]
#define SCRATCH_TOTAL 3012096

__device__ float g_scratch[SCRATCH_TOTAL];

// conv_tc dynamic smem layout (bytes)
#define CONV_SMEM_W     0                    // 152*72 unsigned = 43776
#define CONV_SMEM_ACC   43776                // 2*512 float     = 4096
#define CONV_SMEM_IN    47872                // 2*3*35*35 float = 29400
#define CONV_SMEM_TOTAL 77272

// ---------------- packed f32x2 helpers (Blackwell) ----------------
__device__ __forceinline__ void ffma2(unsigned long long& d,
                                      unsigned long long a, unsigned long long b) {
    asm volatile("fma.rn.f32x2 %0, %1, %2, %0;" : "+l"(d) : "l"(a), "l"(b));
}
__device__ __forceinline__ unsigned long long dup2(float x) {
    unsigned int u = __float_as_uint(x);
    unsigned long long r;
    asm("mov.b64 %0, {%1, %2};" : "=l"(r) : "r"(u), "r"(u));
    return r;
}
__device__ __forceinline__ float2 unpack2(unsigned long long v) {
    unsigned int lo, hi;
    asm("mov.b64 {%0, %1}, %2;" : "=r"(lo), "=r"(hi) : "l"(v));
    return make_float2(__uint_as_float(lo), __uint_as_float(hi));
}

// ---------------- tf32 mma helpers ----------------
__device__ __forceinline__ unsigned f2tf32(float v) {
    unsigned r;
    asm("cvt.rna.tf32.f32 %0, %1;" : "=r"(r) : "f"(v));
    return r;
}
__device__ __forceinline__ void mma_tf32(float c[4],
                                         unsigned a0, unsigned a1, unsigned a2, unsigned a3,
                                         unsigned b0, unsigned b1) {
    asm volatile(
        "mma.sync.aligned.m16n8k8.row.col.f32.tf32.tf32.f32 "
        "{%0,%1,%2,%3}, {%4,%5,%6,%7}, {%8,%9}, {%0,%1,%2,%3};"
        : "+f"(c[0]), "+f"(c[1]), "+f"(c[2]), "+f"(c[3])
        : "r"(a0), "r"(a1), "r"(a2), "r"(a3), "r"(b0), "r"(b1));
}

// ---------------- utility kernels ----------------
__global__ void zero_kernel(float* p, int n) {
    int i = blockIdx.x * blockDim.x + threadIdx.x;
    if (i < n) p[i] = 0.f;
}

// conv_w (512,3,7,7) -> wT[k][co], k = ci*49+kh*7+kw
__global__ void prep_wt_kernel(const float* __restrict__ w, float* __restrict__ wT) {
    int i = blockIdx.x * blockDim.x + threadIdx.x;
    if (i < 512 * 147) {
        int co = i / 147, k = i - co * 147;
        wT[k * 512 + co] = w[i];
    }
}

// ---------------- conv 7x7 s4 p3 + bias + relu + spatial-sum (tensor cores) ----------
// grid (49, 32), block 256 (8 warps). Each block: 8x8 output tile of TWO images.
// Implicit GEMM: M=128 (2 img x 64 pos), N=512 (chunks of 64), K=147 (pad 152).
// Dynamic smem (77.3 KB): s_w tf32 chunk, s_acc, s_in raw tiles.
__global__ void __launch_bounds__(256)
conv_tc_kernel(const float* __restrict__ x, const float* __restrict__ wT,
               const float* __restrict__ bias, float* __restrict__ f_accum)
{
    extern __shared__ __align__(16) char smem[];
    unsigned* s_w  = reinterpret_cast<unsigned*>(smem + CONV_SMEM_W);    // [152][72]
    float*    s_acc = reinterpret_cast<float*>(smem + CONV_SMEM_ACC);    // [2][512]
    float*    s_in  = reinterpret_cast<float*>(smem + CONV_SMEM_IN);     // [2][3][35][35]

    const int t    = threadIdx.x;
    const int tile = blockIdx.x;
    const int bp   = blockIdx.y;            // image pair
    const int oh_base = (tile / 7) * 8;
    const int ow_base = (tile % 7) * 8;
    const int ih0 = oh_base * 4 - 3;
    const int iw0 = ow_base * 4 - 3;

    for (int i = t; i < 1024; i += 256) s_acc[i] = 0.f;

    // input tiles for both images (zero-padded borders)
    for (int i = t; i < 2 * 3 * 1225; i += 256) {
        int img = i / 3675;
        int rem = i - img * 3675;
        int ci  = rem / 1225; rem -= ci * 1225;
        int r = rem / 35, c = rem - (rem / 35) * 35;
        int ih = ih0 + r, iw = iw0 + c;
        float v = 0.f;
        int b = bp * 2 + img;
        if ((unsigned)ih < 224u && (unsigned)iw < 224u)
            v = x[((b * 3 + ci) * 224 + ih) * 224 + iw];
        s_in[(img * 3 + ci) * 1225 + r * 35 + c] = v;
    }

    const int lane = t & 31;
    const int w    = t >> 5;                // warp 0..7
    const int img  = w >> 2;                // image within pair
    const int q    = lane >> 2;             // group id 0..7
    const int j    = lane & 3;              // thread-in-group
    const int ya = (w & 3) * 8;             // (2*(w&3))*4
    const int xb = q * 4;
    const float* my_in = s_in + img * 3675;

    for (int n0 = 0; n0 < 512; n0 += 64) {
        __syncthreads();
        // stage weight chunk as tf32 (zero-padded k >= 147)
        for (int i = t; i < 152 * 64; i += 256) {
            int k = i >> 6, n = i & 63;
            float v = (k < 147) ? wT[k * 512 + n0 + n] : 0.f;
            s_w[k * 72 + n] = f2tf32(v);
        }
        __syncthreads();

        float c[8][4];
        #pragma unroll
        for (int nf = 0; nf < 8; ++nf)
            #pragma unroll
            for (int u2 = 0; u2 < 4; ++u2) c[nf][u2] = 0.f;

        for (int ks = 0; ks < 19; ++ks) {
            int k0 = ks * 8 + j;
            int k1 = k0 + 4;
            int kk0 = min(k0, 146), kk1 = min(k1, 146);
            int ci0 = kk0 / 49, r0 = kk0 - ci0 * 49;
            int kh0 = r0 / 7,  kw0 = r0 - kh0 * 7;
            int ci1 = kk1 / 49, r1 = kk1 - ci1 * 49;
            int kh1 = r1 / 7,  kw1 = r1 - kh1 * 7;

            unsigned a0 = f2tf32(my_in[ci0 * 1225 + (ya + kh0) * 35 + xb + kw0]);
            unsigned a1 = f2tf32(my_in[ci0 * 1225 + (ya + 4 + kh0) * 35 + xb + kw0]);
            unsigned a2 = f2tf32(my_in[ci1 * 1225 + (ya + kh1) * 35 + xb + kw1]);
            unsigned a3 = f2tf32(my_in[ci1 * 1225 + (ya + 4 + kh1) * 35 + xb + kw1]);

            #pragma unroll
            for (int nf = 0; nf < 8; ++nf) {
                unsigned b0 = s_w[k0 * 72 + nf * 8 + q];
                unsigned b1 = s_w[k1 * 72 + nf * 8 + q];
                mma_tf32(c[nf], a0, a1, a2, a3, b0, b1);
            }
        }

        // epilogue: bias + relu per position, reduce over positions
        #pragma unroll
        for (int nf = 0; nf < 8; ++nf) {
            int ca = n0 + nf * 8 + 2 * j;
            float bva = bias[ca], bvb = bias[ca + 1];
            float va = fmaxf(c[nf][0] + bva, 0.f) + fmaxf(c[nf][2] + bva, 0.f);
            float vb = fmaxf(c[nf][1] + bvb, 0.f) + fmaxf(c[nf][3] + bvb, 0.f);
            #pragma unroll
            for (int off = 16; off >= 4; off >>= 1) {
                va += __shfl_down_sync(0xffffffffu, va, off);
                vb += __shfl_down_sync(0xffffffffu, vb, off);
            }
            if (lane < 4) {
                atomicAdd(&s_acc[img * 512 + ca], va);
                atomicAdd(&s_acc[img * 512 + ca + 1], vb);
            }
        }
    }

    __syncthreads();
    for (int i = t; i < 1024; i += 256) {
        int im = i >> 9, ch = i & 511;
        atomicAdd(&f_accum[(bp * 2 + im) * 512 + ch], s_acc[im * 512 + ch]);
    }
}

// ---------------- tiled SGEMM with f32x2:  C[M,N] = act(a_scale*A[M,K] @ W[N,K]^T + bias)
// BM=BN=64, BK=16, 128 threads. k-major smem, float4 global loads.
// Requirements: K % 16 == 0, lda % 4 == 0, M covered exactly by 64-row tiles. N guarded.
__global__ void __launch_bounds__(128)
gemm_kernel(const float* __restrict__ A, int lda,
            const float* __restrict__ W,
            const float* __restrict__ bias,
            float* __restrict__ C, int ldc,
            int M, int N, int K, float a_scale,
            int act, int atomic)
{
    __shared__ __align__(16) float As[16][68];   // k-major
    __shared__ __align__(16) float Ws[16][68];

    const int bm = blockIdx.y * 64;
    const int bn = blockIdx.x * 64;
    const int t  = threadIdx.x;
    const int tx = t & 15;   // n group (4 cols)
    const int ty = t >> 4;   // m group (8 rows)

    const int nz   = gridDim.z;
    const int kPer = K / nz;
    const int kBeg = blockIdx.z * kPer;
    const int kEnd = kBeg + kPer;

    unsigned long long acc[4][4];
    #pragma unroll
    for (int i = 0; i < 4; ++i)
        #pragma unroll
        for (int j = 0; j < 4; ++j) acc[i][j] = 0ull;

    for (int k0 = kBeg; k0 < kEnd; k0 += 16) {
        #pragma unroll
        for (int it = 0; it < 2; ++it) {
            int idx = t + it * 128;
            int r = idx >> 2, c4 = idx & 3;
            {
                float4 v = *reinterpret_cast<const float4*>(
                    A + (size_t)(bm + r) * lda + k0 + c4 * 4);
                As[c4 * 4 + 0][r] = v.x * a_scale;
                As[c4 * 4 + 1][r] = v.y * a_scale;
                As[c4 * 4 + 2][r] = v.z * a_scale;
                As[c4 * 4 + 3][r] = v.w * a_scale;
            }
            {
                int gn = bn + r;
                float4 v = make_float4(0.f, 0.f, 0.f, 0.f);
                if (gn < N)
                    v = *reinterpret_cast<const float4*>(
                        W + (size_t)gn * K + k0 + c4 * 4);
                Ws[c4 * 4 + 0][r] = v.x;
                Ws[c4 * 4 + 1][r] = v.y;
                Ws[c4 * 4 + 2][r] = v.z;
                Ws[c4 * 4 + 3][r] = v.w;
            }
        }
        __syncthreads();

        #pragma unroll
        for (int kk = 0; kk < 16; ++kk) {
            const ulonglong2* ap =
                reinterpret_cast<const ulonglong2*>(&As[kk][ty * 8]);
            ulonglong2 am01 = ap[0];
            ulonglong2 am23 = ap[1];
            float4 wv = *reinterpret_cast<const float4*>(&Ws[kk][tx * 4]);
            unsigned long long pw0 = dup2(wv.x);
            unsigned long long pw1 = dup2(wv.y);
            unsigned long long pw2 = dup2(wv.z);
            unsigned long long pw3 = dup2(wv.w);
            ffma2(acc[0][0], am01.x, pw0); ffma2(acc[0][1], am01.x, pw1);
            ffma2(acc[0][2], am01.x, pw2); ffma2(acc[0][3], am01.x, pw3);
            ffma2(acc[1][0], am01.y, pw0); ffma2(acc[1][1], am01.y, pw1);
            ffma2(acc[1][2], am01.y, pw2); ffma2(acc[1][3], am01.y, pw3);
            ffma2(acc[2][0], am23.x, pw0); ffma2(acc[2][1], am23.x, pw1);
            ffma2(acc[2][2], am23.x, pw2); ffma2(acc[2][3], am23.x, pw3);
            ffma2(acc[3][0], am23.y, pw0); ffma2(acc[3][1], am23.y, pw1);
            ffma2(acc[3][2], am23.y, pw2); ffma2(acc[3][3], am23.y, pw3);
        }
        __syncthreads();
    }

    const int nbase = bn + tx * 4;
    #pragma unroll
    for (int i = 0; i < 4; ++i) {
        int m0 = bm + ty * 8 + 2 * i;
        float2 c0 = unpack2(acc[i][0]);
        float2 c1 = unpack2(acc[i][1]);
        float2 c2 = unpack2(acc[i][2]);
        float2 c3 = unpack2(acc[i][3]);
        float lo[4] = {c0.x, c1.x, c2.x, c3.x};
        float hi[4] = {c0.y, c1.y, c2.y, c3.y};
        if (atomic) {
            #pragma unroll
            for (int j = 0; j < 4; ++j) {
                int n = nbase + j;
                if (n < N) {
                    atomicAdd(&C[(size_t)m0 * ldc + n], lo[j]);
                    atomicAdd(&C[(size_t)(m0 + 1) * ldc + n], hi[j]);
                }
            }
        } else {
            #pragma unroll
            for (int j = 0; j < 4; ++j) {
                int n = nbase + j;
                if (n >= N) continue;
                float bv = bias ? bias[n] : 0.f;
                float v0 = lo[j] + bv, v1 = hi[j] + bv;
                if (act == 1) { v0 = fmaxf(v0, 0.f); v1 = fmaxf(v1, 0.f); }
                else if (act == 2) {
                    v0 = (v0 > 20.f) ? v0 : log1pf(expf(v0));
                    v1 = (v1 > 20.f) ? v1 : log1pf(expf(v1));
                }
                C[(size_t)m0 * ldc + n] = v0;
                C[(size_t)(m0 + 1) * ldc + n] = v1;
            }
        }
    }
}

// ---------------- fc bias + relu + sequence build (reversal at l=0) ----------------
__global__ void build_u_kernel(const float* __restrict__ fcacc, const float* __restrict__ fcb,
                               float* __restrict__ u)
{
    int idx = blockIdx.x * blockDim.x + threadIdx.x;
    if (idx >= NB * DMODEL) return;
    int b = idx >> 11, d = idx & 2047;
    float v = fmaxf(fcacc[idx] + fcb[d], 0.f);
    u[(2 * b + 1) * DMODEL + d] = v;
    u[(2 * b) * DMODEL + (DMODEL - 1 - d)] = v;
}

// ---------------- depthwise conv1d (L=2, causal k=4) + silu ----------------
__global__ void conv1d_silu_kernel(const float* __restrict__ xz, const float* __restrict__ w,
                                   const float* __restrict__ bias, float* __restrict__ xs)
{
    int idx = blockIdx.x * blockDim.x + threadIdx.x;
    if (idx >= NB * DINNER) return;
    int b = idx >> 12, e = idx & 4095;
    float x0 = xz[(2 * b) * (2 * DINNER) + e];
    float x1 = xz[(2 * b + 1) * (2 * DINNER) + e];
    float w2 = w[e * 4 + 2], w3 = w[e * 4 + 3];
    float bv = bias[e];
    float v0 = x0 * w3 + bv;
    float v1 = x0 * w2 + x1 * w3 + bv;
    xs[(2 * b) * DINNER + e]     = v0 / (1.f + expf(-v0));
    xs[(2 * b + 1) * DINNER + e] = v1 / (1.f + expf(-v1));
}

// ---------------- selective scan (L=2, closed form) + D skip + silu(z) gating ----------------
__global__ void scan_kernel(const float* __restrict__ xz, const float* __restrict__ xs,
                            const float* __restrict__ xdbl, const float* __restrict__ dt,
                            const float* __restrict__ A_log, const float* __restrict__ Dv,
                            float* __restrict__ y)
{
    int idx = blockIdx.x * blockDim.x + threadIdx.x;
    if (idx >= NB * DINNER) return;
    int b = idx >> 12, e = idx & 4095;

    float dt0 = dt[(2 * b) * DINNER + e];
    float dt1 = dt[(2 * b + 1) * DINNER + e];
    float x0  = xs[(2 * b) * DINNER + e];
    float x1  = xs[(2 * b + 1) * DINNER + e];
    float z1  = xz[(2 * b + 1) * (2 * DINNER) + DINNER + e];

    const float* bc0 = xdbl + (2 * b) * 160;
    const float* bc1 = xdbl + (2 * b + 1) * 160;

    float acc = 0.f;
    #pragma unroll
    for (int n = 0; n < DSTATE; ++n) {
        float Ae = -expf(A_log[e * DSTATE + n]);
        float h = dt0 * bc0[DTRANK + n] * x0;
        h = h * expf(dt1 * Ae) + dt1 * bc1[DTRANK + n] * x1;
        acc += h * bc1[DTRANK + DSTATE + n];
    }
    float yv = acc + x1 * Dv[e];
    float sg = z1 / (1.f + expf(-z1));
    y[b * DINNER + e] = yv * sg;
}

// ---------------- output heads ----------------
__global__ void heads_kernel(const float* __restrict__ feat,
                             const float* __restrict__ wxyz, const float* __restrict__ bxyz,
                             const float* __restrict__ wpqr, const float* __restrict__ bpqr,
                             float* __restrict__ out)
{
    int b = blockIdx.x / 7, j = blockIdx.x % 7;
    const float* wrow = (j < 3) ? (wxyz + j * DMODEL) : (wpqr + (j - 3) * DMODEL);
    float bias = (j < 3) ? bxyz[j] : bpqr[j - 3];

    float s = 0.f;
    for (int i = threadIdx.x; i < DMODEL; i += 128)
        s += feat[b * DMODEL + i] * wrow[i];

    __shared__ float red[4];
    #pragma unroll
    for (int off = 16; off; off >>= 1) s += __shfl_down_sync(0xffffffffu, s, off);
    if ((threadIdx.x & 31) == 0) red[threadIdx.x >> 5] = s;
    __syncthreads();
    if (threadIdx.x == 0)
        out[b * 7 + j] = red[0] + red[1] + red[2] + red[3] + bias;
}

// ---------------- launcher ----------------
extern "C" void kernel_launch(void* const* d_in, const int* in_sizes, int n_in,
                              void* d_out, int out_size)
{
    const float* x       = (const float*)d_in[0];
    const float* conv_w  = (const float*)d_in[1];
    const float* conv_b  = (const float*)d_in[2];
    const float* fc_w    = (const float*)d_in[3];
    const float* fc_b    = (const float*)d_in[4];
    const float* W_in    = (const float*)d_in[5];
    const float* c1w     = (const float*)d_in[6];
    const float* c1b     = (const float*)d_in[7];
    const float* W_xproj = (const float*)d_in[8];
    const float* W_dt    = (const float*)d_in[9];
    const float* b_dt    = (const float*)d_in[10];
    const float* A_log   = (const float*)d_in[11];
    const float* Dv      = (const float*)d_in[12];
    const float* W_out   = (const float*)d_in[13];
    const float* wxyz    = (const float*)d_in[14];
    const float* bxyz    = (const float*)d_in[15];
    const float* wpqr    = (const float*)d_in[16];
    const float* bpqr    = (const float*)d_in[17];
    float* out = (float*)d_out;

    void* sp = nullptr;
    cudaGetSymbolAddress(&sp, g_scratch);
    float* S = (float*)sp;

    float* f     = S + OFF_F;
    float* fcacc = S + OFF_FC;
    float* u     = S + OFF_U;
    float* xz    = S + OFF_XZ;
    float* xs    = S + OFF_XS;
    float* xdbl  = S + OFF_XDBL;
    float* dtb   = S + OFF_DT;
    float* y     = S + OFF_Y;
    float* feat  = S + OFF_FEAT;
    float* wT    = S + OFF_WT;

    // opt-in to >48KB dynamic smem for the conv kernel (idempotent, capture-safe)
    cudaFuncSetAttribute(conv_tc_kernel,
                         cudaFuncAttributeMaxDynamicSharedMemorySize,
                         CONV_SMEM_TOTAL);

    // zero the atomic accumulators (f+fcacc contiguous)
    zero_kernel<<<(163840 + 255) / 256, 256>>>(f, 163840);
    zero_kernel<<<(20480 + 255) / 256, 256>>>(xdbl, 20480);
    zero_kernel<<<(131072 + 255) / 256, 256>>>(feat, 131072);

    // conv weight transpose
    prep_wt_kernel<<<(75264 + 255) / 256, 256>>>(conv_w, wT);

    // conv + relu + spatial sum (tensor cores, dynamic smem)
    conv_tc_kernel<<<dim3(49, 32), 256, CONV_SMEM_TOTAL>>>(x, wT, conv_b, f);

    // fc (mean scale folded in), split-K atomic; bias+relu in build_u
    gemm_kernel<<<dim3(32, 1, 4), 128>>>(f, 512, fc_w, nullptr, fcacc, 2048,
                                         64, 2048, 512, 1.f / 3136.f, 0, 1);
    build_u_kernel<<<512, 256>>>(fcacc, fc_b, u);

    // xz = u @ W_in^T   (128 x 8192 x 2048)
    gemm_kernel<<<dim3(128, 2, 1), 128>>>(u, 2048, W_in, nullptr, xz, 8192,
                                          128, 8192, 2048, 1.f, 0, 0);

    // depthwise conv1d + silu
    conv1d_silu_kernel<<<1024, 256>>>(xz, c1w, c1b, xs);

    // x_dbl = xs @ W_xproj^T  (128 x 160 x 4096), split-K atomic
    gemm_kernel<<<dim3(3, 2, 16), 128>>>(xs, 4096, W_xproj, nullptr, xdbl, 160,
                                         128, 160, 4096, 1.f, 0, 1);

    // dt = softplus(dt_low @ W_dt^T + b_dt)  (128 x 4096 x 128)
    gemm_kernel<<<dim3(64, 2, 1), 128>>>(xdbl, 160, W_dt, b_dt, dtb, 4096,
                                         128, 4096, 128, 1.f, 2, 0);

    // scan + gating -> y (l=1 only)
    scan_kernel<<<1024, 256>>>(xz, xs, xdbl, dtb, A_log, Dv, y);

    // feat = y @ W_out^T  (64 x 2048 x 4096), split-K atomic
    gemm_kernel<<<dim3(32, 1, 4), 128>>>(y, 4096, W_out, nullptr, feat, 2048,
                                         64, 2048, 4096, 1.f, 0, 1);

    // heads
    heads_kernel<<<448, 128>>>(feat, wxyz, bxyz, wpqr, bpqr, out);
}

// round 6
// speedup vs baseline: 2.1397x; 1.0408x over previous
#include <cuda_runtime.h>
#include <math.h>

// ---------------- problem constants ----------------
#define NB      64
#define DMODEL  2048
#define DINNER  4096
#define DSTATE  16
#define DTRANK  128
#define FE      512

// ---------------- scratch layout (floats) ----------------
#define OFF_F     0          // 64*512      conv relu-sum accumulator
#define OFF_FC    32768      // 64*2048     fc split-K accumulator
#define OFF_U     163840     // 128*2048    mamba input u (rows = b*2+l)
#define OFF_XZ    425984     // 128*8192    xz = u @ W_in^T
#define OFF_XS    1474560    // 128*4096    silu(conv1d(x))
#define OFF_XDBL  1998848    // 128*160     x_dbl
#define OFF_DT    2019328    // 128*4096    dt (softplus)
#define OFF_Y     2543616    // 64*4096     gated scan output at l=1
#define OFF_FEAT  2805760    // 64*2048     y @ W_out^T
#define OFF_WT    2936832    // 147*512     transposed conv weights [k][co]
#define SCRATCH_TOTAL 3012096

__device__ float g_scratch[SCRATCH_TOTAL];

// conv_tc dynamic smem layout (bytes)
#define CONV_SMEM_W     0                    // 152*72 unsigned = 43776
#define CONV_SMEM_ACC   43776                // 2*512 float     = 4096
#define CONV_SMEM_IN    47872                // 2*3*35*35 float = 29400
#define CONV_SMEM_TOTAL 77272

// ---------------- packed f32x2 helpers (Blackwell) ----------------
__device__ __forceinline__ void ffma2(unsigned long long& d,
                                      unsigned long long a, unsigned long long b) {
    asm volatile("fma.rn.f32x2 %0, %1, %2, %0;" : "+l"(d) : "l"(a), "l"(b));
}
__device__ __forceinline__ unsigned long long dup2(float x) {
    unsigned int u = __float_as_uint(x);
    unsigned long long r;
    asm("mov.b64 %0, {%1, %2};" : "=l"(r) : "r"(u), "r"(u));
    return r;
}
__device__ __forceinline__ float2 unpack2(unsigned long long v) {
    unsigned int lo, hi;
    asm("mov.b64 {%0, %1}, %2;" : "=r"(lo), "=r"(hi) : "l"(v));
    return make_float2(__uint_as_float(lo), __uint_as_float(hi));
}

// ---------------- tf32 mma helpers ----------------
__device__ __forceinline__ unsigned f2tf32(float v) {
    unsigned r;
    asm("cvt.rna.tf32.f32 %0, %1;" : "=r"(r) : "f"(v));
    return r;
}
__device__ __forceinline__ void mma_tf32(float c[4],
                                         unsigned a0, unsigned a1, unsigned a2, unsigned a3,
                                         unsigned b0, unsigned b1) {
    asm volatile(
        "mma.sync.aligned.m16n8k8.row.col.f32.tf32.tf32.f32 "
        "{%0,%1,%2,%3}, {%4,%5,%6,%7}, {%8,%9}, {%0,%1,%2,%3};"
        : "+f"(c[0]), "+f"(c[1]), "+f"(c[2]), "+f"(c[3])
        : "r"(a0), "r"(a1), "r"(a2), "r"(a3), "r"(b0), "r"(b1));
}

// ---------------- utility kernels ----------------
__global__ void zero_kernel(float* p, int n) {
    int i = blockIdx.x * blockDim.x + threadIdx.x;
    if (i < n) p[i] = 0.f;
}

// conv_w (512,3,7,7) -> wT[k][co], k = ci*49+kh*7+kw
__global__ void prep_wt_kernel(const float* __restrict__ w, float* __restrict__ wT) {
    int i = blockIdx.x * blockDim.x + threadIdx.x;
    if (i < 512 * 147) {
        int co = i / 147, k = i - co * 147;
        wT[k * 512 + co] = w[i];
    }
}

// ---------------- conv 7x7 s4 p3 + bias + relu + spatial-sum (tensor cores) ----------
// grid (49, 32), block 256 (8 warps). Each block: 8x8 output tile of TWO images.
// Implicit GEMM: M=128 (2 img x 64 pos), N=512 (chunks of 64), K=147 (pad 152).
__global__ void __launch_bounds__(256)
conv_tc_kernel(const float* __restrict__ x, const float* __restrict__ wT,
               const float* __restrict__ bias, float* __restrict__ f_accum)
{
    extern __shared__ __align__(16) char smem[];
    unsigned* s_w  = reinterpret_cast<unsigned*>(smem + CONV_SMEM_W);    // [152][72]
    float*    s_acc = reinterpret_cast<float*>(smem + CONV_SMEM_ACC);    // [2][512]
    float*    s_in  = reinterpret_cast<float*>(smem + CONV_SMEM_IN);     // [2][3][35][35]

    const int t    = threadIdx.x;
    const int tile = blockIdx.x;
    const int bp   = blockIdx.y;            // image pair
    const int oh_base = (tile / 7) * 8;
    const int ow_base = (tile % 7) * 8;
    const int ih0 = oh_base * 4 - 3;
    const int iw0 = ow_base * 4 - 3;

    for (int i = t; i < 1024; i += 256) s_acc[i] = 0.f;

    for (int i = t; i < 2 * 3 * 1225; i += 256) {
        int img = i / 3675;
        int rem = i - img * 3675;
        int ci  = rem / 1225; rem -= ci * 1225;
        int r = rem / 35, c = rem - (rem / 35) * 35;
        int ih = ih0 + r, iw = iw0 + c;
        float v = 0.f;
        int b = bp * 2 + img;
        if ((unsigned)ih < 224u && (unsigned)iw < 224u)
            v = x[((b * 3 + ci) * 224 + ih) * 224 + iw];
        s_in[(img * 3 + ci) * 1225 + r * 35 + c] = v;
    }

    const int lane = t & 31;
    const int w    = t >> 5;
    const int img  = w >> 2;
    const int q    = lane >> 2;
    const int j    = lane & 3;
    const int ya = (w & 3) * 8;
    const int xb = q * 4;
    const float* my_in = s_in + img * 3675;

    for (int n0 = 0; n0 < 512; n0 += 64) {
        __syncthreads();
        for (int i = t; i < 152 * 64; i += 256) {
            int k = i >> 6, n = i & 63;
            float v = (k < 147) ? wT[k * 512 + n0 + n] : 0.f;
            s_w[k * 72 + n] = f2tf32(v);
        }
        __syncthreads();

        float c[8][4];
        #pragma unroll
        for (int nf = 0; nf < 8; ++nf)
            #pragma unroll
            for (int u2 = 0; u2 < 4; ++u2) c[nf][u2] = 0.f;

        for (int ks = 0; ks < 19; ++ks) {
            int k0 = ks * 8 + j;
            int k1 = k0 + 4;
            int kk0 = min(k0, 146), kk1 = min(k1, 146);
            int ci0 = kk0 / 49, r0 = kk0 - ci0 * 49;
            int kh0 = r0 / 7,  kw0 = r0 - kh0 * 7;
            int ci1 = kk1 / 49, r1 = kk1 - ci1 * 49;
            int kh1 = r1 / 7,  kw1 = r1 - kh1 * 7;

            unsigned a0 = f2tf32(my_in[ci0 * 1225 + (ya + kh0) * 35 + xb + kw0]);
            unsigned a1 = f2tf32(my_in[ci0 * 1225 + (ya + 4 + kh0) * 35 + xb + kw0]);
            unsigned a2 = f2tf32(my_in[ci1 * 1225 + (ya + kh1) * 35 + xb + kw1]);
            unsigned a3 = f2tf32(my_in[ci1 * 1225 + (ya + 4 + kh1) * 35 + xb + kw1]);

            #pragma unroll
            for (int nf = 0; nf < 8; ++nf) {
                unsigned b0 = s_w[k0 * 72 + nf * 8 + q];
                unsigned b1 = s_w[k1 * 72 + nf * 8 + q];
                mma_tf32(c[nf], a0, a1, a2, a3, b0, b1);
            }
        }

        #pragma unroll
        for (int nf = 0; nf < 8; ++nf) {
            int ca = n0 + nf * 8 + 2 * j;
            float bva = bias[ca], bvb = bias[ca + 1];
            float va = fmaxf(c[nf][0] + bva, 0.f) + fmaxf(c[nf][2] + bva, 0.f);
            float vb = fmaxf(c[nf][1] + bvb, 0.f) + fmaxf(c[nf][3] + bvb, 0.f);
            #pragma unroll
            for (int off = 16; off >= 4; off >>= 1) {
                va += __shfl_down_sync(0xffffffffu, va, off);
                vb += __shfl_down_sync(0xffffffffu, vb, off);
            }
            if (lane < 4) {
                atomicAdd(&s_acc[img * 512 + ca], va);
                atomicAdd(&s_acc[img * 512 + ca + 1], vb);
            }
        }
    }

    __syncthreads();
    for (int i = t; i < 1024; i += 256) {
        int im = i >> 9, ch = i & 511;
        atomicAdd(&f_accum[(bp * 2 + im) * 512 + ch], s_acc[im * 512 + ch]);
    }
}

// ---------------- tensor-core 3xTF32 GEMM: C[M,N] (+)= A[M,K] @ W[N,K]^T ----------
// BM=128, BN=64, BK=16, 256 threads (8 warps; warp w owns m-rows [w*16, w*16+16)).
// hi/lo tf32 split: a*b ~= ah*bh + ah*bl + al*bh  (error ~2^-22, effectively fp32).
// Strides 136/72 words (== 8 mod 32) -> conflict-free fragment LDS.
// Requirements: K % (16*gridDim.z) == 0, lda % 4 == 0, K % 4 == 0.
// A rows beyond M are read (clamped) but never stored.
#define GT_SA 136
#define GT_SW 72
__global__ void __launch_bounds__(256)
gemm_tc_kernel(const float* __restrict__ A, int lda,
               const float* __restrict__ W,
               float* __restrict__ C, int ldc,
               int M, int N, int K, int atomic)
{
    __shared__ unsigned sAh[16 * GT_SA], sAl[16 * GT_SA];
    __shared__ unsigned sWh[16 * GT_SW], sWl[16 * GT_SW];

    const int bm = blockIdx.y * 128;
    const int bn = blockIdx.x * 64;
    const int t = threadIdx.x, lane = t & 31, w = t >> 5;
    const int kPer = K / gridDim.z;
    const int kBeg = blockIdx.z * kPer;

    float acc[8][4];
    #pragma unroll
    for (int nf = 0; nf < 8; ++nf)
        #pragma unroll
        for (int u2 = 0; u2 < 4; ++u2) acc[nf][u2] = 0.f;

    for (int k0 = kBeg; k0 < kBeg + kPer; k0 += 16) {
        // A tile: 128 rows x 16 k (rows clamped to M-1; junk rows never stored)
        #pragma unroll
        for (int it = 0; it < 2; ++it) {
            int idx = t + it * 256;
            int r = idx >> 2, c4 = idx & 3;
            int gr = min(bm + r, M - 1);
            float4 v = *reinterpret_cast<const float4*>(
                A + (size_t)gr * lda + k0 + c4 * 4);
            float vv[4] = {v.x, v.y, v.z, v.w};
            #pragma unroll
            for (int e = 0; e < 4; ++e) {
                unsigned h = f2tf32(vv[e]);
                unsigned l = f2tf32(vv[e] - __uint_as_float(h));
                sAh[(c4 * 4 + e) * GT_SA + r] = h;
                sAl[(c4 * 4 + e) * GT_SA + r] = l;
            }
        }
        // W tile: 64 rows x 16 k
        {
            int r = t >> 2, c4 = t & 3;
            int gn = bn + r;
            float4 v = make_float4(0.f, 0.f, 0.f, 0.f);
            if (gn < N)
                v = *reinterpret_cast<const float4*>(
                    W + (size_t)gn * K + k0 + c4 * 4);
            float vv[4] = {v.x, v.y, v.z, v.w};
            #pragma unroll
            for (int e = 0; e < 4; ++e) {
                unsigned h = f2tf32(vv[e]);
                unsigned l = f2tf32(vv[e] - __uint_as_float(h));
                sWh[(c4 * 4 + e) * GT_SW + r] = h;
                sWl[(c4 * 4 + e) * GT_SW + r] = l;
            }
        }
        __syncthreads();

        #pragma unroll
        for (int ks = 0; ks < 2; ++ks) {
            int kb = ks * 8;
            int ar = w * 16 + (lane >> 2);
            int ac = kb + (lane & 3);
            unsigned ah0 = sAh[ac * GT_SA + ar];
            unsigned ah1 = sAh[ac * GT_SA + ar + 8];
            unsigned ah2 = sAh[(ac + 4) * GT_SA + ar];
            unsigned ah3 = sAh[(ac + 4) * GT_SA + ar + 8];
            unsigned al0 = sAl[ac * GT_SA + ar];
            unsigned al1 = sAl[ac * GT_SA + ar + 8];
            unsigned al2 = sAl[(ac + 4) * GT_SA + ar];
            unsigned al3 = sAl[(ac + 4) * GT_SA + ar + 8];

            #pragma unroll
            for (int nf = 0; nf < 8; ++nf) {
                int bc = nf * 8 + (lane >> 2);
                int br = kb + (lane & 3);
                unsigned bh0 = sWh[br * GT_SW + bc];
                unsigned bh1 = sWh[(br + 4) * GT_SW + bc];
                unsigned bl0 = sWl[br * GT_SW + bc];
                unsigned bl1 = sWl[(br + 4) * GT_SW + bc];
                mma_tf32(acc[nf], ah0, ah1, ah2, ah3, bh0, bh1);
                mma_tf32(acc[nf], ah0, ah1, ah2, ah3, bl0, bl1);
                mma_tf32(acc[nf], al0, al1, al2, al3, bh0, bh1);
            }
        }
        __syncthreads();
    }

    // epilogue (mma C layout: c0/c1 -> row lane/4, cols 2*(lane%4)+{0,1}; c2/c3 -> row+8)
    const int mr0 = bm + w * 16 + (lane >> 2);
    const int nc0 = bn + (lane & 3) * 2;
    #pragma unroll
    for (int nf = 0; nf < 8; ++nf) {
        int n = nc0 + nf * 8;
        if (n >= N) continue;
        if (atomic) {
            if (mr0 < M) {
                atomicAdd(&C[(size_t)mr0 * ldc + n],     acc[nf][0]);
                atomicAdd(&C[(size_t)mr0 * ldc + n + 1], acc[nf][1]);
            }
            if (mr0 + 8 < M) {
                atomicAdd(&C[(size_t)(mr0 + 8) * ldc + n],     acc[nf][2]);
                atomicAdd(&C[(size_t)(mr0 + 8) * ldc + n + 1], acc[nf][3]);
            }
        } else {
            if (mr0 < M) {
                C[(size_t)mr0 * ldc + n]     = acc[nf][0];
                C[(size_t)mr0 * ldc + n + 1] = acc[nf][1];
            }
            if (mr0 + 8 < M) {
                C[(size_t)(mr0 + 8) * ldc + n]     = acc[nf][2];
                C[(size_t)(mr0 + 8) * ldc + n + 1] = acc[nf][3];
            }
        }
    }
}

// ---------------- tiled SGEMM with f32x2 (small GEMMs) ----------------
__global__ void __launch_bounds__(128)
gemm_kernel(const float* __restrict__ A, int lda,
            const float* __restrict__ W,
            const float* __restrict__ bias,
            float* __restrict__ C, int ldc,
            int M, int N, int K, float a_scale,
            int act, int atomic)
{
    __shared__ __align__(16) float As[16][68];
    __shared__ __align__(16) float Ws[16][68];

    const int bm = blockIdx.y * 64;
    const int bn = blockIdx.x * 64;
    const int t  = threadIdx.x;
    const int tx = t & 15;
    const int ty = t >> 4;

    const int nz   = gridDim.z;
    const int kPer = K / nz;
    const int kBeg = blockIdx.z * kPer;
    const int kEnd = kBeg + kPer;

    unsigned long long acc[4][4];
    #pragma unroll
    for (int i = 0; i < 4; ++i)
        #pragma unroll
        for (int j = 0; j < 4; ++j) acc[i][j] = 0ull;

    for (int k0 = kBeg; k0 < kEnd; k0 += 16) {
        #pragma unroll
        for (int it = 0; it < 2; ++it) {
            int idx = t + it * 128;
            int r = idx >> 2, c4 = idx & 3;
            {
                float4 v = *reinterpret_cast<const float4*>(
                    A + (size_t)(bm + r) * lda + k0 + c4 * 4);
                As[c4 * 4 + 0][r] = v.x * a_scale;
                As[c4 * 4 + 1][r] = v.y * a_scale;
                As[c4 * 4 + 2][r] = v.z * a_scale;
                As[c4 * 4 + 3][r] = v.w * a_scale;
            }
            {
                int gn = bn + r;
                float4 v = make_float4(0.f, 0.f, 0.f, 0.f);
                if (gn < N)
                    v = *reinterpret_cast<const float4*>(
                        W + (size_t)gn * K + k0 + c4 * 4);
                Ws[c4 * 4 + 0][r] = v.x;
                Ws[c4 * 4 + 1][r] = v.y;
                Ws[c4 * 4 + 2][r] = v.z;
                Ws[c4 * 4 + 3][r] = v.w;
            }
        }
        __syncthreads();

        #pragma unroll
        for (int kk = 0; kk < 16; ++kk) {
            const ulonglong2* ap =
                reinterpret_cast<const ulonglong2*>(&As[kk][ty * 8]);
            ulonglong2 am01 = ap[0];
            ulonglong2 am23 = ap[1];
            float4 wv = *reinterpret_cast<const float4*>(&Ws[kk][tx * 4]);
            unsigned long long pw0 = dup2(wv.x);
            unsigned long long pw1 = dup2(wv.y);
            unsigned long long pw2 = dup2(wv.z);
            unsigned long long pw3 = dup2(wv.w);
            ffma2(acc[0][0], am01.x, pw0); ffma2(acc[0][1], am01.x, pw1);
            ffma2(acc[0][2], am01.x, pw2); ffma2(acc[0][3], am01.x, pw3);
            ffma2(acc[1][0], am01.y, pw0); ffma2(acc[1][1], am01.y, pw1);
            ffma2(acc[1][2], am01.y, pw2); ffma2(acc[1][3], am01.y, pw3);
            ffma2(acc[2][0], am23.x, pw0); ffma2(acc[2][1], am23.x, pw1);
            ffma2(acc[2][2], am23.x, pw2); ffma2(acc[2][3], am23.x, pw3);
            ffma2(acc[3][0], am23.y, pw0); ffma2(acc[3][1], am23.y, pw1);
            ffma2(acc[3][2], am23.y, pw2); ffma2(acc[3][3], am23.y, pw3);
        }
        __syncthreads();
    }

    const int nbase = bn + tx * 4;
    #pragma unroll
    for (int i = 0; i < 4; ++i) {
        int m0 = bm + ty * 8 + 2 * i;
        float2 c0 = unpack2(acc[i][0]);
        float2 c1 = unpack2(acc[i][1]);
        float2 c2 = unpack2(acc[i][2]);
        float2 c3 = unpack2(acc[i][3]);
        float lo[4] = {c0.x, c1.x, c2.x, c3.x};
        float hi[4] = {c0.y, c1.y, c2.y, c3.y};
        if (atomic) {
            #pragma unroll
            for (int j = 0; j < 4; ++j) {
                int n = nbase + j;
                if (n < N) {
                    atomicAdd(&C[(size_t)m0 * ldc + n], lo[j]);
                    atomicAdd(&C[(size_t)(m0 + 1) * ldc + n], hi[j]);
                }
            }
        } else {
            #pragma unroll
            for (int j = 0; j < 4; ++j) {
                int n = nbase + j;
                if (n >= N) continue;
                float bv = bias ? bias[n] : 0.f;
                float v0 = lo[j] + bv, v1 = hi[j] + bv;
                if (act == 1) { v0 = fmaxf(v0, 0.f); v1 = fmaxf(v1, 0.f); }
                else if (act == 2) {
                    v0 = (v0 > 20.f) ? v0 : log1pf(expf(v0));
                    v1 = (v1 > 20.f) ? v1 : log1pf(expf(v1));
                }
                C[(size_t)m0 * ldc + n] = v0;
                C[(size_t)(m0 + 1) * ldc + n] = v1;
            }
        }
    }
}

// ---------------- fc bias + relu + sequence build (reversal at l=0) ----------------
__global__ void build_u_kernel(const float* __restrict__ fcacc, const float* __restrict__ fcb,
                               float* __restrict__ u)
{
    int idx = blockIdx.x * blockDim.x + threadIdx.x;
    if (idx >= NB * DMODEL) return;
    int b = idx >> 11, d = idx & 2047;
    float v = fmaxf(fcacc[idx] + fcb[d], 0.f);
    u[(2 * b + 1) * DMODEL + d] = v;
    u[(2 * b) * DMODEL + (DMODEL - 1 - d)] = v;
}

// ---------------- depthwise conv1d (L=2, causal k=4) + silu ----------------
__global__ void conv1d_silu_kernel(const float* __restrict__ xz, const float* __restrict__ w,
                                   const float* __restrict__ bias, float* __restrict__ xs)
{
    int idx = blockIdx.x * blockDim.x + threadIdx.x;
    if (idx >= NB * DINNER) return;
    int b = idx >> 12, e = idx & 4095;
    float x0 = xz[(2 * b) * (2 * DINNER) + e];
    float x1 = xz[(2 * b + 1) * (2 * DINNER) + e];
    float w2 = w[e * 4 + 2], w3 = w[e * 4 + 3];
    float bv = bias[e];
    float v0 = x0 * w3 + bv;
    float v1 = x0 * w2 + x1 * w3 + bv;
    xs[(2 * b) * DINNER + e]     = v0 / (1.f + expf(-v0));
    xs[(2 * b + 1) * DINNER + e] = v1 / (1.f + expf(-v1));
}

// ---------------- selective scan (L=2, closed form) + D skip + silu(z) gating --------
__global__ void scan_kernel(const float* __restrict__ xz, const float* __restrict__ xs,
                            const float* __restrict__ xdbl, const float* __restrict__ dt,
                            const float* __restrict__ A_log, const float* __restrict__ Dv,
                            float* __restrict__ y)
{
    int idx = blockIdx.x * blockDim.x + threadIdx.x;
    if (idx >= NB * DINNER) return;
    int b = idx >> 12, e = idx & 4095;

    float dt0 = dt[(2 * b) * DINNER + e];
    float dt1 = dt[(2 * b + 1) * DINNER + e];
    float x0  = xs[(2 * b) * DINNER + e];
    float x1  = xs[(2 * b + 1) * DINNER + e];
    float z1  = xz[(2 * b + 1) * (2 * DINNER) + DINNER + e];

    const float* bc0 = xdbl + (2 * b) * 160;
    const float* bc1 = xdbl + (2 * b + 1) * 160;

    float acc = 0.f;
    #pragma unroll
    for (int n = 0; n < DSTATE; ++n) {
        float Ae = -expf(A_log[e * DSTATE + n]);
        float h = dt0 * bc0[DTRANK + n] * x0;
        h = h * expf(dt1 * Ae) + dt1 * bc1[DTRANK + n] * x1;
        acc += h * bc1[DTRANK + DSTATE + n];
    }
    float yv = acc + x1 * Dv[e];
    float sg = z1 / (1.f + expf(-z1));
    y[b * DINNER + e] = yv * sg;
}

// ---------------- output heads ----------------
__global__ void heads_kernel(const float* __restrict__ feat,
                             const float* __restrict__ wxyz, const float* __restrict__ bxyz,
                             const float* __restrict__ wpqr, const float* __restrict__ bpqr,
                             float* __restrict__ out)
{
    int b = blockIdx.x / 7, j = blockIdx.x % 7;
    const float* wrow = (j < 3) ? (wxyz + j * DMODEL) : (wpqr + (j - 3) * DMODEL);
    float bias = (j < 3) ? bxyz[j] : bpqr[j - 3];

    float s = 0.f;
    for (int i = threadIdx.x; i < DMODEL; i += 128)
        s += feat[b * DMODEL + i] * wrow[i];

    __shared__ float red[4];
    #pragma unroll
    for (int off = 16; off; off >>= 1) s += __shfl_down_sync(0xffffffffu, s, off);
    if ((threadIdx.x & 31) == 0) red[threadIdx.x >> 5] = s;
    __syncthreads();
    if (threadIdx.x == 0)
        out[b * 7 + j] = red[0] + red[1] + red[2] + red[3] + bias;
}

// ---------------- launcher ----------------
extern "C" void kernel_launch(void* const* d_in, const int* in_sizes, int n_in,
                              void* d_out, int out_size)
{
    const float* x       = (const float*)d_in[0];
    const float* conv_w  = (const float*)d_in[1];
    const float* conv_b  = (const float*)d_in[2];
    const float* fc_w    = (const float*)d_in[3];
    const float* fc_b    = (const float*)d_in[4];
    const float* W_in    = (const float*)d_in[5];
    const float* c1w     = (const float*)d_in[6];
    const float* c1b     = (const float*)d_in[7];
    const float* W_xproj = (const float*)d_in[8];
    const float* W_dt    = (const float*)d_in[9];
    const float* b_dt    = (const float*)d_in[10];
    const float* A_log   = (const float*)d_in[11];
    const float* Dv      = (const float*)d_in[12];
    const float* W_out   = (const float*)d_in[13];
    const float* wxyz    = (const float*)d_in[14];
    const float* bxyz    = (const float*)d_in[15];
    const float* wpqr    = (const float*)d_in[16];
    const float* bpqr    = (const float*)d_in[17];
    float* out = (float*)d_out;

    void* sp = nullptr;
    cudaGetSymbolAddress(&sp, g_scratch);
    float* S = (float*)sp;

    float* f     = S + OFF_F;
    float* fcacc = S + OFF_FC;
    float* u     = S + OFF_U;
    float* xz    = S + OFF_XZ;
    float* xs    = S + OFF_XS;
    float* xdbl  = S + OFF_XDBL;
    float* dtb   = S + OFF_DT;
    float* y     = S + OFF_Y;
    float* feat  = S + OFF_FEAT;
    float* wT    = S + OFF_WT;

    cudaFuncSetAttribute(conv_tc_kernel,
                         cudaFuncAttributeMaxDynamicSharedMemorySize,
                         CONV_SMEM_TOTAL);

    // launch order arranged so launch #4 == conv_tc_kernel (ncu profiles #4)
    // (1) zero f+fcacc
    zero_kernel<<<(163840 + 255) / 256, 256>>>(f, 163840);
    // (2) zero xdbl
    zero_kernel<<<(20480 + 255) / 256, 256>>>(xdbl, 20480);
    // (3) conv weight transpose
    prep_wt_kernel<<<(75264 + 255) / 256, 256>>>(conv_w, wT);
    // (4) conv + relu + spatial sum (tensor cores)
    conv_tc_kernel<<<dim3(49, 32), 256, CONV_SMEM_TOTAL>>>(x, wT, conv_b, f);
    // (5) fc (mean scale folded in), split-K atomic
    gemm_kernel<<<dim3(32, 1, 4), 128>>>(f, 512, fc_w, nullptr, fcacc, 2048,
                                         64, 2048, 512, 1.f / 3136.f, 0, 1);
    // (6) bias+relu + sequence build
    build_u_kernel<<<512, 256>>>(fcacc, fc_b, u);
    // (7) xz = u @ W_in^T  (128 x 8192 x 2048) — tensor 3xTF32
    gemm_tc_kernel<<<dim3(128, 1, 1), 256>>>(u, 2048, W_in, xz, 8192,
                                             128, 8192, 2048, 0);
    // (8) depthwise conv1d + silu
    conv1d_silu_kernel<<<1024, 256>>>(xz, c1w, c1b, xs);
    // (9) x_dbl = xs @ W_xproj^T  (128 x 160 x 4096), split-K atomic
    gemm_kernel<<<dim3(3, 2, 16), 128>>>(xs, 4096, W_xproj, nullptr, xdbl, 160,
                                         128, 160, 4096, 1.f, 0, 1);
    // (10) dt = softplus(dt_low @ W_dt^T + b_dt)
    gemm_kernel<<<dim3(64, 2, 1), 128>>>(xdbl, 160, W_dt, b_dt, dtb, 4096,
                                         128, 4096, 128, 1.f, 2, 0);
    // (11) scan + gating -> y
    scan_kernel<<<1024, 256>>>(xz, xs, xdbl, dtb, A_log, Dv, y);
    // (12) zero feat (needed only before W_out atomics)
    zero_kernel<<<(131072 + 255) / 256, 256>>>(feat, 131072);
    // (13) feat = y @ W_out^T  (64 x 2048 x 4096) — tensor 3xTF32, split-K=4
    gemm_tc_kernel<<<dim3(32, 1, 4), 256>>>(y, 4096, W_out, feat, 2048,
                                            64, 2048, 4096, 1);
    // (14) heads
    heads_kernel<<<448, 128>>>(feat, wxyz, bxyz, wpqr, bpqr, out);
}

// round 7
// speedup vs baseline: 2.6344x; 1.2312x over previous
#include <cuda_runtime.h>
#include <math.h>

// ---------------- problem constants ----------------
#define NB      64
#define DMODEL  2048
#define DINNER  4096
#define DSTATE  16
#define DTRANK  128
#define FE      512

// ---------------- scratch layout (floats) ----------------
#define OFF_F     0          // 64*512      conv relu-sum accumulator
#define OFF_FC    32768      // 64*2048     fc split-K accumulator
#define OFF_U     163840     // 128*2048    mamba input u (rows = b*2+l)
#define OFF_XZ    425984     // 128*8192    xz = u @ W_in^T
#define OFF_XS    1474560    // 128*4096    silu(conv1d(x))
#define OFF_XDBL  1998848    // 128*160     x_dbl
#define OFF_DT    2019328    // 128*4096    dt (softplus)
#define OFF_Y     2543616    // 64*4096     gated scan output at l=1
#define OFF_FEAT  2805760    // 64*2048     y @ W_out^T
#define OFF_WT    2936832    // 152*512     tf32-bit conv weights [k][co], zero-padded k>=147
#define SCRATCH_TOTAL 3014656

__device__ float g_scratch[SCRATCH_TOTAL];

// conv_tc dynamic smem layout (bytes)
#define CONV_SMEM_W     0                    // 152*72 unsigned = 43776
#define CONV_SMEM_ACC   43776                // 2*512 float     = 4096
#define CONV_SMEM_IN    47872                // 2*3*35*35 tf32  = 29400
#define CONV_SMEM_TOTAL 77272

// ---------------- packed f32x2 helpers (Blackwell) ----------------
__device__ __forceinline__ void ffma2(unsigned long long& d,
                                      unsigned long long a, unsigned long long b) {
    asm volatile("fma.rn.f32x2 %0, %1, %2, %0;" : "+l"(d) : "l"(a), "l"(b));
}
__device__ __forceinline__ unsigned long long dup2(float x) {
    unsigned int u = __float_as_uint(x);
    unsigned long long r;
    asm("mov.b64 %0, {%1, %2};" : "=l"(r) : "r"(u), "r"(u));
    return r;
}
__device__ __forceinline__ float2 unpack2(unsigned long long v) {
    unsigned int lo, hi;
    asm("mov.b64 {%0, %1}, %2;" : "=r"(lo), "=r"(hi) : "l"(v));
    return make_float2(__uint_as_float(lo), __uint_as_float(hi));
}

// ---------------- tf32 mma helpers ----------------
__device__ __forceinline__ unsigned f2tf32(float v) {
    unsigned r;
    asm("cvt.rna.tf32.f32 %0, %1;" : "=r"(r) : "f"(v));
    return r;
}
__device__ __forceinline__ void mma_tf32(float c[4],
                                         unsigned a0, unsigned a1, unsigned a2, unsigned a3,
                                         unsigned b0, unsigned b1) {
    asm volatile(
        "mma.sync.aligned.m16n8k8.row.col.f32.tf32.tf32.f32 "
        "{%0,%1,%2,%3}, {%4,%5,%6,%7}, {%8,%9}, {%0,%1,%2,%3};"
        : "+f"(c[0]), "+f"(c[1]), "+f"(c[2]), "+f"(c[3])
        : "r"(a0), "r"(a1), "r"(a2), "r"(a3), "r"(b0), "r"(b1));
}

// ---------------- utility kernels ----------------
__global__ void zero_kernel(float* p, int n) {
    int i = blockIdx.x * blockDim.x + threadIdx.x;
    if (i < n) p[i] = 0.f;
}

// conv_w (512,3,7,7) -> tf32 bits wT[k][co], k = ci*49+kh*7+kw, zero-padded to k=152
__global__ void prep_wt_kernel(const float* __restrict__ w, unsigned* __restrict__ wT) {
    int i = blockIdx.x * blockDim.x + threadIdx.x;
    if (i < 152 * 512) {
        int k = i >> 9, co = i & 511;
        float v = (k < 147) ? w[co * 147 + k] : 0.f;
        wT[k * 512 + co] = f2tf32(v);
    }
}

// ---------------- conv 7x7 s4 p3 + bias + relu + spatial-sum (tensor cores) ----------
// grid (49, 32), block 256 (8 warps). Each block: 8x8 output tile of TWO images.
// Implicit GEMM: M=128 (2 img x 64 pos), N=512 (chunks of 64), K=147 (pad 152).
// Inner loop: pure LDS + MMA. All cvt done at staging; index math hoisted to
// register tables (o0/o1) before the n-chunk loop.
__global__ void __launch_bounds__(256)
conv_tc_kernel(const float* __restrict__ x, const unsigned* __restrict__ wT,
               const float* __restrict__ bias, float* __restrict__ f_accum)
{
    extern __shared__ __align__(16) char smem[];
    unsigned* s_w  = reinterpret_cast<unsigned*>(smem + CONV_SMEM_W);    // [152][72]
    float*    s_acc = reinterpret_cast<float*>(smem + CONV_SMEM_ACC);    // [2][512]
    unsigned* s_in  = reinterpret_cast<unsigned*>(smem + CONV_SMEM_IN);  // [2][3][35][35] tf32

    const int t    = threadIdx.x;
    const int tile = blockIdx.x;
    const int bp   = blockIdx.y;            // image pair
    const int oh_base = (tile / 7) * 8;
    const int ow_base = (tile % 7) * 8;
    const int ih0 = oh_base * 4 - 3;
    const int iw0 = ow_base * 4 - 3;

    for (int i = t; i < 1024; i += 256) s_acc[i] = 0.f;

    // input tiles for both images, converted to tf32 bits once
    for (int i = t; i < 2 * 3 * 1225; i += 256) {
        int img = i / 3675;
        int rem = i - img * 3675;
        int ci  = rem / 1225; rem -= ci * 1225;
        int r = rem / 35, c = rem - (rem / 35) * 35;
        int ih = ih0 + r, iw = iw0 + c;
        float v = 0.f;
        int b = bp * 2 + img;
        if ((unsigned)ih < 224u && (unsigned)iw < 224u)
            v = x[((b * 3 + ci) * 224 + ih) * 224 + iw];
        s_in[(img * 3 + ci) * 1225 + r * 35 + c] = f2tf32(v);
    }

    const int lane = t & 31;
    const int w    = t >> 5;
    const int img  = w >> 2;
    const int q    = lane >> 2;
    const int j    = lane & 3;
    const int ya = (w & 3) * 8;
    const int xb = q * 4;
    // fold (img, ya, xb) into the base pointer
    const unsigned* my_in = s_in + img * 3675 + ya * 35 + xb;

    // per-thread k-step offset tables (register arrays; loop fully unrolled)
    int o0[19], o1[19];
    #pragma unroll
    for (int ks = 0; ks < 19; ++ks) {
        int k0 = ks * 8 + j, k1 = k0 + 4;
        int kk0 = min(k0, 146), kk1 = min(k1, 146);
        int ci0 = kk0 / 49, r0 = kk0 - ci0 * 49;
        int kh0 = r0 / 7,  kw0 = r0 - kh0 * 7;
        int ci1 = kk1 / 49, r1 = kk1 - ci1 * 49;
        int kh1 = r1 / 7,  kw1 = r1 - kh1 * 7;
        o0[ks] = ci0 * 1225 + kh0 * 35 + kw0;
        o1[ks] = ci1 * 1225 + kh1 * 35 + kw1;
    }

    for (int n0 = 0; n0 < 512; n0 += 64) {
        __syncthreads();
        // stage weight chunk: pure uint4 copy (already tf32 bits)
        for (int i = t; i < 152 * 16; i += 256) {
            int k = i >> 4, n4 = i & 15;
            *reinterpret_cast<uint4*>(&s_w[k * 72 + n4 * 4]) =
                *reinterpret_cast<const uint4*>(&wT[k * 512 + n0 + n4 * 4]);
        }
        __syncthreads();

        float c[8][4];
        #pragma unroll
        for (int nf = 0; nf < 8; ++nf)
            #pragma unroll
            for (int u2 = 0; u2 < 4; ++u2) c[nf][u2] = 0.f;

        #pragma unroll
        for (int ks = 0; ks < 19; ++ks) {
            unsigned a0 = my_in[o0[ks]];
            unsigned a1 = my_in[o0[ks] + 140];     // +4 rows
            unsigned a2 = my_in[o1[ks]];
            unsigned a3 = my_in[o1[ks] + 140];
            const unsigned* wr0 = s_w + (ks * 8 + j) * 72 + q;
            const unsigned* wr1 = wr0 + 4 * 72;
            #pragma unroll
            for (int nf = 0; nf < 8; ++nf)
                mma_tf32(c[nf], a0, a1, a2, a3, wr0[nf * 8], wr1[nf * 8]);
        }

        // epilogue: bias + relu per position, reduce over positions
        #pragma unroll
        for (int nf = 0; nf < 8; ++nf) {
            int ca = n0 + nf * 8 + 2 * j;
            float bva = bias[ca], bvb = bias[ca + 1];
            float va = fmaxf(c[nf][0] + bva, 0.f) + fmaxf(c[nf][2] + bva, 0.f);
            float vb = fmaxf(c[nf][1] + bvb, 0.f) + fmaxf(c[nf][3] + bvb, 0.f);
            #pragma unroll
            for (int off = 16; off >= 4; off >>= 1) {
                va += __shfl_down_sync(0xffffffffu, va, off);
                vb += __shfl_down_sync(0xffffffffu, vb, off);
            }
            if (lane < 4) {
                atomicAdd(&s_acc[img * 512 + ca], va);
                atomicAdd(&s_acc[img * 512 + ca + 1], vb);
            }
        }
    }

    __syncthreads();
    for (int i = t; i < 1024; i += 256) {
        int im = i >> 9, ch = i & 511;
        atomicAdd(&f_accum[(bp * 2 + im) * 512 + ch], s_acc[im * 512 + ch]);
    }
}

// ---------------- tensor-core 3xTF32 GEMM: C[M,N] (+)= A[M,K] @ W[N,K]^T ----------
#define GT_SA 136
#define GT_SW 72
__global__ void __launch_bounds__(256)
gemm_tc_kernel(const float* __restrict__ A, int lda,
               const float* __restrict__ W,
               float* __restrict__ C, int ldc,
               int M, int N, int K, int atomic)
{
    __shared__ unsigned sAh[16 * GT_SA], sAl[16 * GT_SA];
    __shared__ unsigned sWh[16 * GT_SW], sWl[16 * GT_SW];

    const int bm = blockIdx.y * 128;
    const int bn = blockIdx.x * 64;
    const int t = threadIdx.x, lane = t & 31, w = t >> 5;
    const int kPer = K / gridDim.z;
    const int kBeg = blockIdx.z * kPer;

    float acc[8][4];
    #pragma unroll
    for (int nf = 0; nf < 8; ++nf)
        #pragma unroll
        for (int u2 = 0; u2 < 4; ++u2) acc[nf][u2] = 0.f;

    for (int k0 = kBeg; k0 < kBeg + kPer; k0 += 16) {
        #pragma unroll
        for (int it = 0; it < 2; ++it) {
            int idx = t + it * 256;
            int r = idx >> 2, c4 = idx & 3;
            int gr = min(bm + r, M - 1);
            float4 v = *reinterpret_cast<const float4*>(
                A + (size_t)gr * lda + k0 + c4 * 4);
            float vv[4] = {v.x, v.y, v.z, v.w};
            #pragma unroll
            for (int e = 0; e < 4; ++e) {
                unsigned h = f2tf32(vv[e]);
                unsigned l = f2tf32(vv[e] - __uint_as_float(h));
                sAh[(c4 * 4 + e) * GT_SA + r] = h;
                sAl[(c4 * 4 + e) * GT_SA + r] = l;
            }
        }
        {
            int r = t >> 2, c4 = t & 3;
            int gn = bn + r;
            float4 v = make_float4(0.f, 0.f, 0.f, 0.f);
            if (gn < N)
                v = *reinterpret_cast<const float4*>(
                    W + (size_t)gn * K + k0 + c4 * 4);
            float vv[4] = {v.x, v.y, v.z, v.w};
            #pragma unroll
            for (int e = 0; e < 4; ++e) {
                unsigned h = f2tf32(vv[e]);
                unsigned l = f2tf32(vv[e] - __uint_as_float(h));
                sWh[(c4 * 4 + e) * GT_SW + r] = h;
                sWl[(c4 * 4 + e) * GT_SW + r] = l;
            }
        }
        __syncthreads();

        #pragma unroll
        for (int ks = 0; ks < 2; ++ks) {
            int kb = ks * 8;
            int ar = w * 16 + (lane >> 2);
            int ac = kb + (lane & 3);
            unsigned ah0 = sAh[ac * GT_SA + ar];
            unsigned ah1 = sAh[ac * GT_SA + ar + 8];
            unsigned ah2 = sAh[(ac + 4) * GT_SA + ar];
            unsigned ah3 = sAh[(ac + 4) * GT_SA + ar + 8];
            unsigned al0 = sAl[ac * GT_SA + ar];
            unsigned al1 = sAl[ac * GT_SA + ar + 8];
            unsigned al2 = sAl[(ac + 4) * GT_SA + ar];
            unsigned al3 = sAl[(ac + 4) * GT_SA + ar + 8];

            #pragma unroll
            for (int nf = 0; nf < 8; ++nf) {
                int bc = nf * 8 + (lane >> 2);
                int br = kb + (lane & 3);
                unsigned bh0 = sWh[br * GT_SW + bc];
                unsigned bh1 = sWh[(br + 4) * GT_SW + bc];
                unsigned bl0 = sWl[br * GT_SW + bc];
                unsigned bl1 = sWl[(br + 4) * GT_SW + bc];
                mma_tf32(acc[nf], ah0, ah1, ah2, ah3, bh0, bh1);
                mma_tf32(acc[nf], ah0, ah1, ah2, ah3, bl0, bl1);
                mma_tf32(acc[nf], al0, al1, al2, al3, bh0, bh1);
            }
        }
        __syncthreads();
    }

    const int mr0 = bm + w * 16 + (lane >> 2);
    const int nc0 = bn + (lane & 3) * 2;
    #pragma unroll
    for (int nf = 0; nf < 8; ++nf) {
        int n = nc0 + nf * 8;
        if (n >= N) continue;
        if (atomic) {
            if (mr0 < M) {
                atomicAdd(&C[(size_t)mr0 * ldc + n],     acc[nf][0]);
                atomicAdd(&C[(size_t)mr0 * ldc + n + 1], acc[nf][1]);
            }
            if (mr0 + 8 < M) {
                atomicAdd(&C[(size_t)(mr0 + 8) * ldc + n],     acc[nf][2]);
                atomicAdd(&C[(size_t)(mr0 + 8) * ldc + n + 1], acc[nf][3]);
            }
        } else {
            if (mr0 < M) {
                C[(size_t)mr0 * ldc + n]     = acc[nf][0];
                C[(size_t)mr0 * ldc + n + 1] = acc[nf][1];
            }
            if (mr0 + 8 < M) {
                C[(size_t)(mr0 + 8) * ldc + n]     = acc[nf][2];
                C[(size_t)(mr0 + 8) * ldc + n + 1] = acc[nf][3];
            }
        }
    }
}

// ---------------- tiled SGEMM with f32x2 (small GEMMs) ----------------
__global__ void __launch_bounds__(128)
gemm_kernel(const float* __restrict__ A, int lda,
            const float* __restrict__ W,
            const float* __restrict__ bias,
            float* __restrict__ C, int ldc,
            int M, int N, int K, float a_scale,
            int act, int atomic)
{
    __shared__ __align__(16) float As[16][68];
    __shared__ __align__(16) float Ws[16][68];

    const int bm = blockIdx.y * 64;
    const int bn = blockIdx.x * 64;
    const int t  = threadIdx.x;
    const int tx = t & 15;
    const int ty = t >> 4;

    const int nz   = gridDim.z;
    const int kPer = K / nz;
    const int kBeg = blockIdx.z * kPer;
    const int kEnd = kBeg + kPer;

    unsigned long long acc[4][4];
    #pragma unroll
    for (int i = 0; i < 4; ++i)
        #pragma unroll
        for (int j = 0; j < 4; ++j) acc[i][j] = 0ull;

    for (int k0 = kBeg; k0 < kEnd; k0 += 16) {
        #pragma unroll
        for (int it = 0; it < 2; ++it) {
            int idx = t + it * 128;
            int r = idx >> 2, c4 = idx & 3;
            {
                float4 v = *reinterpret_cast<const float4*>(
                    A + (size_t)(bm + r) * lda + k0 + c4 * 4);
                As[c4 * 4 + 0][r] = v.x * a_scale;
                As[c4 * 4 + 1][r] = v.y * a_scale;
                As[c4 * 4 + 2][r] = v.z * a_scale;
                As[c4 * 4 + 3][r] = v.w * a_scale;
            }
            {
                int gn = bn + r;
                float4 v = make_float4(0.f, 0.f, 0.f, 0.f);
                if (gn < N)
                    v = *reinterpret_cast<const float4*>(
                        W + (size_t)gn * K + k0 + c4 * 4);
                Ws[c4 * 4 + 0][r] = v.x;
                Ws[c4 * 4 + 1][r] = v.y;
                Ws[c4 * 4 + 2][r] = v.z;
                Ws[c4 * 4 + 3][r] = v.w;
            }
        }
        __syncthreads();

        #pragma unroll
        for (int kk = 0; kk < 16; ++kk) {
            const ulonglong2* ap =
                reinterpret_cast<const ulonglong2*>(&As[kk][ty * 8]);
            ulonglong2 am01 = ap[0];
            ulonglong2 am23 = ap[1];
            float4 wv = *reinterpret_cast<const float4*>(&Ws[kk][tx * 4]);
            unsigned long long pw0 = dup2(wv.x);
            unsigned long long pw1 = dup2(wv.y);
            unsigned long long pw2 = dup2(wv.z);
            unsigned long long pw3 = dup2(wv.w);
            ffma2(acc[0][0], am01.x, pw0); ffma2(acc[0][1], am01.x, pw1);
            ffma2(acc[0][2], am01.x, pw2); ffma2(acc[0][3], am01.x, pw3);
            ffma2(acc[1][0], am01.y, pw0); ffma2(acc[1][1], am01.y, pw1);
            ffma2(acc[1][2], am01.y, pw2); ffma2(acc[1][3], am01.y, pw3);
            ffma2(acc[2][0], am23.x, pw0); ffma2(acc[2][1], am23.x, pw1);
            ffma2(acc[2][2], am23.x, pw2); ffma2(acc[2][3], am23.x, pw3);
            ffma2(acc[3][0], am23.y, pw0); ffma2(acc[3][1], am23.y, pw1);
            ffma2(acc[3][2], am23.y, pw2); ffma2(acc[3][3], am23.y, pw3);
        }
        __syncthreads();
    }

    const int nbase = bn + tx * 4;
    #pragma unroll
    for (int i = 0; i < 4; ++i) {
        int m0 = bm + ty * 8 + 2 * i;
        float2 c0 = unpack2(acc[i][0]);
        float2 c1 = unpack2(acc[i][1]);
        float2 c2 = unpack2(acc[i][2]);
        float2 c3 = unpack2(acc[i][3]);
        float lo[4] = {c0.x, c1.x, c2.x, c3.x};
        float hi[4] = {c0.y, c1.y, c2.y, c3.y};
        if (atomic) {
            #pragma unroll
            for (int j = 0; j < 4; ++j) {
                int n = nbase + j;
                if (n < N) {
                    atomicAdd(&C[(size_t)m0 * ldc + n], lo[j]);
                    atomicAdd(&C[(size_t)(m0 + 1) * ldc + n], hi[j]);
                }
            }
        } else {
            #pragma unroll
            for (int j = 0; j < 4; ++j) {
                int n = nbase + j;
                if (n >= N) continue;
                float bv = bias ? bias[n] : 0.f;
                float v0 = lo[j] + bv, v1 = hi[j] + bv;
                if (act == 1) { v0 = fmaxf(v0, 0.f); v1 = fmaxf(v1, 0.f); }
                else if (act == 2) {
                    v0 = (v0 > 20.f) ? v0 : log1pf(expf(v0));
                    v1 = (v1 > 20.f) ? v1 : log1pf(expf(v1));
                }
                C[(size_t)m0 * ldc + n] = v0;
                C[(size_t)(m0 + 1) * ldc + n] = v1;
            }
        }
    }
}

// ---------------- fc bias + relu + sequence build (reversal at l=0) ----------------
__global__ void build_u_kernel(const float* __restrict__ fcacc, const float* __restrict__ fcb,
                               float* __restrict__ u)
{
    int idx = blockIdx.x * blockDim.x + threadIdx.x;
    if (idx >= NB * DMODEL) return;
    int b = idx >> 11, d = idx & 2047;
    float v = fmaxf(fcacc[idx] + fcb[d], 0.f);
    u[(2 * b + 1) * DMODEL + d] = v;
    u[(2 * b) * DMODEL + (DMODEL - 1 - d)] = v;
}

// ---------------- depthwise conv1d (L=2, causal k=4) + silu ----------------
__global__ void conv1d_silu_kernel(const float* __restrict__ xz, const float* __restrict__ w,
                                   const float* __restrict__ bias, float* __restrict__ xs)
{
    int idx = blockIdx.x * blockDim.x + threadIdx.x;
    if (idx >= NB * DINNER) return;
    int b = idx >> 12, e = idx & 4095;
    float x0 = xz[(2 * b) * (2 * DINNER) + e];
    float x1 = xz[(2 * b + 1) * (2 * DINNER) + e];
    float w2 = w[e * 4 + 2], w3 = w[e * 4 + 3];
    float bv = bias[e];
    float v0 = x0 * w3 + bv;
    float v1 = x0 * w2 + x1 * w3 + bv;
    xs[(2 * b) * DINNER + e]     = v0 / (1.f + expf(-v0));
    xs[(2 * b + 1) * DINNER + e] = v1 / (1.f + expf(-v1));
}

// ---------------- selective scan (L=2, closed form) + D skip + silu(z) gating --------
__global__ void scan_kernel(const float* __restrict__ xz, const float* __restrict__ xs,
                            const float* __restrict__ xdbl, const float* __restrict__ dt,
                            const float* __restrict__ A_log, const float* __restrict__ Dv,
                            float* __restrict__ y)
{
    int idx = blockIdx.x * blockDim.x + threadIdx.x;
    if (idx >= NB * DINNER) return;
    int b = idx >> 12, e = idx & 4095;

    float dt0 = dt[(2 * b) * DINNER + e];
    float dt1 = dt[(2 * b + 1) * DINNER + e];
    float x0  = xs[(2 * b) * DINNER + e];
    float x1  = xs[(2 * b + 1) * DINNER + e];
    float z1  = xz[(2 * b + 1) * (2 * DINNER) + DINNER + e];

    const float* bc0 = xdbl + (2 * b) * 160;
    const float* bc1 = xdbl + (2 * b + 1) * 160;

    float acc = 0.f;
    #pragma unroll
    for (int n = 0; n < DSTATE; ++n) {
        float Ae = -expf(A_log[e * DSTATE + n]);
        float h = dt0 * bc0[DTRANK + n] * x0;
        h = h * expf(dt1 * Ae) + dt1 * bc1[DTRANK + n] * x1;
        acc += h * bc1[DTRANK + DSTATE + n];
    }
    float yv = acc + x1 * Dv[e];
    float sg = z1 / (1.f + expf(-z1));
    y[b * DINNER + e] = yv * sg;
}

// ---------------- output heads ----------------
__global__ void heads_kernel(const float* __restrict__ feat,
                             const float* __restrict__ wxyz, const float* __restrict__ bxyz,
                             const float* __restrict__ wpqr, const float* __restrict__ bpqr,
                             float* __restrict__ out)
{
    int b = blockIdx.x / 7, j = blockIdx.x % 7;
    const float* wrow = (j < 3) ? (wxyz + j * DMODEL) : (wpqr + (j - 3) * DMODEL);
    float bias = (j < 3) ? bxyz[j] : bpqr[j - 3];

    float s = 0.f;
    for (int i = threadIdx.x; i < DMODEL; i += 128)
        s += feat[b * DMODEL + i] * wrow[i];

    __shared__ float red[4];
    #pragma unroll
    for (int off = 16; off; off >>= 1) s += __shfl_down_sync(0xffffffffu, s, off);
    if ((threadIdx.x & 31) == 0) red[threadIdx.x >> 5] = s;
    __syncthreads();
    if (threadIdx.x == 0)
        out[b * 7 + j] = red[0] + red[1] + red[2] + red[3] + bias;
}

// ---------------- launcher ----------------
extern "C" void kernel_launch(void* const* d_in, const int* in_sizes, int n_in,
                              void* d_out, int out_size)
{
    const float* x       = (const float*)d_in[0];
    const float* conv_w  = (const float*)d_in[1];
    const float* conv_b  = (const float*)d_in[2];
    const float* fc_w    = (const float*)d_in[3];
    const float* fc_b    = (const float*)d_in[4];
    const float* W_in    = (const float*)d_in[5];
    const float* c1w     = (const float*)d_in[6];
    const float* c1b     = (const float*)d_in[7];
    const float* W_xproj = (const float*)d_in[8];
    const float* W_dt    = (const float*)d_in[9];
    const float* b_dt    = (const float*)d_in[10];
    const float* A_log   = (const float*)d_in[11];
    const float* Dv      = (const float*)d_in[12];
    const float* W_out   = (const float*)d_in[13];
    const float* wxyz    = (const float*)d_in[14];
    const float* bxyz    = (const float*)d_in[15];
    const float* wpqr    = (const float*)d_in[16];
    const float* bpqr    = (const float*)d_in[17];
    float* out = (float*)d_out;

    void* sp = nullptr;
    cudaGetSymbolAddress(&sp, g_scratch);
    float* S = (float*)sp;

    float* f     = S + OFF_F;
    float* fcacc = S + OFF_FC;
    float* u     = S + OFF_U;
    float* xz    = S + OFF_XZ;
    float* xs    = S + OFF_XS;
    float* xdbl  = S + OFF_XDBL;
    float* dtb   = S + OFF_DT;
    float* y     = S + OFF_Y;
    float* feat  = S + OFF_FEAT;
    unsigned* wT = (unsigned*)(S + OFF_WT);

    cudaFuncSetAttribute(conv_tc_kernel,
                         cudaFuncAttributeMaxDynamicSharedMemorySize,
                         CONV_SMEM_TOTAL);

    // launch order arranged so launch #4 == conv_tc_kernel (ncu profiles #4)
    // (1) zero f+fcacc
    zero_kernel<<<(163840 + 255) / 256, 256>>>(f, 163840);
    // (2) zero xdbl
    zero_kernel<<<(20480 + 255) / 256, 256>>>(xdbl, 20480);
    // (3) conv weight transpose + tf32 convert
    prep_wt_kernel<<<(152 * 512 + 255) / 256, 256>>>(conv_w, wT);
    // (4) conv + relu + spatial sum (tensor cores)
    conv_tc_kernel<<<dim3(49, 32), 256, CONV_SMEM_TOTAL>>>(x, wT, conv_b, f);
    // (5) fc (mean scale folded in), split-K atomic
    gemm_kernel<<<dim3(32, 1, 4), 128>>>(f, 512, fc_w, nullptr, fcacc, 2048,
                                         64, 2048, 512, 1.f / 3136.f, 0, 1);
    // (6) bias+relu + sequence build
    build_u_kernel<<<512, 256>>>(fcacc, fc_b, u);
    // (7) xz = u @ W_in^T  (128 x 8192 x 2048) — tensor 3xTF32
    gemm_tc_kernel<<<dim3(128, 1, 1), 256>>>(u, 2048, W_in, xz, 8192,
                                             128, 8192, 2048, 0);
    // (8) depthwise conv1d + silu
    conv1d_silu_kernel<<<1024, 256>>>(xz, c1w, c1b, xs);
    // (9) x_dbl = xs @ W_xproj^T  (128 x 160 x 4096), split-K atomic
    gemm_kernel<<<dim3(3, 2, 16), 128>>>(xs, 4096, W_xproj, nullptr, xdbl, 160,
                                         128, 160, 4096, 1.f, 0, 1);
    // (10) dt = softplus(dt_low @ W_dt^T + b_dt)
    gemm_kernel<<<dim3(64, 2, 1), 128>>>(xdbl, 160, W_dt, b_dt, dtb, 4096,
                                         128, 4096, 128, 1.f, 2, 0);
    // (11) scan + gating -> y
    scan_kernel<<<1024, 256>>>(xz, xs, xdbl, dtb, A_log, Dv, y);
    // (12) zero feat
    zero_kernel<<<(131072 + 255) / 256, 256>>>(feat, 131072);
    // (13) feat = y @ W_out^T  (64 x 2048 x 4096) — tensor 3xTF32, split-K=4
    gemm_tc_kernel<<<dim3(32, 1, 4), 256>>>(y, 4096, W_out, feat, 2048,
                                            64, 2048, 4096, 1);
    // (14) heads
    heads_kernel<<<448, 128>>>(feat, wxyz, bxyz, wpqr, bpqr, out);
}

// round 8
// speedup vs baseline: 3.0663x; 1.1639x over previous
#include <cuda_runtime.h>
#include <math.h>

// ---------------- problem constants ----------------
#define NB      64
#define DMODEL  2048
#define DINNER  4096
#define DSTATE  16
#define DTRANK  128
#define FE      512

// ---------------- scratch layout (floats) ----------------
#define OFF_F     0          // 64*512      conv relu-sum accumulator
#define OFF_FC    32768      // 64*2048     fc split-K accumulator
#define OFF_U     163840     // 128*2048    mamba input u (rows = b*2+l)
#define OFF_XZ    425984     // 128*8192    xz = u @ W_in^T
#define OFF_XS    1474560    // 128*4096    silu(conv1d(x))
#define OFF_XDBL  1998848    // 128*160     x_dbl
#define OFF_DT    2019328    // 128*4096    dt (softplus)
#define OFF_Y     2543616    // 64*4096     gated scan output at l=1
#define OFF_FEAT  2805760    // 64*2048     y @ W_out^T
#define OFF_WT    2936832    // 76*512 uint2: packed tf32 conv weights (k,k+4 pairs)
#define SCRATCH_TOTAL 3014656

__device__ float g_scratch[SCRATCH_TOTAL];

// conv_tc dynamic smem layout (bytes)
#define CONV_SMEM_W     0                    // 76*68 uint2 = 41344
#define CONV_SMEM_ACC   41344                // 2*512 float = 4096
#define CONV_SMEM_IN    45440                // 2*3*35*35 tf32 = 29400
#define CONV_SMEM_TOTAL 74840

// ---------------- packed f32x2 helpers (Blackwell) ----------------
__device__ __forceinline__ void ffma2(unsigned long long& d,
                                      unsigned long long a, unsigned long long b) {
    asm volatile("fma.rn.f32x2 %0, %1, %2, %0;" : "+l"(d) : "l"(a), "l"(b));
}
__device__ __forceinline__ unsigned long long dup2(float x) {
    unsigned int u = __float_as_uint(x);
    unsigned long long r;
    asm("mov.b64 %0, {%1, %2};" : "=l"(r) : "r"(u), "r"(u));
    return r;
}
__device__ __forceinline__ float2 unpack2(unsigned long long v) {
    unsigned int lo, hi;
    asm("mov.b64 {%0, %1}, %2;" : "=r"(lo), "=r"(hi) : "l"(v));
    return make_float2(__uint_as_float(lo), __uint_as_float(hi));
}

// ---------------- tf32 mma helpers ----------------
__device__ __forceinline__ unsigned f2tf32(float v) {
    unsigned r;
    asm("cvt.rna.tf32.f32 %0, %1;" : "=r"(r) : "f"(v));
    return r;
}
__device__ __forceinline__ void mma_tf32(float c[4],
                                         unsigned a0, unsigned a1, unsigned a2, unsigned a3,
                                         unsigned b0, unsigned b1) {
    asm volatile(
        "mma.sync.aligned.m16n8k8.row.col.f32.tf32.tf32.f32 "
        "{%0,%1,%2,%3}, {%4,%5,%6,%7}, {%8,%9}, {%0,%1,%2,%3};"
        : "+f"(c[0]), "+f"(c[1]), "+f"(c[2]), "+f"(c[3])
        : "r"(a0), "r"(a1), "r"(a2), "r"(a3), "r"(b0), "r"(b1));
}

// ---------------- utility kernels ----------------
__global__ void zero_kernel(float* p, int n) {
    int i = blockIdx.x * blockDim.x + threadIdx.x;
    if (i < n) p[i] = 0.f;
}

// conv_w (512,3,7,7) -> packed tf32 pairs wTp[kp][co] = (w[k0], w[k0+4]),
// kp = ks*4 + j encodes k0 = ks*8 + j; zero-padded beyond k=146.
__global__ void prep_wt_kernel(const float* __restrict__ w, uint2* __restrict__ wTp) {
    int i = blockIdx.x * blockDim.x + threadIdx.x;
    if (i < 76 * 512) {
        int kp = i >> 9, co = i & 511;
        int k0 = (kp >> 2) * 8 + (kp & 3);
        int k1 = k0 + 4;
        float v0 = (k0 < 147) ? w[co * 147 + k0] : 0.f;
        float v1 = (k1 < 147) ? w[co * 147 + k1] : 0.f;
        wTp[kp * 512 + co] = make_uint2(f2tf32(v0), f2tf32(v1));
    }
}

// ---------------- conv 7x7 s4 p3 + bias + relu + spatial-sum (tensor cores) ----------
// grid (49, 32), block 128 (4 warps). Each block: 8x8 output tile of TWO images.
// Each warp: m32 (4 tile rows of one image) = two m16 fragments sharing B.
// Inner loop per k-step: 8 A LDS + 8 B LDS.64 + 16 MMA  (LDS/MMA = 1.0).
__global__ void __launch_bounds__(128)
conv_tc_kernel(const float* __restrict__ x, const uint2* __restrict__ wTp,
               const float* __restrict__ bias, float* __restrict__ f_accum)
{
    extern __shared__ __align__(16) char smem[];
    uint2*    s_w  = reinterpret_cast<uint2*>(smem + CONV_SMEM_W);       // [76][68]
    float*    s_acc = reinterpret_cast<float*>(smem + CONV_SMEM_ACC);    // [2][512]
    unsigned* s_in  = reinterpret_cast<unsigned*>(smem + CONV_SMEM_IN);  // [2][3][35][35] tf32

    const int t    = threadIdx.x;
    const int tile = blockIdx.x;
    const int bp   = blockIdx.y;            // image pair
    const int oh_base = (tile / 7) * 8;
    const int ow_base = (tile % 7) * 8;
    const int ih0 = oh_base * 4 - 3;
    const int iw0 = ow_base * 4 - 3;

    for (int i = t; i < 1024; i += 128) s_acc[i] = 0.f;

    // input tiles for both images, converted to tf32 bits once
    for (int i = t; i < 2 * 3 * 1225; i += 128) {
        int img = i / 3675;
        int rem = i - img * 3675;
        int ci  = rem / 1225; rem -= ci * 1225;
        int r = rem / 35, c = rem - (rem / 35) * 35;
        int ih = ih0 + r, iw = iw0 + c;
        float v = 0.f;
        int b = bp * 2 + img;
        if ((unsigned)ih < 224u && (unsigned)iw < 224u)
            v = x[((b * 3 + ci) * 224 + ih) * 224 + iw];
        s_in[(img * 3 + ci) * 1225 + r * 35 + c] = f2tf32(v);
    }

    const int lane = t & 31;
    const int w    = t >> 5;                // warp 0..3
    const int img  = w >> 1;                // image (2 warps per image)
    const int half = w & 1;                 // which 4 tile-rows
    const int q    = lane >> 2;             // column group 0..7
    const int j    = lane & 3;              // k-in-group
    const int ya = half * 16;               // first image row of warp's region
    const int xb = q * 4;
    const unsigned* my_in = s_in + img * 3675 + ya * 35 + xb;

    // per-thread k-step offset tables (register arrays; loop fully unrolled)
    int o0[19], o1[19];
    #pragma unroll
    for (int ks = 0; ks < 19; ++ks) {
        int k0 = ks * 8 + j, k1 = k0 + 4;
        int kk0 = min(k0, 146), kk1 = min(k1, 146);
        int ci0 = kk0 / 49, r0 = kk0 - ci0 * 49;
        int kh0 = r0 / 7,  kw0 = r0 - kh0 * 7;
        int ci1 = kk1 / 49, r1 = kk1 - ci1 * 49;
        int kh1 = r1 / 7,  kw1 = r1 - kh1 * 7;
        o0[ks] = ci0 * 1225 + kh0 * 35 + kw0;
        o1[ks] = ci1 * 1225 + kh1 * 35 + kw1;
    }

    for (int n0 = 0; n0 < 512; n0 += 64) {
        __syncthreads();
        // stage packed weight chunk: pure uint4 copy (2432 uint4)
        {
            const uint4* src = reinterpret_cast<const uint4*>(wTp);
            uint4* dst = reinterpret_cast<uint4*>(s_w);
            for (int i = t; i < 76 * 32; i += 128) {
                int row = i >> 5, c = i & 31;
                dst[row * 34 + c] = src[row * 256 + (n0 >> 1) + c];
            }
        }
        __syncthreads();

        float c[2][8][4];
        #pragma unroll
        for (int f2 = 0; f2 < 2; ++f2)
            #pragma unroll
            for (int nf = 0; nf < 8; ++nf)
                #pragma unroll
                for (int u2 = 0; u2 < 4; ++u2) c[f2][nf][u2] = 0.f;

        #pragma unroll
        for (int ks = 0; ks < 19; ++ks) {
            int p0 = o0[ks], p1 = o1[ks];
            unsigned aA0 = my_in[p0];
            unsigned aA1 = my_in[p0 + 140];
            unsigned aA2 = my_in[p1];
            unsigned aA3 = my_in[p1 + 140];
            unsigned aB0 = my_in[p0 + 280];
            unsigned aB1 = my_in[p0 + 420];
            unsigned aB2 = my_in[p1 + 280];
            unsigned aB3 = my_in[p1 + 420];
            const uint2* wr = s_w + (ks * 4 + j) * 68 + q;
            #pragma unroll
            for (int nf = 0; nf < 8; ++nf) {
                uint2 b2 = wr[nf * 8];
                mma_tf32(c[0][nf], aA0, aA1, aA2, aA3, b2.x, b2.y);
                mma_tf32(c[1][nf], aB0, aB1, aB2, aB3, b2.x, b2.y);
            }
        }

        // epilogue: bias + relu per position, reduce over positions
        #pragma unroll
        for (int nf = 0; nf < 8; ++nf) {
            int ca = n0 + nf * 8 + 2 * j;
            float bva = bias[ca], bvb = bias[ca + 1];
            float va = fmaxf(c[0][nf][0] + bva, 0.f) + fmaxf(c[0][nf][2] + bva, 0.f)
                     + fmaxf(c[1][nf][0] + bva, 0.f) + fmaxf(c[1][nf][2] + bva, 0.f);
            float vb = fmaxf(c[0][nf][1] + bvb, 0.f) + fmaxf(c[0][nf][3] + bvb, 0.f)
                     + fmaxf(c[1][nf][1] + bvb, 0.f) + fmaxf(c[1][nf][3] + bvb, 0.f);
            #pragma unroll
            for (int off = 16; off >= 4; off >>= 1) {
                va += __shfl_down_sync(0xffffffffu, va, off);
                vb += __shfl_down_sync(0xffffffffu, vb, off);
            }
            if (lane < 4) {
                atomicAdd(&s_acc[img * 512 + ca], va);
                atomicAdd(&s_acc[img * 512 + ca + 1], vb);
            }
        }
    }

    __syncthreads();
    for (int i = t; i < 1024; i += 128) {
        int im = i >> 9, ch = i & 511;
        atomicAdd(&f_accum[(bp * 2 + im) * 512 + ch], s_acc[im * 512 + ch]);
    }
}

// ---------------- tensor-core 3xTF32 GEMM: C[M,N] (+)= A[M,K] @ W[N,K]^T ----------
#define GT_SA 136
#define GT_SW 72
__global__ void __launch_bounds__(256)
gemm_tc_kernel(const float* __restrict__ A, int lda,
               const float* __restrict__ W,
               float* __restrict__ C, int ldc,
               int M, int N, int K, int atomic)
{
    __shared__ unsigned sAh[16 * GT_SA], sAl[16 * GT_SA];
    __shared__ unsigned sWh[16 * GT_SW], sWl[16 * GT_SW];

    const int bm = blockIdx.y * 128;
    const int bn = blockIdx.x * 64;
    const int t = threadIdx.x, lane = t & 31, w = t >> 5;
    const int kPer = K / gridDim.z;
    const int kBeg = blockIdx.z * kPer;

    float acc[8][4];
    #pragma unroll
    for (int nf = 0; nf < 8; ++nf)
        #pragma unroll
        for (int u2 = 0; u2 < 4; ++u2) acc[nf][u2] = 0.f;

    for (int k0 = kBeg; k0 < kBeg + kPer; k0 += 16) {
        #pragma unroll
        for (int it = 0; it < 2; ++it) {
            int idx = t + it * 256;
            int r = idx >> 2, c4 = idx & 3;
            int gr = min(bm + r, M - 1);
            float4 v = *reinterpret_cast<const float4*>(
                A + (size_t)gr * lda + k0 + c4 * 4);
            float vv[4] = {v.x, v.y, v.z, v.w};
            #pragma unroll
            for (int e = 0; e < 4; ++e) {
                unsigned h = f2tf32(vv[e]);
                unsigned l = f2tf32(vv[e] - __uint_as_float(h));
                sAh[(c4 * 4 + e) * GT_SA + r] = h;
                sAl[(c4 * 4 + e) * GT_SA + r] = l;
            }
        }
        {
            int r = t >> 2, c4 = t & 3;
            int gn = bn + r;
            float4 v = make_float4(0.f, 0.f, 0.f, 0.f);
            if (gn < N)
                v = *reinterpret_cast<const float4*>(
                    W + (size_t)gn * K + k0 + c4 * 4);
            float vv[4] = {v.x, v.y, v.z, v.w};
            #pragma unroll
            for (int e = 0; e < 4; ++e) {
                unsigned h = f2tf32(vv[e]);
                unsigned l = f2tf32(vv[e] - __uint_as_float(h));
                sWh[(c4 * 4 + e) * GT_SW + r] = h;
                sWl[(c4 * 4 + e) * GT_SW + r] = l;
            }
        }
        __syncthreads();

        #pragma unroll
        for (int ks = 0; ks < 2; ++ks) {
            int kb = ks * 8;
            int ar = w * 16 + (lane >> 2);
            int ac = kb + (lane & 3);
            unsigned ah0 = sAh[ac * GT_SA + ar];
            unsigned ah1 = sAh[ac * GT_SA + ar + 8];
            unsigned ah2 = sAh[(ac + 4) * GT_SA + ar];
            unsigned ah3 = sAh[(ac + 4) * GT_SA + ar + 8];
            unsigned al0 = sAl[ac * GT_SA + ar];
            unsigned al1 = sAl[ac * GT_SA + ar + 8];
            unsigned al2 = sAl[(ac + 4) * GT_SA + ar];
            unsigned al3 = sAl[(ac + 4) * GT_SA + ar + 8];

            #pragma unroll
            for (int nf = 0; nf < 8; ++nf) {
                int bc = nf * 8 + (lane >> 2);
                int br = kb + (lane & 3);
                unsigned bh0 = sWh[br * GT_SW + bc];
                unsigned bh1 = sWh[(br + 4) * GT_SW + bc];
                unsigned bl0 = sWl[br * GT_SW + bc];
                unsigned bl1 = sWl[(br + 4) * GT_SW + bc];
                mma_tf32(acc[nf], ah0, ah1, ah2, ah3, bh0, bh1);
                mma_tf32(acc[nf], ah0, ah1, ah2, ah3, bl0, bl1);
                mma_tf32(acc[nf], al0, al1, al2, al3, bh0, bh1);
            }
        }
        __syncthreads();
    }

    const int mr0 = bm + w * 16 + (lane >> 2);
    const int nc0 = bn + (lane & 3) * 2;
    #pragma unroll
    for (int nf = 0; nf < 8; ++nf) {
        int n = nc0 + nf * 8;
        if (n >= N) continue;
        if (atomic) {
            if (mr0 < M) {
                atomicAdd(&C[(size_t)mr0 * ldc + n],     acc[nf][0]);
                atomicAdd(&C[(size_t)mr0 * ldc + n + 1], acc[nf][1]);
            }
            if (mr0 + 8 < M) {
                atomicAdd(&C[(size_t)(mr0 + 8) * ldc + n],     acc[nf][2]);
                atomicAdd(&C[(size_t)(mr0 + 8) * ldc + n + 1], acc[nf][3]);
            }
        } else {
            if (mr0 < M) {
                C[(size_t)mr0 * ldc + n]     = acc[nf][0];
                C[(size_t)mr0 * ldc + n + 1] = acc[nf][1];
            }
            if (mr0 + 8 < M) {
                C[(size_t)(mr0 + 8) * ldc + n]     = acc[nf][2];
                C[(size_t)(mr0 + 8) * ldc + n + 1] = acc[nf][3];
            }
        }
    }
}

// ---------------- tiled SGEMM with f32x2 (small GEMMs) ----------------
__global__ void __launch_bounds__(128)
gemm_kernel(const float* __restrict__ A, int lda,
            const float* __restrict__ W,
            const float* __restrict__ bias,
            float* __restrict__ C, int ldc,
            int M, int N, int K, float a_scale,
            int act, int atomic)
{
    __shared__ __align__(16) float As[16][68];
    __shared__ __align__(16) float Ws[16][68];

    const int bm = blockIdx.y * 64;
    const int bn = blockIdx.x * 64;
    const int t  = threadIdx.x;
    const int tx = t & 15;
    const int ty = t >> 4;

    const int nz   = gridDim.z;
    const int kPer = K / nz;
    const int kBeg = blockIdx.z * kPer;
    const int kEnd = kBeg + kPer;

    unsigned long long acc[4][4];
    #pragma unroll
    for (int i = 0; i < 4; ++i)
        #pragma unroll
        for (int j = 0; j < 4; ++j) acc[i][j] = 0ull;

    for (int k0 = kBeg; k0 < kEnd; k0 += 16) {
        #pragma unroll
        for (int it = 0; it < 2; ++it) {
            int idx = t + it * 128;
            int r = idx >> 2, c4 = idx & 3;
            {
                float4 v = *reinterpret_cast<const float4*>(
                    A + (size_t)(bm + r) * lda + k0 + c4 * 4);
                As[c4 * 4 + 0][r] = v.x * a_scale;
                As[c4 * 4 + 1][r] = v.y * a_scale;
                As[c4 * 4 + 2][r] = v.z * a_scale;
                As[c4 * 4 + 3][r] = v.w * a_scale;
            }
            {
                int gn = bn + r;
                float4 v = make_float4(0.f, 0.f, 0.f, 0.f);
                if (gn < N)
                    v = *reinterpret_cast<const float4*>(
                        W + (size_t)gn * K + k0 + c4 * 4);
                Ws[c4 * 4 + 0][r] = v.x;
                Ws[c4 * 4 + 1][r] = v.y;
                Ws[c4 * 4 + 2][r] = v.z;
                Ws[c4 * 4 + 3][r] = v.w;
            }
        }
        __syncthreads();

        #pragma unroll
        for (int kk = 0; kk < 16; ++kk) {
            const ulonglong2* ap =
                reinterpret_cast<const ulonglong2*>(&As[kk][ty * 8]);
            ulonglong2 am01 = ap[0];
            ulonglong2 am23 = ap[1];
            float4 wv = *reinterpret_cast<const float4*>(&Ws[kk][tx * 4]);
            unsigned long long pw0 = dup2(wv.x);
            unsigned long long pw1 = dup2(wv.y);
            unsigned long long pw2 = dup2(wv.z);
            unsigned long long pw3 = dup2(wv.w);
            ffma2(acc[0][0], am01.x, pw0); ffma2(acc[0][1], am01.x, pw1);
            ffma2(acc[0][2], am01.x, pw2); ffma2(acc[0][3], am01.x, pw3);
            ffma2(acc[1][0], am01.y, pw0); ffma2(acc[1][1], am01.y, pw1);
            ffma2(acc[1][2], am01.y, pw2); ffma2(acc[1][3], am01.y, pw3);
            ffma2(acc[2][0], am23.x, pw0); ffma2(acc[2][1], am23.x, pw1);
            ffma2(acc[2][2], am23.x, pw2); ffma2(acc[2][3], am23.x, pw3);
            ffma2(acc[3][0], am23.y, pw0); ffma2(acc[3][1], am23.y, pw1);
            ffma2(acc[3][2], am23.y, pw2); ffma2(acc[3][3], am23.y, pw3);
        }
        __syncthreads();
    }

    const int nbase = bn + tx * 4;
    #pragma unroll
    for (int i = 0; i < 4; ++i) {
        int m0 = bm + ty * 8 + 2 * i;
        float2 c0 = unpack2(acc[i][0]);
        float2 c1 = unpack2(acc[i][1]);
        float2 c2 = unpack2(acc[i][2]);
        float2 c3 = unpack2(acc[i][3]);
        float lo[4] = {c0.x, c1.x, c2.x, c3.x};
        float hi[4] = {c0.y, c1.y, c2.y, c3.y};
        if (atomic) {
            #pragma unroll
            for (int j = 0; j < 4; ++j) {
                int n = nbase + j;
                if (n < N) {
                    atomicAdd(&C[(size_t)m0 * ldc + n], lo[j]);
                    atomicAdd(&C[(size_t)(m0 + 1) * ldc + n], hi[j]);
                }
            }
        } else {
            #pragma unroll
            for (int j = 0; j < 4; ++j) {
                int n = nbase + j;
                if (n >= N) continue;
                float bv = bias ? bias[n] : 0.f;
                float v0 = lo[j] + bv, v1 = hi[j] + bv;
                if (act == 1) { v0 = fmaxf(v0, 0.f); v1 = fmaxf(v1, 0.f); }
                else if (act == 2) {
                    v0 = (v0 > 20.f) ? v0 : log1pf(expf(v0));
                    v1 = (v1 > 20.f) ? v1 : log1pf(expf(v1));
                }
                C[(size_t)m0 * ldc + n] = v0;
                C[(size_t)(m0 + 1) * ldc + n] = v1;
            }
        }
    }
}

// ---------------- fc bias + relu + sequence build (reversal at l=0) ----------------
__global__ void build_u_kernel(const float* __restrict__ fcacc, const float* __restrict__ fcb,
                               float* __restrict__ u)
{
    int idx = blockIdx.x * blockDim.x + threadIdx.x;
    if (idx >= NB * DMODEL) return;
    int b = idx >> 11, d = idx & 2047;
    float v = fmaxf(fcacc[idx] + fcb[d], 0.f);
    u[(2 * b + 1) * DMODEL + d] = v;
    u[(2 * b) * DMODEL + (DMODEL - 1 - d)] = v;
}

// ---------------- depthwise conv1d (L=2, causal k=4) + silu ----------------
__global__ void conv1d_silu_kernel(const float* __restrict__ xz, const float* __restrict__ w,
                                   const float* __restrict__ bias, float* __restrict__ xs)
{
    int idx = blockIdx.x * blockDim.x + threadIdx.x;
    if (idx >= NB * DINNER) return;
    int b = idx >> 12, e = idx & 4095;
    float x0 = xz[(2 * b) * (2 * DINNER) + e];
    float x1 = xz[(2 * b + 1) * (2 * DINNER) + e];
    float w2 = w[e * 4 + 2], w3 = w[e * 4 + 3];
    float bv = bias[e];
    float v0 = x0 * w3 + bv;
    float v1 = x0 * w2 + x1 * w3 + bv;
    xs[(2 * b) * DINNER + e]     = v0 / (1.f + expf(-v0));
    xs[(2 * b + 1) * DINNER + e] = v1 / (1.f + expf(-v1));
}

// ---------------- selective scan (L=2, closed form) + D skip + silu(z) gating --------
__global__ void scan_kernel(const float* __restrict__ xz, const float* __restrict__ xs,
                            const float* __restrict__ xdbl, const float* __restrict__ dt,
                            const float* __restrict__ A_log, const float* __restrict__ Dv,
                            float* __restrict__ y)
{
    int idx = blockIdx.x * blockDim.x + threadIdx.x;
    if (idx >= NB * DINNER) return;
    int b = idx >> 12, e = idx & 4095;

    float dt0 = dt[(2 * b) * DINNER + e];
    float dt1 = dt[(2 * b + 1) * DINNER + e];
    float x0  = xs[(2 * b) * DINNER + e];
    float x1  = xs[(2 * b + 1) * DINNER + e];
    float z1  = xz[(2 * b + 1) * (2 * DINNER) + DINNER + e];

    const float* bc0 = xdbl + (2 * b) * 160;
    const float* bc1 = xdbl + (2 * b + 1) * 160;

    float acc = 0.f;
    #pragma unroll
    for (int n = 0; n < DSTATE; ++n) {
        float Ae = -expf(A_log[e * DSTATE + n]);
        float h = dt0 * bc0[DTRANK + n] * x0;
        h = h * expf(dt1 * Ae) + dt1 * bc1[DTRANK + n] * x1;
        acc += h * bc1[DTRANK + DSTATE + n];
    }
    float yv = acc + x1 * Dv[e];
    float sg = z1 / (1.f + expf(-z1));
    y[b * DINNER + e] = yv * sg;
}

// ---------------- output heads ----------------
__global__ void heads_kernel(const float* __restrict__ feat,
                             const float* __restrict__ wxyz, const float* __restrict__ bxyz,
                             const float* __restrict__ wpqr, const float* __restrict__ bpqr,
                             float* __restrict__ out)
{
    int b = blockIdx.x / 7, j = blockIdx.x % 7;
    const float* wrow = (j < 3) ? (wxyz + j * DMODEL) : (wpqr + (j - 3) * DMODEL);
    float bias = (j < 3) ? bxyz[j] : bpqr[j - 3];

    float s = 0.f;
    for (int i = threadIdx.x; i < DMODEL; i += 128)
        s += feat[b * DMODEL + i] * wrow[i];

    __shared__ float red[4];
    #pragma unroll
    for (int off = 16; off; off >>= 1) s += __shfl_down_sync(0xffffffffu, s, off);
    if ((threadIdx.x & 31) == 0) red[threadIdx.x >> 5] = s;
    __syncthreads();
    if (threadIdx.x == 0)
        out[b * 7 + j] = red[0] + red[1] + red[2] + red[3] + bias;
}

// ---------------- launcher ----------------
extern "C" void kernel_launch(void* const* d_in, const int* in_sizes, int n_in,
                              void* d_out, int out_size)
{
    const float* x       = (const float*)d_in[0];
    const float* conv_w  = (const float*)d_in[1];
    const float* conv_b  = (const float*)d_in[2];
    const float* fc_w    = (const float*)d_in[3];
    const float* fc_b    = (const float*)d_in[4];
    const float* W_in    = (const float*)d_in[5];
    const float* c1w     = (const float*)d_in[6];
    const float* c1b     = (const float*)d_in[7];
    const float* W_xproj = (const float*)d_in[8];
    const float* W_dt    = (const float*)d_in[9];
    const float* b_dt    = (const float*)d_in[10];
    const float* A_log   = (const float*)d_in[11];
    const float* Dv      = (const float*)d_in[12];
    const float* W_out   = (const float*)d_in[13];
    const float* wxyz    = (const float*)d_in[14];
    const float* bxyz    = (const float*)d_in[15];
    const float* wpqr    = (const float*)d_in[16];
    const float* bpqr    = (const float*)d_in[17];
    float* out = (float*)d_out;

    void* sp = nullptr;
    cudaGetSymbolAddress(&sp, g_scratch);
    float* S = (float*)sp;

    float* f     = S + OFF_F;
    float* fcacc = S + OFF_FC;
    float* u     = S + OFF_U;
    float* xz    = S + OFF_XZ;
    float* xs    = S + OFF_XS;
    float* xdbl  = S + OFF_XDBL;
    float* dtb   = S + OFF_DT;
    float* y     = S + OFF_Y;
    float* feat  = S + OFF_FEAT;
    uint2* wTp   = (uint2*)(S + OFF_WT);

    cudaFuncSetAttribute(conv_tc_kernel,
                         cudaFuncAttributeMaxDynamicSharedMemorySize,
                         CONV_SMEM_TOTAL);

    // launch order arranged so launch #4 == conv_tc_kernel (ncu profiles #4)
    // (1) zero f+fcacc
    zero_kernel<<<(163840 + 255) / 256, 256>>>(f, 163840);
    // (2) zero xdbl
    zero_kernel<<<(20480 + 255) / 256, 256>>>(xdbl, 20480);
    // (3) conv weight transpose + tf32 pack
    prep_wt_kernel<<<(76 * 512 + 255) / 256, 256>>>(conv_w, wTp);
    // (4) conv + relu + spatial sum (tensor cores)
    conv_tc_kernel<<<dim3(49, 32), 128, CONV_SMEM_TOTAL>>>(x, wTp, conv_b, f);
    // (5) fc (mean scale folded in), split-K atomic
    gemm_kernel<<<dim3(32, 1, 4), 128>>>(f, 512, fc_w, nullptr, fcacc, 2048,
                                         64, 2048, 512, 1.f / 3136.f, 0, 1);
    // (6) bias+relu + sequence build
    build_u_kernel<<<512, 256>>>(fcacc, fc_b, u);
    // (7) xz = u @ W_in^T  (128 x 8192 x 2048) — tensor 3xTF32
    gemm_tc_kernel<<<dim3(128, 1, 1), 256>>>(u, 2048, W_in, xz, 8192,
                                             128, 8192, 2048, 0);
    // (8) depthwise conv1d + silu
    conv1d_silu_kernel<<<1024, 256>>>(xz, c1w, c1b, xs);
    // (9) x_dbl = xs @ W_xproj^T  (128 x 160 x 4096), split-K atomic
    gemm_kernel<<<dim3(3, 2, 16), 128>>>(xs, 4096, W_xproj, nullptr, xdbl, 160,
                                         128, 160, 4096, 1.f, 0, 1);
    // (10) dt = softplus(dt_low @ W_dt^T + b_dt)
    gemm_kernel<<<dim3(64, 2, 1), 128>>>(xdbl, 160, W_dt, b_dt, dtb, 4096,
                                         128, 4096, 128, 1.f, 2, 0);
    // (11) scan + gating -> y
    scan_kernel<<<1024, 256>>>(xz, xs, xdbl, dtb, A_log, Dv, y);
    // (12) zero feat
    zero_kernel<<<(131072 + 255) / 256, 256>>>(feat, 131072);
    // (13) feat = y @ W_out^T  (64 x 2048 x 4096) — tensor 3xTF32, split-K=4
    gemm_tc_kernel<<<dim3(32, 1, 4), 256>>>(y, 4096, W_out, feat, 2048,
                                            64, 2048, 4096, 1);
    // (14) heads
    heads_kernel<<<448, 128>>>(feat, wxyz, bxyz, wpqr, bpqr, out);
}

// round 10
// speedup vs baseline: 3.1527x; 1.0282x over previous
#include <cuda_runtime.h>
#include <math.h>

// ---------------- problem constants ----------------
#define NB      64
#define DMODEL  2048
#define DINNER  4096
#define DSTATE  16
#define DTRANK  128
#define FE      512

// ---------------- scratch layout (floats) ----------------
#define OFF_F     0          // 64*512      conv relu-sum accumulator
#define OFF_FC    32768      // 64*2048     fc split-K accumulator
#define OFF_U     163840     // 128*2048    mamba input u (rows = b*2+l)
#define OFF_XZ    425984     // 128*8192    xz = u @ W_in^T
#define OFF_XS    1474560    // 128*4096    silu(conv1d(x))
#define OFF_XDBL  1998848    // 128*160     x_dbl
#define OFF_DT    2019328    // 128*4096    dt (softplus)
#define OFF_Y     2543616    // 64*4096     gated scan output at l=1
#define OFF_FEAT  2805760    // 64*2048     y @ W_out^T
#define OFF_WT    2936832    // 76*512 uint2: packed tf32 conv weights (k,k+4 pairs)
#define SCRATCH_TOTAL 3014656

__device__ float g_scratch[SCRATCH_TOTAL];

// conv_tc dynamic smem layout (bytes) — 32-channel weight chunks
#define CONV_SMEM_W     0                    // 76*36 uint2 = 21888
#define CONV_SMEM_ACC   21888                // 2*512 float = 4096
#define CONV_SMEM_IN    25984                // 2*3*35*35 tf32 = 29400
#define CONV_SMEM_TOTAL 55384

// ---------------- packed f32x2 helpers (Blackwell) ----------------
__device__ __forceinline__ void ffma2(unsigned long long& d,
                                      unsigned long long a, unsigned long long b) {
    asm volatile("fma.rn.f32x2 %0, %1, %2, %0;" : "+l"(d) : "l"(a), "l"(b));
}
__device__ __forceinline__ unsigned long long dup2(float x) {
    unsigned int u = __float_as_uint(x);
    unsigned long long r;
    asm("mov.b64 %0, {%1, %2};" : "=l"(r) : "r"(u), "r"(u));
    return r;
}
__device__ __forceinline__ float2 unpack2(unsigned long long v) {
    unsigned int lo, hi;
    asm("mov.b64 {%0, %1}, %2;" : "=r"(lo), "=r"(hi) : "l"(v));
    return make_float2(__uint_as_float(lo), __uint_as_float(hi));
}

// ---------------- tf32 mma helpers ----------------
__device__ __forceinline__ unsigned f2tf32(float v) {
    unsigned r;
    asm("cvt.rna.tf32.f32 %0, %1;" : "=r"(r) : "f"(v));
    return r;
}
__device__ __forceinline__ void mma_tf32(float c[4],
                                         unsigned a0, unsigned a1, unsigned a2, unsigned a3,
                                         unsigned b0, unsigned b1) {
    asm volatile(
        "mma.sync.aligned.m16n8k8.row.col.f32.tf32.tf32.f32 "
        "{%0,%1,%2,%3}, {%4,%5,%6,%7}, {%8,%9}, {%0,%1,%2,%3};"
        : "+f"(c[0]), "+f"(c[1]), "+f"(c[2]), "+f"(c[3])
        : "r"(a0), "r"(a1), "r"(a2), "r"(a3), "r"(b0), "r"(b1));
}

// ---------------- utility kernels ----------------
__global__ void zero_kernel(float* p, int n) {
    int i = blockIdx.x * blockDim.x + threadIdx.x;
    if (i < n) p[i] = 0.f;
}

// conv_w (512,3,7,7) -> packed tf32 pairs wTp[kp][co] = (w[k0], w[k0+4]),
// kp = ks*4 + j encodes k0 = ks*8 + j; zero-padded beyond k=146.
__global__ void prep_wt_kernel(const float* __restrict__ w, uint2* __restrict__ wTp) {
    int i = blockIdx.x * blockDim.x + threadIdx.x;
    if (i < 76 * 512) {
        int kp = i >> 9, co = i & 511;
        int k0 = (kp >> 2) * 8 + (kp & 3);
        int k1 = k0 + 4;
        float v0 = (k0 < 147) ? w[co * 147 + k0] : 0.f;
        float v1 = (k1 < 147) ? w[co * 147 + k1] : 0.f;
        wTp[kp * 512 + co] = make_uint2(f2tf32(v0), f2tf32(v1));
    }
}

// ---------------- conv 7x7 s4 p3 + bias + relu + spatial-sum (tensor cores) ----------
// grid (49, 32), block 128 (4 warps). Each block: 8x8 output tile of TWO images.
// Each warp: m32 (4 tile rows of one image) = two m16 fragments sharing B.
// N chunked by 32 channels (8 chunks) -> 55.4 KB smem -> 4 blocks/SM.
__global__ void __launch_bounds__(128)
conv_tc_kernel(const float* __restrict__ x, const uint2* __restrict__ wTp,
               const float* __restrict__ bias, float* __restrict__ f_accum)
{
    extern __shared__ __align__(16) char smem[];
    uint2*    s_w  = reinterpret_cast<uint2*>(smem + CONV_SMEM_W);       // [76][36]
    float*    s_acc = reinterpret_cast<float*>(smem + CONV_SMEM_ACC);    // [2][512]
    unsigned* s_in  = reinterpret_cast<unsigned*>(smem + CONV_SMEM_IN);  // [2][3][35][35] tf32

    const int t    = threadIdx.x;
    const int tile = blockIdx.x;
    const int bp   = blockIdx.y;            // image pair
    const int oh_base = (tile / 7) * 8;
    const int ow_base = (tile % 7) * 8;
    const int ih0 = oh_base * 4 - 3;
    const int iw0 = ow_base * 4 - 3;

    for (int i = t; i < 1024; i += 128) s_acc[i] = 0.f;

    // input tiles for both images, converted to tf32 bits once
    for (int i = t; i < 2 * 3 * 1225; i += 128) {
        int img = i / 3675;
        int rem = i - img * 3675;
        int ci  = rem / 1225; rem -= ci * 1225;
        int r = rem / 35, c = rem - (rem / 35) * 35;
        int ih = ih0 + r, iw = iw0 + c;
        float v = 0.f;
        int b = bp * 2 + img;
        if ((unsigned)ih < 224u && (unsigned)iw < 224u)
            v = x[((b * 3 + ci) * 224 + ih) * 224 + iw];
        s_in[(img * 3 + ci) * 1225 + r * 35 + c] = f2tf32(v);
    }

    const int lane = t & 31;
    const int w    = t >> 5;                // warp 0..3
    const int img  = w >> 1;                // image (2 warps per image)
    const int half = w & 1;                 // which 4 tile-rows
    const int q    = lane >> 2;             // column group 0..7
    const int j    = lane & 3;              // k-in-group
    const int ya = half * 16;               // first image row of warp's region
    const int xb = q * 4;
    const unsigned* my_in = s_in + img * 3675 + ya * 35 + xb;

    // per-thread k-step offset tables (register arrays; loop fully unrolled)
    int o0[19], o1[19];
    #pragma unroll
    for (int ks = 0; ks < 19; ++ks) {
        int k0 = ks * 8 + j, k1 = k0 + 4;
        int kk0 = min(k0, 146), kk1 = min(k1, 146);
        int ci0 = kk0 / 49, r0 = kk0 - ci0 * 49;
        int kh0 = r0 / 7,  kw0 = r0 - kh0 * 7;
        int ci1 = kk1 / 49, r1 = kk1 - ci1 * 49;
        int kh1 = r1 / 7,  kw1 = r1 - kh1 * 7;
        o0[ks] = ci0 * 1225 + kh0 * 35 + kw0;
        o1[ks] = ci1 * 1225 + kh1 * 35 + kw1;
    }

    for (int n0 = 0; n0 < 512; n0 += 32) {
        __syncthreads();
        // stage packed weight chunk: 76 rows x 32 channels = 16 uint4/row
        // (one uint4 = 2 packed uint2 channels -> 16 uint4 = 32 channels)
        {
            const uint4* src = reinterpret_cast<const uint4*>(wTp);
            uint4* dst = reinterpret_cast<uint4*>(s_w);
            for (int i = t; i < 76 * 16; i += 128) {
                int row = i >> 4, c = i & 15;
                dst[row * 18 + c] = src[row * 256 + (n0 >> 1) + c];
            }
        }
        __syncthreads();

        float c[2][4][4];
        #pragma unroll
        for (int f2 = 0; f2 < 2; ++f2)
            #pragma unroll
            for (int nf = 0; nf < 4; ++nf)
                #pragma unroll
                for (int u2 = 0; u2 < 4; ++u2) c[f2][nf][u2] = 0.f;

        #pragma unroll
        for (int ks = 0; ks < 19; ++ks) {
            int p0 = o0[ks], p1 = o1[ks];
            unsigned aA0 = my_in[p0];
            unsigned aA1 = my_in[p0 + 140];
            unsigned aA2 = my_in[p1];
            unsigned aA3 = my_in[p1 + 140];
            unsigned aB0 = my_in[p0 + 280];
            unsigned aB1 = my_in[p0 + 420];
            unsigned aB2 = my_in[p1 + 280];
            unsigned aB3 = my_in[p1 + 420];
            const uint2* wr = s_w + (ks * 4 + j) * 36 + q;
            #pragma unroll
            for (int nf = 0; nf < 4; ++nf) {
                uint2 b2 = wr[nf * 8];
                mma_tf32(c[0][nf], aA0, aA1, aA2, aA3, b2.x, b2.y);
                mma_tf32(c[1][nf], aB0, aB1, aB2, aB3, b2.x, b2.y);
            }
        }

        // epilogue: bias + relu per position, reduce over positions
        #pragma unroll
        for (int nf = 0; nf < 4; ++nf) {
            int ca = n0 + nf * 8 + 2 * j;
            float bva = bias[ca], bvb = bias[ca + 1];
            float va = fmaxf(c[0][nf][0] + bva, 0.f) + fmaxf(c[0][nf][2] + bva, 0.f)
                     + fmaxf(c[1][nf][0] + bva, 0.f) + fmaxf(c[1][nf][2] + bva, 0.f);
            float vb = fmaxf(c[0][nf][1] + bvb, 0.f) + fmaxf(c[0][nf][3] + bvb, 0.f)
                     + fmaxf(c[1][nf][1] + bvb, 0.f) + fmaxf(c[1][nf][3] + bvb, 0.f);
            #pragma unroll
            for (int off = 16; off >= 4; off >>= 1) {
                va += __shfl_down_sync(0xffffffffu, va, off);
                vb += __shfl_down_sync(0xffffffffu, vb, off);
            }
            if (lane < 4) {
                atomicAdd(&s_acc[img * 512 + ca], va);
                atomicAdd(&s_acc[img * 512 + ca + 1], vb);
            }
        }
    }

    __syncthreads();
    for (int i = t; i < 1024; i += 128) {
        int im = i >> 9, ch = i & 511;
        atomicAdd(&f_accum[(bp * 2 + im) * 512 + ch], s_acc[im * 512 + ch]);
    }
}

// ---------------- tensor-core 3xTF32 GEMM (pipelined): C[M,N] (+)= A @ W^T --------
// BM=128, BN=64, BK=16, 256 threads. Register prefetch of next k-tile overlaps
// global-load latency with the MMA section.
#define GT_SA 136
#define GT_SW 72
__global__ void __launch_bounds__(256)
gemm_tc_kernel(const float* __restrict__ A, int lda,
               const float* __restrict__ W,
               float* __restrict__ C, int ldc,
               int M, int N, int K, int atomic)
{
    __shared__ unsigned sAh[16 * GT_SA], sAl[16 * GT_SA];
    __shared__ unsigned sWh[16 * GT_SW], sWl[16 * GT_SW];

    const int bm = blockIdx.y * 128;
    const int bn = blockIdx.x * 64;
    const int t = threadIdx.x, lane = t & 31, w = t >> 5;
    const int kPer = K / gridDim.z;
    const int kBeg = blockIdx.z * kPer;
    const int kEnd = kBeg + kPer;

    // fixed load coordinates for this thread
    const int rA0 = t >> 2,   cA = t & 3;          // A row pair 0 (rows 0..63)
    const int rA1 = rA0 + 64;                       // A row pair 1
    const int gA0 = min(bm + rA0, M - 1);
    const int gA1 = min(bm + rA1, M - 1);
    const int gW  = bn + rA0;                       // W row (rA0 in 0..63)
    const bool wOk = (gW < N);

    float acc[8][4];
    #pragma unroll
    for (int nf = 0; nf < 8; ++nf)
        #pragma unroll
        for (int u2 = 0; u2 < 4; ++u2) acc[nf][u2] = 0.f;

    // prefetch first k-tile
    float4 rAv0 = *reinterpret_cast<const float4*>(A + (size_t)gA0 * lda + kBeg + cA * 4);
    float4 rAv1 = *reinterpret_cast<const float4*>(A + (size_t)gA1 * lda + kBeg + cA * 4);
    float4 rWv  = wOk ? *reinterpret_cast<const float4*>(W + (size_t)gW * K + kBeg + cA * 4)
                      : make_float4(0.f, 0.f, 0.f, 0.f);

    for (int k0 = kBeg; k0 < kEnd; k0 += 16) {
        // store current tile to smem (hi/lo split)
        {
            float vv0[4] = {rAv0.x, rAv0.y, rAv0.z, rAv0.w};
            float vv1[4] = {rAv1.x, rAv1.y, rAv1.z, rAv1.w};
            float vvW[4] = {rWv.x, rWv.y, rWv.z, rWv.w};
            #pragma unroll
            for (int e = 0; e < 4; ++e) {
                unsigned h0 = f2tf32(vv0[e]);
                sAh[(cA * 4 + e) * GT_SA + rA0] = h0;
                sAl[(cA * 4 + e) * GT_SA + rA0] = f2tf32(vv0[e] - __uint_as_float(h0));
                unsigned h1 = f2tf32(vv1[e]);
                sAh[(cA * 4 + e) * GT_SA + rA1] = h1;
                sAl[(cA * 4 + e) * GT_SA + rA1] = f2tf32(vv1[e] - __uint_as_float(h1));
                unsigned hw = f2tf32(vvW[e]);
                sWh[(cA * 4 + e) * GT_SW + rA0] = hw;
                sWl[(cA * 4 + e) * GT_SW + rA0] = f2tf32(vvW[e] - __uint_as_float(hw));
            }
        }
        __syncthreads();

        // issue next tile's loads (latency overlapped with MMAs below)
        int kn = k0 + 16;
        if (kn < kEnd) {
            rAv0 = *reinterpret_cast<const float4*>(A + (size_t)gA0 * lda + kn + cA * 4);
            rAv1 = *reinterpret_cast<const float4*>(A + (size_t)gA1 * lda + kn + cA * 4);
            if (wOk)
                rWv = *reinterpret_cast<const float4*>(W + (size_t)gW * K + kn + cA * 4);
        }

        #pragma unroll
        for (int ks = 0; ks < 2; ++ks) {
            int kb = ks * 8;
            int ar = w * 16 + (lane >> 2);
            int ac = kb + (lane & 3);
            unsigned ah0 = sAh[ac * GT_SA + ar];
            unsigned ah1 = sAh[ac * GT_SA + ar + 8];
            unsigned ah2 = sAh[(ac + 4) * GT_SA + ar];
            unsigned ah3 = sAh[(ac + 4) * GT_SA + ar + 8];
            unsigned al0 = sAl[ac * GT_SA + ar];
            unsigned al1 = sAl[ac * GT_SA + ar + 8];
            unsigned al2 = sAl[(ac + 4) * GT_SA + ar];
            unsigned al3 = sAl[(ac + 4) * GT_SA + ar + 8];

            #pragma unroll
            for (int nf = 0; nf < 8; ++nf) {
                int bc = nf * 8 + (lane >> 2);
                int br = kb + (lane & 3);
                unsigned bh0 = sWh[br * GT_SW + bc];
                unsigned bh1 = sWh[(br + 4) * GT_SW + bc];
                unsigned bl0 = sWl[br * GT_SW + bc];
                unsigned bl1 = sWl[(br + 4) * GT_SW + bc];
                mma_tf32(acc[nf], ah0, ah1, ah2, ah3, bh0, bh1);
                mma_tf32(acc[nf], ah0, ah1, ah2, ah3, bl0, bl1);
                mma_tf32(acc[nf], al0, al1, al2, al3, bh0, bh1);
            }
        }
        __syncthreads();
    }

    const int mr0 = bm + w * 16 + (lane >> 2);
    const int nc0 = bn + (lane & 3) * 2;
    #pragma unroll
    for (int nf = 0; nf < 8; ++nf) {
        int n = nc0 + nf * 8;
        if (n >= N) continue;
        if (atomic) {
            if (mr0 < M) {
                atomicAdd(&C[(size_t)mr0 * ldc + n],     acc[nf][0]);
                atomicAdd(&C[(size_t)mr0 * ldc + n + 1], acc[nf][1]);
            }
            if (mr0 + 8 < M) {
                atomicAdd(&C[(size_t)(mr0 + 8) * ldc + n],     acc[nf][2]);
                atomicAdd(&C[(size_t)(mr0 + 8) * ldc + n + 1], acc[nf][3]);
            }
        } else {
            if (mr0 < M) {
                C[(size_t)mr0 * ldc + n]     = acc[nf][0];
                C[(size_t)mr0 * ldc + n + 1] = acc[nf][1];
            }
            if (mr0 + 8 < M) {
                C[(size_t)(mr0 + 8) * ldc + n]     = acc[nf][2];
                C[(size_t)(mr0 + 8) * ldc + n + 1] = acc[nf][3];
            }
        }
    }
}

// ---------------- tiled SGEMM with f32x2 (small GEMMs) ----------------
__global__ void __launch_bounds__(128)
gemm_kernel(const float* __restrict__ A, int lda,
            const float* __restrict__ W,
            const float* __restrict__ bias,
            float* __restrict__ C, int ldc,
            int M, int N, int K, float a_scale,
            int act, int atomic)
{
    __shared__ __align__(16) float As[16][68];
    __shared__ __align__(16) float Ws[16][68];

    const int bm = blockIdx.y * 64;
    const int bn = blockIdx.x * 64;
    const int t  = threadIdx.x;
    const int tx = t & 15;
    const int ty = t >> 4;

    const int nz   = gridDim.z;
    const int kPer = K / nz;
    const int kBeg = blockIdx.z * kPer;
    const int kEnd = kBeg + kPer;

    unsigned long long acc[4][4];
    #pragma unroll
    for (int i = 0; i < 4; ++i)
        #pragma unroll
        for (int j = 0; j < 4; ++j) acc[i][j] = 0ull;

    for (int k0 = kBeg; k0 < kEnd; k0 += 16) {
        #pragma unroll
        for (int it = 0; it < 2; ++it) {
            int idx = t + it * 128;
            int r = idx >> 2, c4 = idx & 3;
            {
                float4 v = *reinterpret_cast<const float4*>(
                    A + (size_t)(bm + r) * lda + k0 + c4 * 4);
                As[c4 * 4 + 0][r] = v.x * a_scale;
                As[c4 * 4 + 1][r] = v.y * a_scale;
                As[c4 * 4 + 2][r] = v.z * a_scale;
                As[c4 * 4 + 3][r] = v.w * a_scale;
            }
            {
                int gn = bn + r;
                float4 v = make_float4(0.f, 0.f, 0.f, 0.f);
                if (gn < N)
                    v = *reinterpret_cast<const float4*>(
                        W + (size_t)gn * K + k0 + c4 * 4);
                Ws[c4 * 4 + 0][r] = v.x;
                Ws[c4 * 4 + 1][r] = v.y;
                Ws[c4 * 4 + 2][r] = v.z;
                Ws[c4 * 4 + 3][r] = v.w;
            }
        }
        __syncthreads();

        #pragma unroll
        for (int kk = 0; kk < 16; ++kk) {
            const ulonglong2* ap =
                reinterpret_cast<const ulonglong2*>(&As[kk][ty * 8]);
            ulonglong2 am01 = ap[0];
            ulonglong2 am23 = ap[1];
            float4 wv = *reinterpret_cast<const float4*>(&Ws[kk][tx * 4]);
            unsigned long long pw0 = dup2(wv.x);
            unsigned long long pw1 = dup2(wv.y);
            unsigned long long pw2 = dup2(wv.z);
            unsigned long long pw3 = dup2(wv.w);
            ffma2(acc[0][0], am01.x, pw0); ffma2(acc[0][1], am01.x, pw1);
            ffma2(acc[0][2], am01.x, pw2); ffma2(acc[0][3], am01.x, pw3);
            ffma2(acc[1][0], am01.y, pw0); ffma2(acc[1][1], am01.y, pw1);
            ffma2(acc[1][2], am01.y, pw2); ffma2(acc[1][3], am01.y, pw3);
            ffma2(acc[2][0], am23.x, pw0); ffma2(acc[2][1], am23.x, pw1);
            ffma2(acc[2][2], am23.x, pw2); ffma2(acc[2][3], am23.x, pw3);
            ffma2(acc[3][0], am23.y, pw0); ffma2(acc[3][1], am23.y, pw1);
            ffma2(acc[3][2], am23.y, pw2); ffma2(acc[3][3], am23.y, pw3);
        }
        __syncthreads();
    }

    const int nbase = bn + tx * 4;
    #pragma unroll
    for (int i = 0; i < 4; ++i) {
        int m0 = bm + ty * 8 + 2 * i;
        float2 c0 = unpack2(acc[i][0]);
        float2 c1 = unpack2(acc[i][1]);
        float2 c2 = unpack2(acc[i][2]);
        float2 c3 = unpack2(acc[i][3]);
        float lo[4] = {c0.x, c1.x, c2.x, c3.x};
        float hi[4] = {c0.y, c1.y, c2.y, c3.y};
        if (atomic) {
            #pragma unroll
            for (int j = 0; j < 4; ++j) {
                int n = nbase + j;
                if (n < N) {
                    atomicAdd(&C[(size_t)m0 * ldc + n], lo[j]);
                    atomicAdd(&C[(size_t)(m0 + 1) * ldc + n], hi[j]);
                }
            }
        } else {
            #pragma unroll
            for (int j = 0; j < 4; ++j) {
                int n = nbase + j;
                if (n >= N) continue;
                float bv = bias ? bias[n] : 0.f;
                float v0 = lo[j] + bv, v1 = hi[j] + bv;
                if (act == 1) { v0 = fmaxf(v0, 0.f); v1 = fmaxf(v1, 0.f); }
                else if (act == 2) {
                    v0 = (v0 > 20.f) ? v0 : log1pf(expf(v0));
                    v1 = (v1 > 20.f) ? v1 : log1pf(expf(v1));
                }
                C[(size_t)m0 * ldc + n] = v0;
                C[(size_t)(m0 + 1) * ldc + n] = v1;
            }
        }
    }
}

// ---------------- fc bias + relu + sequence build (reversal at l=0) ----------------
__global__ void build_u_kernel(const float* __restrict__ fcacc, const float* __restrict__ fcb,
                               float* __restrict__ u)
{
    int idx = blockIdx.x * blockDim.x + threadIdx.x;
    if (idx >= NB * DMODEL) return;
    int b = idx >> 11, d = idx & 2047;
    float v = fmaxf(fcacc[idx] + fcb[d], 0.f);
    u[(2 * b + 1) * DMODEL + d] = v;
    u[(2 * b) * DMODEL + (DMODEL - 1 - d)] = v;
}

// ---------------- depthwise conv1d (L=2, causal k=4) + silu ----------------
__global__ void conv1d_silu_kernel(const float* __restrict__ xz, const float* __restrict__ w,
                                   const float* __restrict__ bias, float* __restrict__ xs)
{
    int idx = blockIdx.x * blockDim.x + threadIdx.x;
    if (idx >= NB * DINNER) return;
    int b = idx >> 12, e = idx & 4095;
    float x0 = xz[(2 * b) * (2 * DINNER) + e];
    float x1 = xz[(2 * b + 1) * (2 * DINNER) + e];
    float w2 = w[e * 4 + 2], w3 = w[e * 4 + 3];
    float bv = bias[e];
    float v0 = x0 * w3 + bv;
    float v1 = x0 * w2 + x1 * w3 + bv;
    xs[(2 * b) * DINNER + e]     = v0 / (1.f + expf(-v0));
    xs[(2 * b + 1) * DINNER + e] = v1 / (1.f + expf(-v1));
}

// ---------------- selective scan (L=2, closed form) + D skip + silu(z) gating --------
__global__ void scan_kernel(const float* __restrict__ xz, const float* __restrict__ xs,
                            const float* __restrict__ xdbl, const float* __restrict__ dt,
                            const float* __restrict__ A_log, const float* __restrict__ Dv,
                            float* __restrict__ y)
{
    int idx = blockIdx.x * blockDim.x + threadIdx.x;
    if (idx >= NB * DINNER) return;
    int b = idx >> 12, e = idx & 4095;

    float dt0 = dt[(2 * b) * DINNER + e];
    float dt1 = dt[(2 * b + 1) * DINNER + e];
    float x0  = xs[(2 * b) * DINNER + e];
    float x1  = xs[(2 * b + 1) * DINNER + e];
    float z1  = xz[(2 * b + 1) * (2 * DINNER) + DINNER + e];

    const float* bc0 = xdbl + (2 * b) * 160;
    const float* bc1 = xdbl + (2 * b + 1) * 160;

    float acc = 0.f;
    #pragma unroll
    for (int n = 0; n < DSTATE; ++n) {
        float Ae = -expf(A_log[e * DSTATE + n]);
        float h = dt0 * bc0[DTRANK + n] * x0;
        h = h * expf(dt1 * Ae) + dt1 * bc1[DTRANK + n] * x1;
        acc += h * bc1[DTRANK + DSTATE + n];
    }
    float yv = acc + x1 * Dv[e];
    float sg = z1 / (1.f + expf(-z1));
    y[b * DINNER + e] = yv * sg;
}

// ---------------- output heads ----------------
__global__ void heads_kernel(const float* __restrict__ feat,
                             const float* __restrict__ wxyz, const float* __restrict__ bxyz,
                             const float* __restrict__ wpqr, const float* __restrict__ bpqr,
                             float* __restrict__ out)
{
    int b = blockIdx.x / 7, j = blockIdx.x % 7;
    const float* wrow = (j < 3) ? (wxyz + j * DMODEL) : (wpqr + (j - 3) * DMODEL);
    float bias = (j < 3) ? bxyz[j] : bpqr[j - 3];

    float s = 0.f;
    for (int i = threadIdx.x; i < DMODEL; i += 128)
        s += feat[b * DMODEL + i] * wrow[i];

    __shared__ float red[4];
    #pragma unroll
    for (int off = 16; off; off >>= 1) s += __shfl_down_sync(0xffffffffu, s, off);
    if ((threadIdx.x & 31) == 0) red[threadIdx.x >> 5] = s;
    __syncthreads();
    if (threadIdx.x == 0)
        out[b * 7 + j] = red[0] + red[1] + red[2] + red[3] + bias;
}

// ---------------- launcher ----------------
extern "C" void kernel_launch(void* const* d_in, const int* in_sizes, int n_in,
                              void* d_out, int out_size)
{
    const float* x       = (const float*)d_in[0];
    const float* conv_w  = (const float*)d_in[1];
    const float* conv_b  = (const float*)d_in[2];
    const float* fc_w    = (const float*)d_in[3];
    const float* fc_b    = (const float*)d_in[4];
    const float* W_in    = (const float*)d_in[5];
    const float* c1w     = (const float*)d_in[6];
    const float* c1b     = (const float*)d_in[7];
    const float* W_xproj = (const float*)d_in[8];
    const float* W_dt    = (const float*)d_in[9];
    const float* b_dt    = (const float*)d_in[10];
    const float* A_log   = (const float*)d_in[11];
    const float* Dv      = (const float*)d_in[12];
    const float* W_out   = (const float*)d_in[13];
    const float* wxyz    = (const float*)d_in[14];
    const float* bxyz    = (const float*)d_in[15];
    const float* wpqr    = (const float*)d_in[16];
    const float* bpqr    = (const float*)d_in[17];
    float* out = (float*)d_out;

    void* sp = nullptr;
    cudaGetSymbolAddress(&sp, g_scratch);
    float* S = (float*)sp;

    float* f     = S + OFF_F;
    float* fcacc = S + OFF_FC;
    float* u     = S + OFF_U;
    float* xz    = S + OFF_XZ;
    float* xs    = S + OFF_XS;
    float* xdbl  = S + OFF_XDBL;
    float* dtb   = S + OFF_DT;
    float* y     = S + OFF_Y;
    float* feat  = S + OFF_FEAT;
    uint2* wTp   = (uint2*)(S + OFF_WT);

    cudaFuncSetAttribute(conv_tc_kernel,
                         cudaFuncAttributeMaxDynamicSharedMemorySize,
                         CONV_SMEM_TOTAL);

    // launch order arranged so launch #4 == conv_tc_kernel (ncu profiles #4)
    // (1) zero f+fcacc
    zero_kernel<<<(163840 + 255) / 256, 256>>>(f, 163840);
    // (2) zero xdbl
    zero_kernel<<<(20480 + 255) / 256, 256>>>(xdbl, 20480);
    // (3) conv weight transpose + tf32 pack
    prep_wt_kernel<<<(76 * 512 + 255) / 256, 256>>>(conv_w, wTp);
    // (4) conv + relu + spatial sum (tensor cores)
    conv_tc_kernel<<<dim3(49, 32), 128, CONV_SMEM_TOTAL>>>(x, wTp, conv_b, f);
    // (5) fc (mean scale folded in), split-K atomic
    gemm_kernel<<<dim3(32, 1, 4), 128>>>(f, 512, fc_w, nullptr, fcacc, 2048,
                                         64, 2048, 512, 1.f / 3136.f, 0, 1);
    // (6) bias+relu + sequence build
    build_u_kernel<<<512, 256>>>(fcacc, fc_b, u);
    // (7) xz = u @ W_in^T  (128 x 8192 x 2048) — tensor 3xTF32, pipelined
    gemm_tc_kernel<<<dim3(128, 1, 1), 256>>>(u, 2048, W_in, xz, 8192,
                                             128, 8192, 2048, 0);
    // (8) depthwise conv1d + silu
    conv1d_silu_kernel<<<1024, 256>>>(xz, c1w, c1b, xs);
    // (9) x_dbl = xs @ W_xproj^T  (128 x 160 x 4096), split-K atomic
    gemm_kernel<<<dim3(3, 2, 16), 128>>>(xs, 4096, W_xproj, nullptr, xdbl, 160,
                                         128, 160, 4096, 1.f, 0, 1);
    // (10) dt = softplus(dt_low @ W_dt^T + b_dt)
    gemm_kernel<<<dim3(64, 2, 1), 128>>>(xdbl, 160, W_dt, b_dt, dtb, 4096,
                                         128, 4096, 128, 1.f, 2, 0);
    // (11) scan + gating -> y
    scan_kernel<<<1024, 256>>>(xz, xs, xdbl, dtb, A_log, Dv, y);
    // (12) zero feat
    zero_kernel<<<(131072 + 255) / 256, 256>>>(feat, 131072);
    // (13) feat = y @ W_out^T  (64 x 2048 x 4096) — tensor 3xTF32, split-K=4
    gemm_tc_kernel<<<dim3(32, 1, 4), 256>>>(y, 4096, W_out, feat, 2048,
                                            64, 2048, 4096, 1);
    // (14) heads
    heads_kernel<<<448, 128>>>(feat, wxyz, bxyz, wpqr, bpqr, out);
}

// round 12
// speedup vs baseline: 3.2445x; 1.0291x over previous
#include <cuda_runtime.h>
#include <math.h>

// ---------------- problem constants ----------------
#define NB      64
#define DMODEL  2048
#define DINNER  4096
#define DSTATE  16
#define DTRANK  128
#define FE      512

// ---------------- scratch layout (floats) ----------------
#define OFF_F     0          // 64*512      conv relu-sum accumulator
#define OFF_FC    32768      // 64*2048     fc split-K accumulator
#define OFF_U     163840     // 128*2048    mamba input u (rows = b*2+l)
#define OFF_XZ    425984     // 128*8192    xz = u @ W_in^T
#define OFF_XS    1474560    // 128*4096    silu(conv1d(x))
#define OFF_XDBL  1998848    // 128*160     x_dbl
#define OFF_DT    2019328    // 128*4096    dt (softplus)
#define OFF_Y     2543616    // 64*4096     gated scan output at l=1
#define OFF_FEAT  2805760    // 64*2048     y @ W_out^T
#define OFF_WT    2936832    // 76*512 uint2: packed tf32 conv weights (k,k+4 pairs)
#define SCRATCH_TOTAL 3014656

__device__ float g_scratch[SCRATCH_TOTAL];

// conv_tc dynamic smem layout (bytes) — 64-channel weight chunks (R8 proven config)
#define CONV_SMEM_W     0                    // 76*68 uint2 = 41344
#define CONV_SMEM_ACC   41344                // 2*512 float = 4096
#define CONV_SMEM_IN    45440                // 2*3*35*35 tf32 = 29400
#define CONV_SMEM_TOTAL 74840

// ---------------- tf32 mma helpers ----------------
__device__ __forceinline__ unsigned f2tf32(float v) {
    unsigned r;
    asm("cvt.rna.tf32.f32 %0, %1;" : "=r"(r) : "f"(v));
    return r;
}
__device__ __forceinline__ void mma_tf32(float c[4],
                                         unsigned a0, unsigned a1, unsigned a2, unsigned a3,
                                         unsigned b0, unsigned b1) {
    asm volatile(
        "mma.sync.aligned.m16n8k8.row.col.f32.tf32.tf32.f32 "
        "{%0,%1,%2,%3}, {%4,%5,%6,%7}, {%8,%9}, {%0,%1,%2,%3};"
        : "+f"(c[0]), "+f"(c[1]), "+f"(c[2]), "+f"(c[3])
        : "r"(a0), "r"(a1), "r"(a2), "r"(a3), "r"(b0), "r"(b1));
}

// ---------------- utility kernels ----------------
// zero the three atomic-accumulator regions in one launch
#define Z_N1 184320              // f+fcacc (163840) + xdbl (20480)
#define Z_TOTAL 315392           // + feat (131072)
__global__ void zero3_kernel(float* S) {
    int i = blockIdx.x * blockDim.x + threadIdx.x;
    if (i >= Z_TOTAL) return;
    if (i < 163840)      S[OFF_F + i] = 0.f;
    else if (i < Z_N1)   S[OFF_XDBL + (i - 163840)] = 0.f;
    else                 S[OFF_FEAT + (i - Z_N1)] = 0.f;
}

// conv_w (512,3,7,7) -> packed tf32 pairs wTp[kp][co] = (w[k0], w[k0+4]),
// kp = ks*4 + j encodes k0 = ks*8 + j; zero-padded beyond k=146.
__global__ void prep_wt_kernel(const float* __restrict__ w, uint2* __restrict__ wTp) {
    int i = blockIdx.x * blockDim.x + threadIdx.x;
    if (i < 76 * 512) {
        int kp = i >> 9, co = i & 511;
        int k0 = (kp >> 2) * 8 + (kp & 3);
        int k1 = k0 + 4;
        float v0 = (k0 < 147) ? w[co * 147 + k0] : 0.f;
        float v1 = (k1 < 147) ? w[co * 147 + k1] : 0.f;
        wTp[kp * 512 + co] = make_uint2(f2tf32(v0), f2tf32(v1));
    }
}

// ---------------- conv 7x7 s4 p3 + bias + relu + spatial-sum (tensor cores) ----------
// grid (49, 32), block 128 (4 warps). Each block: 8x8 output tile of TWO images.
// Each warp: m32 (4 tile rows of one image) = two m16 fragments sharing B.
// 64-channel weight chunks (8 chunks), 74.8 KB smem, 3 blocks/SM. (R8 config)
__global__ void __launch_bounds__(128)
conv_tc_kernel(const float* __restrict__ x, const uint2* __restrict__ wTp,
               const float* __restrict__ bias, float* __restrict__ f_accum)
{
    extern __shared__ __align__(16) char smem[];
    uint2*    s_w  = reinterpret_cast<uint2*>(smem + CONV_SMEM_W);       // [76][68]
    float*    s_acc = reinterpret_cast<float*>(smem + CONV_SMEM_ACC);    // [2][512]
    unsigned* s_in  = reinterpret_cast<unsigned*>(smem + CONV_SMEM_IN);  // [2][3][35][35] tf32

    const int t    = threadIdx.x;
    const int tile = blockIdx.x;
    const int bp   = blockIdx.y;            // image pair
    const int oh_base = (tile / 7) * 8;
    const int ow_base = (tile % 7) * 8;
    const int ih0 = oh_base * 4 - 3;
    const int iw0 = ow_base * 4 - 3;

    for (int i = t; i < 1024; i += 128) s_acc[i] = 0.f;

    // input tiles for both images, converted to tf32 bits once
    for (int i = t; i < 2 * 3 * 1225; i += 128) {
        int img = i / 3675;
        int rem = i - img * 3675;
        int ci  = rem / 1225; rem -= ci * 1225;
        int r = rem / 35, c = rem - (rem / 35) * 35;
        int ih = ih0 + r, iw = iw0 + c;
        float v = 0.f;
        int b = bp * 2 + img;
        if ((unsigned)ih < 224u && (unsigned)iw < 224u)
            v = x[((b * 3 + ci) * 224 + ih) * 224 + iw];
        s_in[(img * 3 + ci) * 1225 + r * 35 + c] = f2tf32(v);
    }

    const int lane = t & 31;
    const int w    = t >> 5;                // warp 0..3
    const int img  = w >> 1;                // image (2 warps per image)
    const int half = w & 1;                 // which 4 tile-rows
    const int q    = lane >> 2;             // column group 0..7
    const int j    = lane & 3;              // k-in-group
    const int ya = half * 16;               // first image row of warp's region
    const int xb = q * 4;
    const unsigned* my_in = s_in + img * 3675 + ya * 35 + xb;

    // per-thread k-step offset tables (register arrays; loop fully unrolled)
    int o0[19], o1[19];
    #pragma unroll
    for (int ks = 0; ks < 19; ++ks) {
        int k0 = ks * 8 + j, k1 = k0 + 4;
        int kk0 = min(k0, 146), kk1 = min(k1, 146);
        int ci0 = kk0 / 49, r0 = kk0 - ci0 * 49;
        int kh0 = r0 / 7,  kw0 = r0 - kh0 * 7;
        int ci1 = kk1 / 49, r1 = kk1 - ci1 * 49;
        int kh1 = r1 / 7,  kw1 = r1 - kh1 * 7;
        o0[ks] = ci0 * 1225 + kh0 * 35 + kw0;
        o1[ks] = ci1 * 1225 + kh1 * 35 + kw1;
    }

    for (int n0 = 0; n0 < 512; n0 += 64) {
        __syncthreads();
        // stage packed weight chunk: 76 rows x 64 channels = 32 uint4/row
        {
            const uint4* src = reinterpret_cast<const uint4*>(wTp);
            uint4* dst = reinterpret_cast<uint4*>(s_w);
            for (int i = t; i < 76 * 32; i += 128) {
                int row = i >> 5, c = i & 31;
                dst[row * 34 + c] = src[row * 256 + (n0 >> 1) + c];
            }
        }
        __syncthreads();

        float c[2][8][4];
        #pragma unroll
        for (int f2 = 0; f2 < 2; ++f2)
            #pragma unroll
            for (int nf = 0; nf < 8; ++nf)
                #pragma unroll
                for (int u2 = 0; u2 < 4; ++u2) c[f2][nf][u2] = 0.f;

        #pragma unroll
        for (int ks = 0; ks < 19; ++ks) {
            int p0 = o0[ks], p1 = o1[ks];
            unsigned aA0 = my_in[p0];
            unsigned aA1 = my_in[p0 + 140];
            unsigned aA2 = my_in[p1];
            unsigned aA3 = my_in[p1 + 140];
            unsigned aB0 = my_in[p0 + 280];
            unsigned aB1 = my_in[p0 + 420];
            unsigned aB2 = my_in[p1 + 280];
            unsigned aB3 = my_in[p1 + 420];
            const uint2* wr = s_w + (ks * 4 + j) * 68 + q;
            #pragma unroll
            for (int nf = 0; nf < 8; ++nf) {
                uint2 b2 = wr[nf * 8];
                mma_tf32(c[0][nf], aA0, aA1, aA2, aA3, b2.x, b2.y);
                mma_tf32(c[1][nf], aB0, aB1, aB2, aB3, b2.x, b2.y);
            }
        }

        // epilogue: bias + relu per position, reduce over positions
        #pragma unroll
        for (int nf = 0; nf < 8; ++nf) {
            int ca = n0 + nf * 8 + 2 * j;
            float bva = bias[ca], bvb = bias[ca + 1];
            float va = fmaxf(c[0][nf][0] + bva, 0.f) + fmaxf(c[0][nf][2] + bva, 0.f)
                     + fmaxf(c[1][nf][0] + bva, 0.f) + fmaxf(c[1][nf][2] + bva, 0.f);
            float vb = fmaxf(c[0][nf][1] + bvb, 0.f) + fmaxf(c[0][nf][3] + bvb, 0.f)
                     + fmaxf(c[1][nf][1] + bvb, 0.f) + fmaxf(c[1][nf][3] + bvb, 0.f);
            #pragma unroll
            for (int off = 16; off >= 4; off >>= 1) {
                va += __shfl_down_sync(0xffffffffu, va, off);
                vb += __shfl_down_sync(0xffffffffu, vb, off);
            }
            if (lane < 4) {
                atomicAdd(&s_acc[img * 512 + ca], va);
                atomicAdd(&s_acc[img * 512 + ca + 1], vb);
            }
        }
    }

    __syncthreads();
    for (int i = t; i < 1024; i += 128) {
        int im = i >> 9, ch = i & 511;
        atomicAdd(&f_accum[(bp * 2 + im) * 512 + ch], s_acc[im * 512 + ch]);
    }
}

// ---------------- tensor-core 3xTF32 GEMM (pipelined, fused epilogue) ----------
// C[M,N] (+)= A[M,K] @ W[N,K]^T  [+ bias, act]  (act: 0=none, 2=softplus)
// BM=128, BN=64, BK=16, 256 threads. Register prefetch overlaps LDG with MMA.
// Requirements: K % (16*gridDim.z) == 0, lda % 4 == 0. A rows clamped past M.
#define GT_SA 136
#define GT_SW 72
__global__ void __launch_bounds__(256)
gemm_tc_kernel(const float* __restrict__ A, int lda,
               const float* __restrict__ W,
               const float* __restrict__ bias, int act,
               float* __restrict__ C, int ldc,
               int M, int N, int K, int atomic)
{
    __shared__ unsigned sAh[16 * GT_SA], sAl[16 * GT_SA];
    __shared__ unsigned sWh[16 * GT_SW], sWl[16 * GT_SW];

    const int bm = blockIdx.y * 128;
    const int bn = blockIdx.x * 64;
    const int t = threadIdx.x, lane = t & 31, w = t >> 5;
    const int kPer = K / gridDim.z;
    const int kBeg = blockIdx.z * kPer;
    const int kEnd = kBeg + kPer;

    // fixed load coordinates for this thread
    const int rA0 = t >> 2,   cA = t & 3;          // A row pair 0 (rows 0..63)
    const int rA1 = rA0 + 64;                       // A row pair 1
    const int gA0 = min(bm + rA0, M - 1);
    const int gA1 = min(bm + rA1, M - 1);
    const int gW  = bn + rA0;                       // W row (rA0 in 0..63)
    const bool wOk = (gW < N);

    float acc[8][4];
    #pragma unroll
    for (int nf = 0; nf < 8; ++nf)
        #pragma unroll
        for (int u2 = 0; u2 < 4; ++u2) acc[nf][u2] = 0.f;

    // prefetch first k-tile
    float4 rAv0 = *reinterpret_cast<const float4*>(A + (size_t)gA0 * lda + kBeg + cA * 4);
    float4 rAv1 = *reinterpret_cast<const float4*>(A + (size_t)gA1 * lda + kBeg + cA * 4);
    float4 rWv  = wOk ? *reinterpret_cast<const float4*>(W + (size_t)gW * K + kBeg + cA * 4)
                      : make_float4(0.f, 0.f, 0.f, 0.f);

    for (int k0 = kBeg; k0 < kEnd; k0 += 16) {
        // store current tile to smem (hi/lo split)
        {
            float vv0[4] = {rAv0.x, rAv0.y, rAv0.z, rAv0.w};
            float vv1[4] = {rAv1.x, rAv1.y, rAv1.z, rAv1.w};
            float vvW[4] = {rWv.x, rWv.y, rWv.z, rWv.w};
            #pragma unroll
            for (int e = 0; e < 4; ++e) {
                unsigned h0 = f2tf32(vv0[e]);
                sAh[(cA * 4 + e) * GT_SA + rA0] = h0;
                sAl[(cA * 4 + e) * GT_SA + rA0] = f2tf32(vv0[e] - __uint_as_float(h0));
                unsigned h1 = f2tf32(vv1[e]);
                sAh[(cA * 4 + e) * GT_SA + rA1] = h1;
                sAl[(cA * 4 + e) * GT_SA + rA1] = f2tf32(vv1[e] - __uint_as_float(h1));
                unsigned hw = f2tf32(vvW[e]);
                sWh[(cA * 4 + e) * GT_SW + rA0] = hw;
                sWl[(cA * 4 + e) * GT_SW + rA0] = f2tf32(vvW[e] - __uint_as_float(hw));
            }
        }
        __syncthreads();

        // issue next tile's loads (latency overlapped with MMAs below)
        int kn = k0 + 16;
        if (kn < kEnd) {
            rAv0 = *reinterpret_cast<const float4*>(A + (size_t)gA0 * lda + kn + cA * 4);
            rAv1 = *reinterpret_cast<const float4*>(A + (size_t)gA1 * lda + kn + cA * 4);
            if (wOk)
                rWv = *reinterpret_cast<const float4*>(W + (size_t)gW * K + kn + cA * 4);
        }

        #pragma unroll
        for (int ks = 0; ks < 2; ++ks) {
            int kb = ks * 8;
            int ar = w * 16 + (lane >> 2);
            int ac = kb + (lane & 3);
            unsigned ah0 = sAh[ac * GT_SA + ar];
            unsigned ah1 = sAh[ac * GT_SA + ar + 8];
            unsigned ah2 = sAh[(ac + 4) * GT_SA + ar];
            unsigned ah3 = sAh[(ac + 4) * GT_SA + ar + 8];
            unsigned al0 = sAl[ac * GT_SA + ar];
            unsigned al1 = sAl[ac * GT_SA + ar + 8];
            unsigned al2 = sAl[(ac + 4) * GT_SA + ar];
            unsigned al3 = sAl[(ac + 4) * GT_SA + ar + 8];

            #pragma unroll
            for (int nf = 0; nf < 8; ++nf) {
                int bc = nf * 8 + (lane >> 2);
                int br = kb + (lane & 3);
                unsigned bh0 = sWh[br * GT_SW + bc];
                unsigned bh1 = sWh[(br + 4) * GT_SW + bc];
                unsigned bl0 = sWl[br * GT_SW + bc];
                unsigned bl1 = sWl[(br + 4) * GT_SW + bc];
                mma_tf32(acc[nf], ah0, ah1, ah2, ah3, bh0, bh1);
                mma_tf32(acc[nf], ah0, ah1, ah2, ah3, bl0, bl1);
                mma_tf32(acc[nf], al0, al1, al2, al3, bh0, bh1);
            }
        }
        __syncthreads();
    }

    const int mr0 = bm + w * 16 + (lane >> 2);
    const int nc0 = bn + (lane & 3) * 2;
    #pragma unroll
    for (int nf = 0; nf < 8; ++nf) {
        int n = nc0 + nf * 8;
        if (n >= N) continue;
        if (atomic) {
            if (mr0 < M) {
                atomicAdd(&C[(size_t)mr0 * ldc + n],     acc[nf][0]);
                atomicAdd(&C[(size_t)mr0 * ldc + n + 1], acc[nf][1]);
            }
            if (mr0 + 8 < M) {
                atomicAdd(&C[(size_t)(mr0 + 8) * ldc + n],     acc[nf][2]);
                atomicAdd(&C[(size_t)(mr0 + 8) * ldc + n + 1], acc[nf][3]);
            }
        } else {
            float b0 = bias ? bias[n] : 0.f;
            float b1 = bias ? bias[n + 1] : 0.f;
            float v00 = acc[nf][0] + b0, v01 = acc[nf][1] + b1;
            float v10 = acc[nf][2] + b0, v11 = acc[nf][3] + b1;
            if (act == 2) {
                v00 = (v00 > 20.f) ? v00 : log1pf(expf(v00));
                v01 = (v01 > 20.f) ? v01 : log1pf(expf(v01));
                v10 = (v10 > 20.f) ? v10 : log1pf(expf(v10));
                v11 = (v11 > 20.f) ? v11 : log1pf(expf(v11));
            }
            if (mr0 < M) {
                C[(size_t)mr0 * ldc + n]     = v00;
                C[(size_t)mr0 * ldc + n + 1] = v01;
            }
            if (mr0 + 8 < M) {
                C[(size_t)(mr0 + 8) * ldc + n]     = v10;
                C[(size_t)(mr0 + 8) * ldc + n + 1] = v11;
            }
        }
    }
}

// ---------------- fc mean-scale + bias + relu + sequence build (reversal at l=0) -----
__global__ void build_u_kernel(const float* __restrict__ fcacc, const float* __restrict__ fcb,
                               float* __restrict__ u)
{
    int idx = blockIdx.x * blockDim.x + threadIdx.x;
    if (idx >= NB * DMODEL) return;
    int b = idx >> 11, d = idx & 2047;
    float v = fmaxf(fcacc[idx] * (1.f / 3136.f) + fcb[d], 0.f);
    u[(2 * b + 1) * DMODEL + d] = v;
    u[(2 * b) * DMODEL + (DMODEL - 1 - d)] = v;
}

// ---------------- depthwise conv1d (L=2, causal k=4) + silu ----------------
__global__ void conv1d_silu_kernel(const float* __restrict__ xz, const float* __restrict__ w,
                                   const float* __restrict__ bias, float* __restrict__ xs)
{
    int idx = blockIdx.x * blockDim.x + threadIdx.x;
    if (idx >= NB * DINNER) return;
    int b = idx >> 12, e = idx & 4095;
    float x0 = xz[(2 * b) * (2 * DINNER) + e];
    float x1 = xz[(2 * b + 1) * (2 * DINNER) + e];
    float w2 = w[e * 4 + 2], w3 = w[e * 4 + 3];
    float bv = bias[e];
    float v0 = x0 * w3 + bv;
    float v1 = x0 * w2 + x1 * w3 + bv;
    xs[(2 * b) * DINNER + e]     = v0 / (1.f + expf(-v0));
    xs[(2 * b + 1) * DINNER + e] = v1 / (1.f + expf(-v1));
}

// ---------------- selective scan (L=2, closed form) + D skip + silu(z) gating --------
__global__ void scan_kernel(const float* __restrict__ xz, const float* __restrict__ xs,
                            const float* __restrict__ xdbl, const float* __restrict__ dt,
                            const float* __restrict__ A_log, const float* __restrict__ Dv,
                            float* __restrict__ y)
{
    int idx = blockIdx.x * blockDim.x + threadIdx.x;
    if (idx >= NB * DINNER) return;
    int b = idx >> 12, e = idx & 4095;

    float dt0 = dt[(2 * b) * DINNER + e];
    float dt1 = dt[(2 * b + 1) * DINNER + e];
    float x0  = xs[(2 * b) * DINNER + e];
    float x1  = xs[(2 * b + 1) * DINNER + e];
    float z1  = xz[(2 * b + 1) * (2 * DINNER) + DINNER + e];

    const float* bc0 = xdbl + (2 * b) * 160;
    const float* bc1 = xdbl + (2 * b + 1) * 160;

    float acc = 0.f;
    #pragma unroll
    for (int n = 0; n < DSTATE; ++n) {
        float Ae = -expf(A_log[e * DSTATE + n]);
        float h = dt0 * bc0[DTRANK + n] * x0;
        h = h * expf(dt1 * Ae) + dt1 * bc1[DTRANK + n] * x1;
        acc += h * bc1[DTRANK + DSTATE + n];
    }
    float yv = acc + x1 * Dv[e];
    float sg = z1 / (1.f + expf(-z1));
    y[b * DINNER + e] = yv * sg;
}

// ---------------- output heads ----------------
__global__ void heads_kernel(const float* __restrict__ feat,
                             const float* __restrict__ wxyz, const float* __restrict__ bxyz,
                             const float* __restrict__ wpqr, const float* __restrict__ bpqr,
                             float* __restrict__ out)
{
    int b = blockIdx.x / 7, j = blockIdx.x % 7;
    const float* wrow = (j < 3) ? (wxyz + j * DMODEL) : (wpqr + (j - 3) * DMODEL);
    float bias = (j < 3) ? bxyz[j] : bpqr[j - 3];

    float s = 0.f;
    for (int i = threadIdx.x; i < DMODEL; i += 128)
        s += feat[b * DMODEL + i] * wrow[i];

    __shared__ float red[4];
    #pragma unroll
    for (int off = 16; off; off >>= 1) s += __shfl_down_sync(0xffffffffu, s, off);
    if ((threadIdx.x & 31) == 0) red[threadIdx.x >> 5] = s;
    __syncthreads();
    if (threadIdx.x == 0)
        out[b * 7 + j] = red[0] + red[1] + red[2] + red[3] + bias;
}

// ---------------- launcher ----------------
extern "C" void kernel_launch(void* const* d_in, const int* in_sizes, int n_in,
                              void* d_out, int out_size)
{
    const float* x       = (const float*)d_in[0];
    const float* conv_w  = (const float*)d_in[1];
    const float* conv_b  = (const float*)d_in[2];
    const float* fc_w    = (const float*)d_in[3];
    const float* fc_b    = (const float*)d_in[4];
    const float* W_in    = (const float*)d_in[5];
    const float* c1w     = (const float*)d_in[6];
    const float* c1b     = (const float*)d_in[7];
    const float* W_xproj = (const float*)d_in[8];
    const float* W_dt    = (const float*)d_in[9];
    const float* b_dt    = (const float*)d_in[10];
    const float* A_log   = (const float*)d_in[11];
    const float* Dv      = (const float*)d_in[12];
    const float* W_out   = (const float*)d_in[13];
    const float* wxyz    = (const float*)d_in[14];
    const float* bxyz    = (const float*)d_in[15];
    const float* wpqr    = (const float*)d_in[16];
    const float* bpqr    = (const float*)d_in[17];
    float* out = (float*)d_out;

    void* sp = nullptr;
    cudaGetSymbolAddress(&sp, g_scratch);
    float* S = (float*)sp;

    float* f     = S + OFF_F;
    float* fcacc = S + OFF_FC;
    float* u     = S + OFF_U;
    float* xz    = S + OFF_XZ;
    float* xs    = S + OFF_XS;
    float* xdbl  = S + OFF_XDBL;
    float* dtb   = S + OFF_DT;
    float* y     = S + OFF_Y;
    float* feat  = S + OFF_FEAT;
    uint2* wTp   = (uint2*)(S + OFF_WT);

    cudaFuncSetAttribute(conv_tc_kernel,
                         cudaFuncAttributeMaxDynamicSharedMemorySize,
                         CONV_SMEM_TOTAL);

    // (1) zero all atomic accumulators in one launch
    zero3_kernel<<<(Z_TOTAL + 255) / 256, 256>>>(S);
    // (2) conv weight transpose + tf32 pack
    prep_wt_kernel<<<(76 * 512 + 255) / 256, 256>>>(conv_w, wTp);
    // (3) conv + relu + spatial sum (tensor cores)
    conv_tc_kernel<<<dim3(49, 32), 128, CONV_SMEM_TOTAL>>>(x, wTp, conv_b, f);
    // (4) fc = f @ fc_w^T  (64 x 2048 x 512) — TC, split-K=4 atomic (profiled slot)
    gemm_tc_kernel<<<dim3(32, 1, 4), 256>>>(f, 512, fc_w, nullptr, 0,
                                            fcacc, 2048, 64, 2048, 512, 1);
    // (5) mean-scale + bias + relu + sequence build
    build_u_kernel<<<512, 256>>>(fcacc, fc_b, u);
    // (6) xz = u @ W_in^T  (128 x 8192 x 2048) — TC, pipelined
    gemm_tc_kernel<<<dim3(128, 1, 1), 256>>>(u, 2048, W_in, nullptr, 0,
                                             xz, 8192, 128, 8192, 2048, 0);
    // (7) depthwise conv1d + silu
    conv1d_silu_kernel<<<1024, 256>>>(xz, c1w, c1b, xs);
    // (8) x_dbl = xs @ W_xproj^T  (128 x 160 x 4096) — TC, split-K=16 atomic
    gemm_tc_kernel<<<dim3(3, 1, 16), 256>>>(xs, 4096, W_xproj, nullptr, 0,
                                            xdbl, 160, 128, 160, 4096, 1);
    // (9) dt = softplus(x_dbl[:, :128] @ W_dt^T + b_dt)  (128 x 4096 x 128) — TC
    gemm_tc_kernel<<<dim3(64, 1, 1), 256>>>(xdbl, 160, W_dt, b_dt, 2,
                                            dtb, 4096, 128, 4096, 128, 0);
    // (10) scan + gating -> y
    scan_kernel<<<1024, 256>>>(xz, xs, xdbl, dtb, A_log, Dv, y);
    // (11) feat = y @ W_out^T  (64 x 2048 x 4096) — TC, split-K=4 atomic
    gemm_tc_kernel<<<dim3(32, 1, 4), 256>>>(y, 4096, W_out, nullptr, 0,
                                            feat, 2048, 64, 2048, 4096, 1);
    // (12) heads
    heads_kernel<<<448, 128>>>(feat, wxyz, bxyz, wpqr, bpqr, out);
}

// round 13
// speedup vs baseline: 3.2798x; 1.0109x over previous
#include <cuda_runtime.h>
#include <math.h>

// ---------------- problem constants ----------------
#define NB      64
#define DMODEL  2048
#define DINNER  4096
#define DSTATE  16
#define DTRANK  128
#define FE      512

// ---------------- scratch layout (floats) ----------------
#define OFF_F     0          // 64*512      conv relu-sum accumulator
#define OFF_U     163840     // 128*2048    mamba input u (rows = b*2+l)
#define OFF_XZ    425984     // 128*8192    xz = u @ W_in^T
#define OFF_XS    1474560    // 128*4096    silu(conv1d(x))
#define OFF_XDBL  1998848    // 128*160     x_dbl
#define OFF_DT    2019328    // 128*4096    dt (softplus)
#define OFF_Y     2543616    // 64*4096     gated scan output at l=1
#define OFF_FEAT  2805760    // 64*2048     y @ W_out^T
#define OFF_WT    2936832    // 76*512 uint2: packed tf32 conv weights (k,k+4 pairs)
#define SCRATCH_TOTAL 3014656

__device__ float g_scratch[SCRATCH_TOTAL];

// conv_tc dynamic smem layout (bytes) — 64-channel weight chunks (R8 proven config)
#define CONV_SMEM_W     0                    // 76*68 uint2 = 41344
#define CONV_SMEM_ACC   41344                // 2*512 float = 4096
#define CONV_SMEM_IN    45440                // 2*3*35*35 tf32 = 29400
#define CONV_SMEM_TOTAL 74840

// ---------------- tf32 mma helpers ----------------
__device__ __forceinline__ unsigned f2tf32(float v) {
    unsigned r;
    asm("cvt.rna.tf32.f32 %0, %1;" : "=r"(r) : "f"(v));
    return r;
}
__device__ __forceinline__ void mma_tf32(float c[4],
                                         unsigned a0, unsigned a1, unsigned a2, unsigned a3,
                                         unsigned b0, unsigned b1) {
    asm volatile(
        "mma.sync.aligned.m16n8k8.row.col.f32.tf32.tf32.f32 "
        "{%0,%1,%2,%3}, {%4,%5,%6,%7}, {%8,%9}, {%0,%1,%2,%3};"
        : "+f"(c[0]), "+f"(c[1]), "+f"(c[2]), "+f"(c[3])
        : "r"(a0), "r"(a1), "r"(a2), "r"(a3), "r"(b0), "r"(b1));
}

// ---------------- fused prep: conv weight pack + zero accumulators ----------------
// i < 38912: pack wTp[kp][co] = (tf32(w[k0]), tf32(w[k0+4])), k0 = (kp>>2)*8 + (kp&3)
// then zero xdbl (20480) and feat (131072).
#define PZ_WT   38912
#define PZ_XD   59392     // + 20480
#define PZ_TOT  190464    // + 131072
__global__ void prep_zero_kernel(const float* __restrict__ w, float* S) {
    int i = blockIdx.x * blockDim.x + threadIdx.x;
    if (i >= PZ_TOT) return;
    if (i < PZ_WT) {
        int kp = i >> 9, co = i & 511;
        int k0 = (kp >> 2) * 8 + (kp & 3);
        int k1 = k0 + 4;
        float v0 = (k0 < 147) ? w[co * 147 + k0] : 0.f;
        float v1 = (k1 < 147) ? w[co * 147 + k1] : 0.f;
        ((uint2*)(S + OFF_WT))[kp * 512 + co] = make_uint2(f2tf32(v0), f2tf32(v1));
    } else if (i < PZ_XD) {
        S[OFF_XDBL + (i - PZ_WT)] = 0.f;
    } else {
        S[OFF_FEAT + (i - PZ_XD)] = 0.f;
    }
}

// ---------------- conv 7x7 s4 p3 + bias + relu + spatial-sum (tensor cores) ----------
// grid (49, 32), block 128 (4 warps). Each block: 8x8 output tile of TWO images.
// 64-channel weight chunks (8 chunks), 74.8 KB smem, 3 blocks/SM. (R8 proven config)
__global__ void __launch_bounds__(128)
conv_tc_kernel(const float* __restrict__ x, const uint2* __restrict__ wTp,
               const float* __restrict__ bias, float* __restrict__ f_accum)
{
    extern __shared__ __align__(16) char smem[];
    uint2*    s_w  = reinterpret_cast<uint2*>(smem + CONV_SMEM_W);       // [76][68]
    float*    s_acc = reinterpret_cast<float*>(smem + CONV_SMEM_ACC);    // [2][512]
    unsigned* s_in  = reinterpret_cast<unsigned*>(smem + CONV_SMEM_IN);  // [2][3][35][35] tf32

    const int t    = threadIdx.x;
    const int tile = blockIdx.x;
    const int bp   = blockIdx.y;            // image pair
    const int oh_base = (tile / 7) * 8;
    const int ow_base = (tile % 7) * 8;
    const int ih0 = oh_base * 4 - 3;
    const int iw0 = ow_base * 4 - 3;

    for (int i = t; i < 1024; i += 128) s_acc[i] = 0.f;

    for (int i = t; i < 2 * 3 * 1225; i += 128) {
        int img = i / 3675;
        int rem = i - img * 3675;
        int ci  = rem / 1225; rem -= ci * 1225;
        int r = rem / 35, c = rem - (rem / 35) * 35;
        int ih = ih0 + r, iw = iw0 + c;
        float v = 0.f;
        int b = bp * 2 + img;
        if ((unsigned)ih < 224u && (unsigned)iw < 224u)
            v = x[((b * 3 + ci) * 224 + ih) * 224 + iw];
        s_in[(img * 3 + ci) * 1225 + r * 35 + c] = f2tf32(v);
    }

    const int lane = t & 31;
    const int w    = t >> 5;
    const int img  = w >> 1;
    const int half = w & 1;
    const int q    = lane >> 2;
    const int j    = lane & 3;
    const int ya = half * 16;
    const int xb = q * 4;
    const unsigned* my_in = s_in + img * 3675 + ya * 35 + xb;

    int o0[19], o1[19];
    #pragma unroll
    for (int ks = 0; ks < 19; ++ks) {
        int k0 = ks * 8 + j, k1 = k0 + 4;
        int kk0 = min(k0, 146), kk1 = min(k1, 146);
        int ci0 = kk0 / 49, r0 = kk0 - ci0 * 49;
        int kh0 = r0 / 7,  kw0 = r0 - kh0 * 7;
        int ci1 = kk1 / 49, r1 = kk1 - ci1 * 49;
        int kh1 = r1 / 7,  kw1 = r1 - kh1 * 7;
        o0[ks] = ci0 * 1225 + kh0 * 35 + kw0;
        o1[ks] = ci1 * 1225 + kh1 * 35 + kw1;
    }

    for (int n0 = 0; n0 < 512; n0 += 64) {
        __syncthreads();
        {
            const uint4* src = reinterpret_cast<const uint4*>(wTp);
            uint4* dst = reinterpret_cast<uint4*>(s_w);
            for (int i = t; i < 76 * 32; i += 128) {
                int row = i >> 5, c = i & 31;
                dst[row * 34 + c] = src[row * 256 + (n0 >> 1) + c];
            }
        }
        __syncthreads();

        float c[2][8][4];
        #pragma unroll
        for (int f2 = 0; f2 < 2; ++f2)
            #pragma unroll
            for (int nf = 0; nf < 8; ++nf)
                #pragma unroll
                for (int u2 = 0; u2 < 4; ++u2) c[f2][nf][u2] = 0.f;

        #pragma unroll
        for (int ks = 0; ks < 19; ++ks) {
            int p0 = o0[ks], p1 = o1[ks];
            unsigned aA0 = my_in[p0];
            unsigned aA1 = my_in[p0 + 140];
            unsigned aA2 = my_in[p1];
            unsigned aA3 = my_in[p1 + 140];
            unsigned aB0 = my_in[p0 + 280];
            unsigned aB1 = my_in[p0 + 420];
            unsigned aB2 = my_in[p1 + 280];
            unsigned aB3 = my_in[p1 + 420];
            const uint2* wr = s_w + (ks * 4 + j) * 68 + q;
            #pragma unroll
            for (int nf = 0; nf < 8; ++nf) {
                uint2 b2 = wr[nf * 8];
                mma_tf32(c[0][nf], aA0, aA1, aA2, aA3, b2.x, b2.y);
                mma_tf32(c[1][nf], aB0, aB1, aB2, aB3, b2.x, b2.y);
            }
        }

        #pragma unroll
        for (int nf = 0; nf < 8; ++nf) {
            int ca = n0 + nf * 8 + 2 * j;
            float bva = bias[ca], bvb = bias[ca + 1];
            float va = fmaxf(c[0][nf][0] + bva, 0.f) + fmaxf(c[0][nf][2] + bva, 0.f)
                     + fmaxf(c[1][nf][0] + bva, 0.f) + fmaxf(c[1][nf][2] + bva, 0.f);
            float vb = fmaxf(c[0][nf][1] + bvb, 0.f) + fmaxf(c[0][nf][3] + bvb, 0.f)
                     + fmaxf(c[1][nf][1] + bvb, 0.f) + fmaxf(c[1][nf][3] + bvb, 0.f);
            #pragma unroll
            for (int off = 16; off >= 4; off >>= 1) {
                va += __shfl_down_sync(0xffffffffu, va, off);
                vb += __shfl_down_sync(0xffffffffu, vb, off);
            }
            if (lane < 4) {
                atomicAdd(&s_acc[img * 512 + ca], va);
                atomicAdd(&s_acc[img * 512 + ca + 1], vb);
            }
        }
    }

    __syncthreads();
    for (int i = t; i < 1024; i += 128) {
        int im = i >> 9, ch = i & 511;
        atomicAdd(&f_accum[(bp * 2 + im) * 512 + ch], s_acc[im * 512 + ch]);
    }
}

// ---------------- BM=128 tensor-core 3xTF32 GEMM (pipelined, fused epilogue) --------
// act: 0=none, 2=softplus. For M=128 GEMMs (xz, xproj, dt).
#define GT_SA 136
#define GT_SW 72
__global__ void __launch_bounds__(256)
gemm_tc_kernel(const float* __restrict__ A, int lda,
               const float* __restrict__ W,
               const float* __restrict__ bias, int act,
               float* __restrict__ C, int ldc,
               int M, int N, int K, int atomic)
{
    __shared__ unsigned sAh[16 * GT_SA], sAl[16 * GT_SA];
    __shared__ unsigned sWh[16 * GT_SW], sWl[16 * GT_SW];

    const int bm = blockIdx.y * 128;
    const int bn = blockIdx.x * 64;
    const int t = threadIdx.x, lane = t & 31, w = t >> 5;
    const int kPer = K / gridDim.z;
    const int kBeg = blockIdx.z * kPer;
    const int kEnd = kBeg + kPer;

    const int rA0 = t >> 2,   cA = t & 3;
    const int rA1 = rA0 + 64;
    const int gA0 = min(bm + rA0, M - 1);
    const int gA1 = min(bm + rA1, M - 1);
    const int gW  = bn + rA0;
    const bool wOk = (gW < N);

    float acc[8][4];
    #pragma unroll
    for (int nf = 0; nf < 8; ++nf)
        #pragma unroll
        for (int u2 = 0; u2 < 4; ++u2) acc[nf][u2] = 0.f;

    float4 rAv0 = *reinterpret_cast<const float4*>(A + (size_t)gA0 * lda + kBeg + cA * 4);
    float4 rAv1 = *reinterpret_cast<const float4*>(A + (size_t)gA1 * lda + kBeg + cA * 4);
    float4 rWv  = wOk ? *reinterpret_cast<const float4*>(W + (size_t)gW * K + kBeg + cA * 4)
                      : make_float4(0.f, 0.f, 0.f, 0.f);

    for (int k0 = kBeg; k0 < kEnd; k0 += 16) {
        {
            float vv0[4] = {rAv0.x, rAv0.y, rAv0.z, rAv0.w};
            float vv1[4] = {rAv1.x, rAv1.y, rAv1.z, rAv1.w};
            float vvW[4] = {rWv.x, rWv.y, rWv.z, rWv.w};
            #pragma unroll
            for (int e = 0; e < 4; ++e) {
                unsigned h0 = f2tf32(vv0[e]);
                sAh[(cA * 4 + e) * GT_SA + rA0] = h0;
                sAl[(cA * 4 + e) * GT_SA + rA0] = f2tf32(vv0[e] - __uint_as_float(h0));
                unsigned h1 = f2tf32(vv1[e]);
                sAh[(cA * 4 + e) * GT_SA + rA1] = h1;
                sAl[(cA * 4 + e) * GT_SA + rA1] = f2tf32(vv1[e] - __uint_as_float(h1));
                unsigned hw = f2tf32(vvW[e]);
                sWh[(cA * 4 + e) * GT_SW + rA0] = hw;
                sWl[(cA * 4 + e) * GT_SW + rA0] = f2tf32(vvW[e] - __uint_as_float(hw));
            }
        }
        __syncthreads();

        int kn = k0 + 16;
        if (kn < kEnd) {
            rAv0 = *reinterpret_cast<const float4*>(A + (size_t)gA0 * lda + kn + cA * 4);
            rAv1 = *reinterpret_cast<const float4*>(A + (size_t)gA1 * lda + kn + cA * 4);
            if (wOk)
                rWv = *reinterpret_cast<const float4*>(W + (size_t)gW * K + kn + cA * 4);
        }

        #pragma unroll
        for (int ks = 0; ks < 2; ++ks) {
            int kb = ks * 8;
            int ar = w * 16 + (lane >> 2);
            int ac = kb + (lane & 3);
            unsigned ah0 = sAh[ac * GT_SA + ar];
            unsigned ah1 = sAh[ac * GT_SA + ar + 8];
            unsigned ah2 = sAh[(ac + 4) * GT_SA + ar];
            unsigned ah3 = sAh[(ac + 4) * GT_SA + ar + 8];
            unsigned al0 = sAl[ac * GT_SA + ar];
            unsigned al1 = sAl[ac * GT_SA + ar + 8];
            unsigned al2 = sAl[(ac + 4) * GT_SA + ar];
            unsigned al3 = sAl[(ac + 4) * GT_SA + ar + 8];

            #pragma unroll
            for (int nf = 0; nf < 8; ++nf) {
                int bc = nf * 8 + (lane >> 2);
                int br = kb + (lane & 3);
                unsigned bh0 = sWh[br * GT_SW + bc];
                unsigned bh1 = sWh[(br + 4) * GT_SW + bc];
                unsigned bl0 = sWl[br * GT_SW + bc];
                unsigned bl1 = sWl[(br + 4) * GT_SW + bc];
                mma_tf32(acc[nf], ah0, ah1, ah2, ah3, bh0, bh1);
                mma_tf32(acc[nf], ah0, ah1, ah2, ah3, bl0, bl1);
                mma_tf32(acc[nf], al0, al1, al2, al3, bh0, bh1);
            }
        }
        __syncthreads();
    }

    const int mr0 = bm + w * 16 + (lane >> 2);
    const int nc0 = bn + (lane & 3) * 2;
    #pragma unroll
    for (int nf = 0; nf < 8; ++nf) {
        int n = nc0 + nf * 8;
        if (n >= N) continue;
        if (atomic) {
            if (mr0 < M) {
                atomicAdd(&C[(size_t)mr0 * ldc + n],     acc[nf][0]);
                atomicAdd(&C[(size_t)mr0 * ldc + n + 1], acc[nf][1]);
            }
            if (mr0 + 8 < M) {
                atomicAdd(&C[(size_t)(mr0 + 8) * ldc + n],     acc[nf][2]);
                atomicAdd(&C[(size_t)(mr0 + 8) * ldc + n + 1], acc[nf][3]);
            }
        } else {
            float b0 = bias ? bias[n] : 0.f;
            float b1 = bias ? bias[n + 1] : 0.f;
            float v00 = acc[nf][0] + b0, v01 = acc[nf][1] + b1;
            float v10 = acc[nf][2] + b0, v11 = acc[nf][3] + b1;
            if (act == 2) {
                v00 = (v00 > 20.f) ? v00 : log1pf(expf(v00));
                v01 = (v01 > 20.f) ? v01 : log1pf(expf(v01));
                v10 = (v10 > 20.f) ? v10 : log1pf(expf(v10));
                v11 = (v11 > 20.f) ? v11 : log1pf(expf(v11));
            }
            if (mr0 < M) {
                C[(size_t)mr0 * ldc + n]     = v00;
                C[(size_t)mr0 * ldc + n + 1] = v01;
            }
            if (mr0 + 8 < M) {
                C[(size_t)(mr0 + 8) * ldc + n]     = v10;
                C[(size_t)(mr0 + 8) * ldc + n + 1] = v11;
            }
        }
    }
}

// ---------------- BM=64 tensor-core 3xTF32 GEMM (for M=64 GEMMs: fc, W_out) --------
// 8 warps: warp w -> m-rows (w&3)*16..+16, n-half (w>>2)*32..+32 (4 n-frags).
// act: 0=none (plain/atomic), 3=fc-fused (mean-scale+bias+relu -> build u with reversal:
//      C==u; writes u[(2m+1)*2048+n]=v and u[2m*2048+(2047-n)]=v).
#define GT64_S 72
__global__ void __launch_bounds__(256)
gemm_tc64_kernel(const float* __restrict__ A, int lda,
                 const float* __restrict__ W,
                 const float* __restrict__ bias, int act,
                 float* __restrict__ C, int ldc,
                 int M, int N, int K, int atomic)
{
    __shared__ unsigned sAh[16 * GT64_S], sAl[16 * GT64_S];
    __shared__ unsigned sWh[16 * GT64_S], sWl[16 * GT64_S];

    const int bm = blockIdx.y * 64;
    const int bn = blockIdx.x * 64;
    const int t = threadIdx.x, lane = t & 31, w = t >> 5;
    const int kPer = K / gridDim.z;
    const int kBeg = blockIdx.z * kPer;
    const int kEnd = kBeg + kPer;

    const int rA = t >> 2, cA = t & 3;          // 64 rows x 4 float4
    const int gA = min(bm + rA, M - 1);
    const int gW = bn + rA;
    const bool wOk = (gW < N);

    float acc[4][4];
    #pragma unroll
    for (int nf = 0; nf < 4; ++nf)
        #pragma unroll
        for (int u2 = 0; u2 < 4; ++u2) acc[nf][u2] = 0.f;

    float4 rAv = *reinterpret_cast<const float4*>(A + (size_t)gA * lda + kBeg + cA * 4);
    float4 rWv = wOk ? *reinterpret_cast<const float4*>(W + (size_t)gW * K + kBeg + cA * 4)
                     : make_float4(0.f, 0.f, 0.f, 0.f);

    for (int k0 = kBeg; k0 < kEnd; k0 += 16) {
        {
            float vvA[4] = {rAv.x, rAv.y, rAv.z, rAv.w};
            float vvW[4] = {rWv.x, rWv.y, rWv.z, rWv.w};
            #pragma unroll
            for (int e = 0; e < 4; ++e) {
                unsigned ha = f2tf32(vvA[e]);
                sAh[(cA * 4 + e) * GT64_S + rA] = ha;
                sAl[(cA * 4 + e) * GT64_S + rA] = f2tf32(vvA[e] - __uint_as_float(ha));
                unsigned hw = f2tf32(vvW[e]);
                sWh[(cA * 4 + e) * GT64_S + rA] = hw;
                sWl[(cA * 4 + e) * GT64_S + rA] = f2tf32(vvW[e] - __uint_as_float(hw));
            }
        }
        __syncthreads();

        int kn = k0 + 16;
        if (kn < kEnd) {
            rAv = *reinterpret_cast<const float4*>(A + (size_t)gA * lda + kn + cA * 4);
            if (wOk)
                rWv = *reinterpret_cast<const float4*>(W + (size_t)gW * K + kn + cA * 4);
        }

        #pragma unroll
        for (int ks = 0; ks < 2; ++ks) {
            int kb = ks * 8;
            int ar = (w & 3) * 16 + (lane >> 2);
            int ac = kb + (lane & 3);
            unsigned ah0 = sAh[ac * GT64_S + ar];
            unsigned ah1 = sAh[ac * GT64_S + ar + 8];
            unsigned ah2 = sAh[(ac + 4) * GT64_S + ar];
            unsigned ah3 = sAh[(ac + 4) * GT64_S + ar + 8];
            unsigned al0 = sAl[ac * GT64_S + ar];
            unsigned al1 = sAl[ac * GT64_S + ar + 8];
            unsigned al2 = sAl[(ac + 4) * GT64_S + ar];
            unsigned al3 = sAl[(ac + 4) * GT64_S + ar + 8];

            #pragma unroll
            for (int nf = 0; nf < 4; ++nf) {
                int bc = (w >> 2) * 32 + nf * 8 + (lane >> 2);
                int br = kb + (lane & 3);
                unsigned bh0 = sWh[br * GT64_S + bc];
                unsigned bh1 = sWh[(br + 4) * GT64_S + bc];
                unsigned bl0 = sWl[br * GT64_S + bc];
                unsigned bl1 = sWl[(br + 4) * GT64_S + bc];
                mma_tf32(acc[nf], ah0, ah1, ah2, ah3, bh0, bh1);
                mma_tf32(acc[nf], ah0, ah1, ah2, ah3, bl0, bl1);
                mma_tf32(acc[nf], al0, al1, al2, al3, bh0, bh1);
            }
        }
        __syncthreads();
    }

    const int mr0 = bm + (w & 3) * 16 + (lane >> 2);
    const int nc0 = bn + (w >> 2) * 32 + (lane & 3) * 2;
    #pragma unroll
    for (int nf = 0; nf < 4; ++nf) {
        int n = nc0 + nf * 8;
        if (n >= N) continue;
        if (atomic) {
            if (mr0 < M) {
                atomicAdd(&C[(size_t)mr0 * ldc + n],     acc[nf][0]);
                atomicAdd(&C[(size_t)mr0 * ldc + n + 1], acc[nf][1]);
            }
            if (mr0 + 8 < M) {
                atomicAdd(&C[(size_t)(mr0 + 8) * ldc + n],     acc[nf][2]);
                atomicAdd(&C[(size_t)(mr0 + 8) * ldc + n + 1], acc[nf][3]);
            }
        } else if (act == 3) {
            // fused fc epilogue: v = relu(acc/3136 + bias); u rows 2m+1 (fwd), 2m (reversed)
            float b0 = bias[n], b1 = bias[n + 1];
            #pragma unroll
            for (int h = 0; h < 2; ++h) {
                int m = mr0 + h * 8;
                if (m >= M) continue;
                float v0 = fmaxf(acc[nf][h * 2 + 0] * (1.f / 3136.f) + b0, 0.f);
                float v1 = fmaxf(acc[nf][h * 2 + 1] * (1.f / 3136.f) + b1, 0.f);
                C[(size_t)(2 * m + 1) * DMODEL + n]     = v0;
                C[(size_t)(2 * m + 1) * DMODEL + n + 1] = v1;
                C[(size_t)(2 * m) * DMODEL + (DMODEL - 1 - n)]       = v0;
                C[(size_t)(2 * m) * DMODEL + (DMODEL - 1 - (n + 1))] = v1;
            }
        } else {
            float b0 = bias ? bias[n] : 0.f;
            float b1 = bias ? bias[n + 1] : 0.f;
            if (mr0 < M) {
                C[(size_t)mr0 * ldc + n]     = acc[nf][0] + b0;
                C[(size_t)mr0 * ldc + n + 1] = acc[nf][1] + b1;
            }
            if (mr0 + 8 < M) {
                C[(size_t)(mr0 + 8) * ldc + n]     = acc[nf][2] + b0;
                C[(size_t)(mr0 + 8) * ldc + n + 1] = acc[nf][3] + b1;
            }
        }
    }
}

// ---------------- depthwise conv1d (L=2, causal k=4) + silu ----------------
__global__ void conv1d_silu_kernel(const float* __restrict__ xz, const float* __restrict__ w,
                                   const float* __restrict__ bias, float* __restrict__ xs)
{
    int idx = blockIdx.x * blockDim.x + threadIdx.x;
    if (idx >= NB * DINNER) return;
    int b = idx >> 12, e = idx & 4095;
    float x0 = xz[(2 * b) * (2 * DINNER) + e];
    float x1 = xz[(2 * b + 1) * (2 * DINNER) + e];
    float w2 = w[e * 4 + 2], w3 = w[e * 4 + 3];
    float bv = bias[e];
    float v0 = x0 * w3 + bv;
    float v1 = x0 * w2 + x1 * w3 + bv;
    xs[(2 * b) * DINNER + e]     = v0 / (1.f + expf(-v0));
    xs[(2 * b + 1) * DINNER + e] = v1 / (1.f + expf(-v1));
}

// ---------------- selective scan (L=2, closed form) + D skip + silu(z) gating --------
__global__ void scan_kernel(const float* __restrict__ xz, const float* __restrict__ xs,
                            const float* __restrict__ xdbl, const float* __restrict__ dt,
                            const float* __restrict__ A_log, const float* __restrict__ Dv,
                            float* __restrict__ y)
{
    int idx = blockIdx.x * blockDim.x + threadIdx.x;
    if (idx >= NB * DINNER) return;
    int b = idx >> 12, e = idx & 4095;

    float dt0 = dt[(2 * b) * DINNER + e];
    float dt1 = dt[(2 * b + 1) * DINNER + e];
    float x0  = xs[(2 * b) * DINNER + e];
    float x1  = xs[(2 * b + 1) * DINNER + e];
    float z1  = xz[(2 * b + 1) * (2 * DINNER) + DINNER + e];

    const float* bc0 = xdbl + (2 * b) * 160;
    const float* bc1 = xdbl + (2 * b + 1) * 160;

    float acc = 0.f;
    #pragma unroll
    for (int n = 0; n < DSTATE; ++n) {
        float Ae = -expf(A_log[e * DSTATE + n]);
        float h = dt0 * bc0[DTRANK + n] * x0;
        h = h * expf(dt1 * Ae) + dt1 * bc1[DTRANK + n] * x1;
        acc += h * bc1[DTRANK + DSTATE + n];
    }
    float yv = acc + x1 * Dv[e];
    float sg = z1 / (1.f + expf(-z1));
    y[b * DINNER + e] = yv * sg;
}

// ---------------- output heads ----------------
__global__ void heads_kernel(const float* __restrict__ feat,
                             const float* __restrict__ wxyz, const float* __restrict__ bxyz,
                             const float* __restrict__ wpqr, const float* __restrict__ bpqr,
                             float* __restrict__ out)
{
    int b = blockIdx.x / 7, j = blockIdx.x % 7;
    const float* wrow = (j < 3) ? (wxyz + j * DMODEL) : (wpqr + (j - 3) * DMODEL);
    float bias = (j < 3) ? bxyz[j] : bpqr[j - 3];

    float s = 0.f;
    for (int i = threadIdx.x; i < DMODEL; i += 128)
        s += feat[b * DMODEL + i] * wrow[i];

    __shared__ float red[4];
    #pragma unroll
    for (int off = 16; off; off >>= 1) s += __shfl_down_sync(0xffffffffu, s, off);
    if ((threadIdx.x & 31) == 0) red[threadIdx.x >> 5] = s;
    __syncthreads();
    if (threadIdx.x == 0)
        out[b * 7 + j] = red[0] + red[1] + red[2] + red[3] + bias;
}

// ---------------- launcher ----------------
extern "C" void kernel_launch(void* const* d_in, const int* in_sizes, int n_in,
                              void* d_out, int out_size)
{
    const float* x       = (const float*)d_in[0];
    const float* conv_w  = (const float*)d_in[1];
    const float* conv_b  = (const float*)d_in[2];
    const float* fc_w    = (const float*)d_in[3];
    const float* fc_b    = (const float*)d_in[4];
    const float* W_in    = (const float*)d_in[5];
    const float* c1w     = (const float*)d_in[6];
    const float* c1b     = (const float*)d_in[7];
    const float* W_xproj = (const float*)d_in[8];
    const float* W_dt    = (const float*)d_in[9];
    const float* b_dt    = (const float*)d_in[10];
    const float* A_log   = (const float*)d_in[11];
    const float* Dv      = (const float*)d_in[12];
    const float* W_out   = (const float*)d_in[13];
    const float* wxyz    = (const float*)d_in[14];
    const float* bxyz    = (const float*)d_in[15];
    const float* wpqr    = (const float*)d_in[16];
    const float* bpqr    = (const float*)d_in[17];
    float* out = (float*)d_out;

    void* sp = nullptr;
    cudaGetSymbolAddress(&sp, g_scratch);
    float* S = (float*)sp;

    float* f     = S + OFF_F;
    float* u     = S + OFF_U;
    float* xz    = S + OFF_XZ;
    float* xs    = S + OFF_XS;
    float* xdbl  = S + OFF_XDBL;
    float* dtb   = S + OFF_DT;
    float* y     = S + OFF_Y;
    float* feat  = S + OFF_FEAT;
    uint2* wTp   = (uint2*)(S + OFF_WT);

    cudaFuncSetAttribute(conv_tc_kernel,
                         cudaFuncAttributeMaxDynamicSharedMemorySize,
                         CONV_SMEM_TOTAL);

    // NOTE: f accumulator must be zeroed; fold it in prep_zero? f (32768) is
    // written by conv atomics -> zero here too (append range).
    // (1) prep: weight pack + zero xdbl/feat, then separate tiny zero for f
    prep_zero_kernel<<<(PZ_TOT + 255) / 256, 256>>>(conv_w, S);
    cudaMemsetAsync(f, 0, 32768 * sizeof(float));
    // (2) conv + relu + spatial sum (tensor cores)
    conv_tc_kernel<<<dim3(49, 32), 128, CONV_SMEM_TOTAL>>>(x, wTp, conv_b, f);
    // (3) fc + build_u fused  (64 x 2048 x 512, BM=64, z=1, act=3 writes u)
    gemm_tc64_kernel<<<dim3(32, 1, 1), 256>>>(f, 512, fc_w, fc_b, 3,
                                              u, DMODEL, 64, 2048, 512, 0);
    // (4) xz = u @ W_in^T  (128 x 8192 x 2048) — profiled slot
    gemm_tc_kernel<<<dim3(128, 1, 1), 256>>>(u, 2048, W_in, nullptr, 0,
                                             xz, 8192, 128, 8192, 2048, 0);
    // (5) depthwise conv1d + silu
    conv1d_silu_kernel<<<1024, 256>>>(xz, c1w, c1b, xs);
    // (6) x_dbl = xs @ W_xproj^T  (128 x 160 x 4096) — split-K=16 atomic
    gemm_tc_kernel<<<dim3(3, 1, 16), 256>>>(xs, 4096, W_xproj, nullptr, 0,
                                            xdbl, 160, 128, 160, 4096, 1);
    // (7) dt = softplus(x_dbl[:, :128] @ W_dt^T + b_dt)  (128 x 4096 x 128)
    gemm_tc_kernel<<<dim3(64, 1, 1), 256>>>(xdbl, 160, W_dt, b_dt, 2,
                                            dtb, 4096, 128, 4096, 128, 0);
    // (8) scan + gating -> y
    scan_kernel<<<1024, 256>>>(xz, xs, xdbl, dtb, A_log, Dv, y);
    // (9) feat = y @ W_out^T  (64 x 2048 x 4096, BM=64, split-K=4 atomic)
    gemm_tc64_kernel<<<dim3(32, 1, 4), 256>>>(y, 4096, W_out, nullptr, 0,
                                              feat, 2048, 64, 2048, 4096, 1);
    // (10) heads
    heads_kernel<<<448, 128>>>(feat, wxyz, bxyz, wpqr, bpqr, out);
}

// round 14
// speedup vs baseline: 3.4297x; 1.0457x over previous
#include <cuda_runtime.h>
#include <math.h>

// ---------------- problem constants ----------------
#define NB      64
#define DMODEL  2048
#define DINNER  4096
#define DSTATE  16
#define DTRANK  128
#define FE      512

// ---------------- scratch layout (floats) ----------------
#define OFF_F     0          // 64*512      conv relu-sum accumulator
#define OFF_U     163840     // 128*2048    mamba input u (rows = b*2+l)
#define OFF_XZ    425984     // 128*8192    xz = u @ W_in^T (split-K atomic)
#define OFF_XS    1474560    // 128*4096    silu(conv1d(x))
#define OFF_XDBL  1998848    // 128*160     x_dbl
#define OFF_DT    2019328    // 128*4096    dt (softplus)
#define OFF_Y     2543616    // 64*4096     gated scan output at l=1
#define OFF_FEAT  2805760    // 64*2048     y @ W_out^T
#define OFF_WT    2936832    // 76*512 uint2: packed tf32 conv weights (k,k+4 pairs)
#define SCRATCH_TOTAL 3014656

__device__ float g_scratch[SCRATCH_TOTAL];

// conv_tc dynamic smem layout (bytes) — 64-channel weight chunks (R8 proven config)
#define CONV_SMEM_W     0                    // 76*68 uint2 = 41344
#define CONV_SMEM_ACC   41344                // 2*512 float = 4096
#define CONV_SMEM_IN    45440                // 2*3*35*35 tf32 = 29400
#define CONV_SMEM_TOTAL 74840

// ---------------- tf32 mma helpers ----------------
__device__ __forceinline__ unsigned f2tf32(float v) {
    unsigned r;
    asm("cvt.rna.tf32.f32 %0, %1;" : "=r"(r) : "f"(v));
    return r;
}
__device__ __forceinline__ void mma_tf32(float c[4],
                                         unsigned a0, unsigned a1, unsigned a2, unsigned a3,
                                         unsigned b0, unsigned b1) {
    asm volatile(
        "mma.sync.aligned.m16n8k8.row.col.f32.tf32.tf32.f32 "
        "{%0,%1,%2,%3}, {%4,%5,%6,%7}, {%8,%9}, {%0,%1,%2,%3};"
        : "+f"(c[0]), "+f"(c[1]), "+f"(c[2]), "+f"(c[3])
        : "r"(a0), "r"(a1), "r"(a2), "r"(a3), "r"(b0), "r"(b1));
}

// ---------------- fused prep: conv weight pack + zero ALL accumulators ----------------
// ranges: [0, 38912)        pack wTp
//         [38912, 59392)    zero xdbl  (20480)
//         [59392, 190464)   zero feat  (131072)
//         [190464, 223232)  zero f     (32768)
//         [223232, 1271808) zero xz    (1048576)
#define PZ_WT   38912
#define PZ_XD   59392
#define PZ_FT   190464
#define PZ_F    223232
#define PZ_TOT  1271808
__global__ void prep_zero_kernel(const float* __restrict__ w, float* S) {
    int i = blockIdx.x * blockDim.x + threadIdx.x;
    if (i >= PZ_TOT) return;
    if (i < PZ_WT) {
        int kp = i >> 9, co = i & 511;
        int k0 = (kp >> 2) * 8 + (kp & 3);
        int k1 = k0 + 4;
        float v0 = (k0 < 147) ? w[co * 147 + k0] : 0.f;
        float v1 = (k1 < 147) ? w[co * 147 + k1] : 0.f;
        ((uint2*)(S + OFF_WT))[kp * 512 + co] = make_uint2(f2tf32(v0), f2tf32(v1));
    } else if (i < PZ_XD) {
        S[OFF_XDBL + (i - PZ_WT)] = 0.f;
    } else if (i < PZ_FT) {
        S[OFF_FEAT + (i - PZ_XD)] = 0.f;
    } else if (i < PZ_F) {
        S[OFF_F + (i - PZ_FT)] = 0.f;
    } else {
        S[OFF_XZ + (i - PZ_F)] = 0.f;
    }
}

// ---------------- conv 7x7 s4 p3 + bias + relu + spatial-sum (tensor cores) ----------
// grid (49, 32), block 128 (4 warps). Each block: 8x8 output tile of TWO images.
// 64-channel weight chunks (8 chunks), 74.8 KB smem, 3 blocks/SM. (R8 proven config)
__global__ void __launch_bounds__(128)
conv_tc_kernel(const float* __restrict__ x, const uint2* __restrict__ wTp,
               const float* __restrict__ bias, float* __restrict__ f_accum)
{
    extern __shared__ __align__(16) char smem[];
    uint2*    s_w  = reinterpret_cast<uint2*>(smem + CONV_SMEM_W);       // [76][68]
    float*    s_acc = reinterpret_cast<float*>(smem + CONV_SMEM_ACC);    // [2][512]
    unsigned* s_in  = reinterpret_cast<unsigned*>(smem + CONV_SMEM_IN);  // [2][3][35][35] tf32

    const int t    = threadIdx.x;
    const int tile = blockIdx.x;
    const int bp   = blockIdx.y;            // image pair
    const int oh_base = (tile / 7) * 8;
    const int ow_base = (tile % 7) * 8;
    const int ih0 = oh_base * 4 - 3;
    const int iw0 = ow_base * 4 - 3;

    for (int i = t; i < 1024; i += 128) s_acc[i] = 0.f;

    for (int i = t; i < 2 * 3 * 1225; i += 128) {
        int img = i / 3675;
        int rem = i - img * 3675;
        int ci  = rem / 1225; rem -= ci * 1225;
        int r = rem / 35, c = rem - (rem / 35) * 35;
        int ih = ih0 + r, iw = iw0 + c;
        float v = 0.f;
        int b = bp * 2 + img;
        if ((unsigned)ih < 224u && (unsigned)iw < 224u)
            v = x[((b * 3 + ci) * 224 + ih) * 224 + iw];
        s_in[(img * 3 + ci) * 1225 + r * 35 + c] = f2tf32(v);
    }

    const int lane = t & 31;
    const int w    = t >> 5;
    const int img  = w >> 1;
    const int half = w & 1;
    const int q    = lane >> 2;
    const int j    = lane & 3;
    const int ya = half * 16;
    const int xb = q * 4;
    const unsigned* my_in = s_in + img * 3675 + ya * 35 + xb;

    int o0[19], o1[19];
    #pragma unroll
    for (int ks = 0; ks < 19; ++ks) {
        int k0 = ks * 8 + j, k1 = k0 + 4;
        int kk0 = min(k0, 146), kk1 = min(k1, 146);
        int ci0 = kk0 / 49, r0 = kk0 - ci0 * 49;
        int kh0 = r0 / 7,  kw0 = r0 - kh0 * 7;
        int ci1 = kk1 / 49, r1 = kk1 - ci1 * 49;
        int kh1 = r1 / 7,  kw1 = r1 - kh1 * 7;
        o0[ks] = ci0 * 1225 + kh0 * 35 + kw0;
        o1[ks] = ci1 * 1225 + kh1 * 35 + kw1;
    }

    for (int n0 = 0; n0 < 512; n0 += 64) {
        __syncthreads();
        {
            const uint4* src = reinterpret_cast<const uint4*>(wTp);
            uint4* dst = reinterpret_cast<uint4*>(s_w);
            for (int i = t; i < 76 * 32; i += 128) {
                int row = i >> 5, c = i & 31;
                dst[row * 34 + c] = src[row * 256 + (n0 >> 1) + c];
            }
        }
        __syncthreads();

        float c[2][8][4];
        #pragma unroll
        for (int f2 = 0; f2 < 2; ++f2)
            #pragma unroll
            for (int nf = 0; nf < 8; ++nf)
                #pragma unroll
                for (int u2 = 0; u2 < 4; ++u2) c[f2][nf][u2] = 0.f;

        #pragma unroll
        for (int ks = 0; ks < 19; ++ks) {
            int p0 = o0[ks], p1 = o1[ks];
            unsigned aA0 = my_in[p0];
            unsigned aA1 = my_in[p0 + 140];
            unsigned aA2 = my_in[p1];
            unsigned aA3 = my_in[p1 + 140];
            unsigned aB0 = my_in[p0 + 280];
            unsigned aB1 = my_in[p0 + 420];
            unsigned aB2 = my_in[p1 + 280];
            unsigned aB3 = my_in[p1 + 420];
            const uint2* wr = s_w + (ks * 4 + j) * 68 + q;
            #pragma unroll
            for (int nf = 0; nf < 8; ++nf) {
                uint2 b2 = wr[nf * 8];
                mma_tf32(c[0][nf], aA0, aA1, aA2, aA3, b2.x, b2.y);
                mma_tf32(c[1][nf], aB0, aB1, aB2, aB3, b2.x, b2.y);
            }
        }

        #pragma unroll
        for (int nf = 0; nf < 8; ++nf) {
            int ca = n0 + nf * 8 + 2 * j;
            float bva = bias[ca], bvb = bias[ca + 1];
            float va = fmaxf(c[0][nf][0] + bva, 0.f) + fmaxf(c[0][nf][2] + bva, 0.f)
                     + fmaxf(c[1][nf][0] + bva, 0.f) + fmaxf(c[1][nf][2] + bva, 0.f);
            float vb = fmaxf(c[0][nf][1] + bvb, 0.f) + fmaxf(c[0][nf][3] + bvb, 0.f)
                     + fmaxf(c[1][nf][1] + bvb, 0.f) + fmaxf(c[1][nf][3] + bvb, 0.f);
            #pragma unroll
            for (int off = 16; off >= 4; off >>= 1) {
                va += __shfl_down_sync(0xffffffffu, va, off);
                vb += __shfl_down_sync(0xffffffffu, vb, off);
            }
            if (lane < 4) {
                atomicAdd(&s_acc[img * 512 + ca], va);
                atomicAdd(&s_acc[img * 512 + ca + 1], vb);
            }
        }
    }

    __syncthreads();
    for (int i = t; i < 1024; i += 128) {
        int im = i >> 9, ch = i & 511;
        atomicAdd(&f_accum[(bp * 2 + im) * 512 + ch], s_acc[im * 512 + ch]);
    }
}

// ---------------- BM=128 tensor-core 3xTF32 GEMM (pipelined, fused epilogue) --------
// act: 0=none, 2=softplus. For M=128 GEMMs (xz, xproj, dt).
#define GT_SA 136
#define GT_SW 72
__global__ void __launch_bounds__(256)
gemm_tc_kernel(const float* __restrict__ A, int lda,
               const float* __restrict__ W,
               const float* __restrict__ bias, int act,
               float* __restrict__ C, int ldc,
               int M, int N, int K, int atomic)
{
    __shared__ unsigned sAh[16 * GT_SA], sAl[16 * GT_SA];
    __shared__ unsigned sWh[16 * GT_SW], sWl[16 * GT_SW];

    const int bm = blockIdx.y * 128;
    const int bn = blockIdx.x * 64;
    const int t = threadIdx.x, lane = t & 31, w = t >> 5;
    const int kPer = K / gridDim.z;
    const int kBeg = blockIdx.z * kPer;
    const int kEnd = kBeg + kPer;

    const int rA0 = t >> 2,   cA = t & 3;
    const int rA1 = rA0 + 64;
    const int gA0 = min(bm + rA0, M - 1);
    const int gA1 = min(bm + rA1, M - 1);
    const int gW  = bn + rA0;
    const bool wOk = (gW < N);

    float acc[8][4];
    #pragma unroll
    for (int nf = 0; nf < 8; ++nf)
        #pragma unroll
        for (int u2 = 0; u2 < 4; ++u2) acc[nf][u2] = 0.f;

    float4 rAv0 = *reinterpret_cast<const float4*>(A + (size_t)gA0 * lda + kBeg + cA * 4);
    float4 rAv1 = *reinterpret_cast<const float4*>(A + (size_t)gA1 * lda + kBeg + cA * 4);
    float4 rWv  = wOk ? *reinterpret_cast<const float4*>(W + (size_t)gW * K + kBeg + cA * 4)
                      : make_float4(0.f, 0.f, 0.f, 0.f);

    for (int k0 = kBeg; k0 < kEnd; k0 += 16) {
        {
            float vv0[4] = {rAv0.x, rAv0.y, rAv0.z, rAv0.w};
            float vv1[4] = {rAv1.x, rAv1.y, rAv1.z, rAv1.w};
            float vvW[4] = {rWv.x, rWv.y, rWv.z, rWv.w};
            #pragma unroll
            for (int e = 0; e < 4; ++e) {
                unsigned h0 = f2tf32(vv0[e]);
                sAh[(cA * 4 + e) * GT_SA + rA0] = h0;
                sAl[(cA * 4 + e) * GT_SA + rA0] = f2tf32(vv0[e] - __uint_as_float(h0));
                unsigned h1 = f2tf32(vv1[e]);
                sAh[(cA * 4 + e) * GT_SA + rA1] = h1;
                sAl[(cA * 4 + e) * GT_SA + rA1] = f2tf32(vv1[e] - __uint_as_float(h1));
                unsigned hw = f2tf32(vvW[e]);
                sWh[(cA * 4 + e) * GT_SW + rA0] = hw;
                sWl[(cA * 4 + e) * GT_SW + rA0] = f2tf32(vvW[e] - __uint_as_float(hw));
            }
        }
        __syncthreads();

        int kn = k0 + 16;
        if (kn < kEnd) {
            rAv0 = *reinterpret_cast<const float4*>(A + (size_t)gA0 * lda + kn + cA * 4);
            rAv1 = *reinterpret_cast<const float4*>(A + (size_t)gA1 * lda + kn + cA * 4);
            if (wOk)
                rWv = *reinterpret_cast<const float4*>(W + (size_t)gW * K + kn + cA * 4);
        }

        #pragma unroll
        for (int ks = 0; ks < 2; ++ks) {
            int kb = ks * 8;
            int ar = w * 16 + (lane >> 2);
            int ac = kb + (lane & 3);
            unsigned ah0 = sAh[ac * GT_SA + ar];
            unsigned ah1 = sAh[ac * GT_SA + ar + 8];
            unsigned ah2 = sAh[(ac + 4) * GT_SA + ar];
            unsigned ah3 = sAh[(ac + 4) * GT_SA + ar + 8];
            unsigned al0 = sAl[ac * GT_SA + ar];
            unsigned al1 = sAl[ac * GT_SA + ar + 8];
            unsigned al2 = sAl[(ac + 4) * GT_SA + ar];
            unsigned al3 = sAl[(ac + 4) * GT_SA + ar + 8];

            #pragma unroll
            for (int nf = 0; nf < 8; ++nf) {
                int bc = nf * 8 + (lane >> 2);
                int br = kb + (lane & 3);
                unsigned bh0 = sWh[br * GT_SW + bc];
                unsigned bh1 = sWh[(br + 4) * GT_SW + bc];
                unsigned bl0 = sWl[br * GT_SW + bc];
                unsigned bl1 = sWl[(br + 4) * GT_SW + bc];
                mma_tf32(acc[nf], ah0, ah1, ah2, ah3, bh0, bh1);
                mma_tf32(acc[nf], ah0, ah1, ah2, ah3, bl0, bl1);
                mma_tf32(acc[nf], al0, al1, al2, al3, bh0, bh1);
            }
        }
        __syncthreads();
    }

    const int mr0 = bm + w * 16 + (lane >> 2);
    const int nc0 = bn + (lane & 3) * 2;
    #pragma unroll
    for (int nf = 0; nf < 8; ++nf) {
        int n = nc0 + nf * 8;
        if (n >= N) continue;
        if (atomic) {
            if (mr0 < M) {
                atomicAdd(&C[(size_t)mr0 * ldc + n],     acc[nf][0]);
                atomicAdd(&C[(size_t)mr0 * ldc + n + 1], acc[nf][1]);
            }
            if (mr0 + 8 < M) {
                atomicAdd(&C[(size_t)(mr0 + 8) * ldc + n],     acc[nf][2]);
                atomicAdd(&C[(size_t)(mr0 + 8) * ldc + n + 1], acc[nf][3]);
            }
        } else {
            float b0 = bias ? bias[n] : 0.f;
            float b1 = bias ? bias[n + 1] : 0.f;
            float v00 = acc[nf][0] + b0, v01 = acc[nf][1] + b1;
            float v10 = acc[nf][2] + b0, v11 = acc[nf][3] + b1;
            if (act == 2) {
                v00 = (v00 > 20.f) ? v00 : log1pf(expf(v00));
                v01 = (v01 > 20.f) ? v01 : log1pf(expf(v01));
                v10 = (v10 > 20.f) ? v10 : log1pf(expf(v10));
                v11 = (v11 > 20.f) ? v11 : log1pf(expf(v11));
            }
            if (mr0 < M) {
                C[(size_t)mr0 * ldc + n]     = v00;
                C[(size_t)mr0 * ldc + n + 1] = v01;
            }
            if (mr0 + 8 < M) {
                C[(size_t)(mr0 + 8) * ldc + n]     = v10;
                C[(size_t)(mr0 + 8) * ldc + n + 1] = v11;
            }
        }
    }
}

// ---------------- BM=64 tensor-core 3xTF32 GEMM (for M=64 GEMMs: fc, W_out) --------
// 8 warps: warp w -> m-rows (w&3)*16..+16, n-half (w>>2)*32..+32 (4 n-frags).
// act: 0=none (plain/atomic), 3=fc-fused (mean-scale+bias+relu -> u with reversal).
#define GT64_S 72
__global__ void __launch_bounds__(256)
gemm_tc64_kernel(const float* __restrict__ A, int lda,
                 const float* __restrict__ W,
                 const float* __restrict__ bias, int act,
                 float* __restrict__ C, int ldc,
                 int M, int N, int K, int atomic)
{
    __shared__ unsigned sAh[16 * GT64_S], sAl[16 * GT64_S];
    __shared__ unsigned sWh[16 * GT64_S], sWl[16 * GT64_S];

    const int bm = blockIdx.y * 64;
    const int bn = blockIdx.x * 64;
    const int t = threadIdx.x, lane = t & 31, w = t >> 5;
    const int kPer = K / gridDim.z;
    const int kBeg = blockIdx.z * kPer;
    const int kEnd = kBeg + kPer;

    const int rA = t >> 2, cA = t & 3;
    const int gA = min(bm + rA, M - 1);
    const int gW = bn + rA;
    const bool wOk = (gW < N);

    float acc[4][4];
    #pragma unroll
    for (int nf = 0; nf < 4; ++nf)
        #pragma unroll
        for (int u2 = 0; u2 < 4; ++u2) acc[nf][u2] = 0.f;

    float4 rAv = *reinterpret_cast<const float4*>(A + (size_t)gA * lda + kBeg + cA * 4);
    float4 rWv = wOk ? *reinterpret_cast<const float4*>(W + (size_t)gW * K + kBeg + cA * 4)
                     : make_float4(0.f, 0.f, 0.f, 0.f);

    for (int k0 = kBeg; k0 < kEnd; k0 += 16) {
        {
            float vvA[4] = {rAv.x, rAv.y, rAv.z, rAv.w};
            float vvW[4] = {rWv.x, rWv.y, rWv.z, rWv.w};
            #pragma unroll
            for (int e = 0; e < 4; ++e) {
                unsigned ha = f2tf32(vvA[e]);
                sAh[(cA * 4 + e) * GT64_S + rA] = ha;
                sAl[(cA * 4 + e) * GT64_S + rA] = f2tf32(vvA[e] - __uint_as_float(ha));
                unsigned hw = f2tf32(vvW[e]);
                sWh[(cA * 4 + e) * GT64_S + rA] = hw;
                sWl[(cA * 4 + e) * GT64_S + rA] = f2tf32(vvW[e] - __uint_as_float(hw));
            }
        }
        __syncthreads();

        int kn = k0 + 16;
        if (kn < kEnd) {
            rAv = *reinterpret_cast<const float4*>(A + (size_t)gA * lda + kn + cA * 4);
            if (wOk)
                rWv = *reinterpret_cast<const float4*>(W + (size_t)gW * K + kn + cA * 4);
        }

        #pragma unroll
        for (int ks = 0; ks < 2; ++ks) {
            int kb = ks * 8;
            int ar = (w & 3) * 16 + (lane >> 2);
            int ac = kb + (lane & 3);
            unsigned ah0 = sAh[ac * GT64_S + ar];
            unsigned ah1 = sAh[ac * GT64_S + ar + 8];
            unsigned ah2 = sAh[(ac + 4) * GT64_S + ar];
            unsigned ah3 = sAh[(ac + 4) * GT64_S + ar + 8];
            unsigned al0 = sAl[ac * GT64_S + ar];
            unsigned al1 = sAl[ac * GT64_S + ar + 8];
            unsigned al2 = sAl[(ac + 4) * GT64_S + ar];
            unsigned al3 = sAl[(ac + 4) * GT64_S + ar + 8];

            #pragma unroll
            for (int nf = 0; nf < 4; ++nf) {
                int bc = (w >> 2) * 32 + nf * 8 + (lane >> 2);
                int br = kb + (lane & 3);
                unsigned bh0 = sWh[br * GT64_S + bc];
                unsigned bh1 = sWh[(br + 4) * GT64_S + bc];
                unsigned bl0 = sWl[br * GT64_S + bc];
                unsigned bl1 = sWl[(br + 4) * GT64_S + bc];
                mma_tf32(acc[nf], ah0, ah1, ah2, ah3, bh0, bh1);
                mma_tf32(acc[nf], ah0, ah1, ah2, ah3, bl0, bl1);
                mma_tf32(acc[nf], al0, al1, al2, al3, bh0, bh1);
            }
        }
        __syncthreads();
    }

    const int mr0 = bm + (w & 3) * 16 + (lane >> 2);
    const int nc0 = bn + (w >> 2) * 32 + (lane & 3) * 2;
    #pragma unroll
    for (int nf = 0; nf < 4; ++nf) {
        int n = nc0 + nf * 8;
        if (n >= N) continue;
        if (atomic) {
            if (mr0 < M) {
                atomicAdd(&C[(size_t)mr0 * ldc + n],     acc[nf][0]);
                atomicAdd(&C[(size_t)mr0 * ldc + n + 1], acc[nf][1]);
            }
            if (mr0 + 8 < M) {
                atomicAdd(&C[(size_t)(mr0 + 8) * ldc + n],     acc[nf][2]);
                atomicAdd(&C[(size_t)(mr0 + 8) * ldc + n + 1], acc[nf][3]);
            }
        } else if (act == 3) {
            float b0 = bias[n], b1 = bias[n + 1];
            #pragma unroll
            for (int h = 0; h < 2; ++h) {
                int m = mr0 + h * 8;
                if (m >= M) continue;
                float v0 = fmaxf(acc[nf][h * 2 + 0] * (1.f / 3136.f) + b0, 0.f);
                float v1 = fmaxf(acc[nf][h * 2 + 1] * (1.f / 3136.f) + b1, 0.f);
                C[(size_t)(2 * m + 1) * DMODEL + n]     = v0;
                C[(size_t)(2 * m + 1) * DMODEL + n + 1] = v1;
                C[(size_t)(2 * m) * DMODEL + (DMODEL - 1 - n)]       = v0;
                C[(size_t)(2 * m) * DMODEL + (DMODEL - 1 - (n + 1))] = v1;
            }
        } else {
            float b0 = bias ? bias[n] : 0.f;
            float b1 = bias ? bias[n + 1] : 0.f;
            if (mr0 < M) {
                C[(size_t)mr0 * ldc + n]     = acc[nf][0] + b0;
                C[(size_t)mr0 * ldc + n + 1] = acc[nf][1] + b1;
            }
            if (mr0 + 8 < M) {
                C[(size_t)(mr0 + 8) * ldc + n]     = acc[nf][2] + b0;
                C[(size_t)(mr0 + 8) * ldc + n + 1] = acc[nf][3] + b1;
            }
        }
    }
}

// ---------------- depthwise conv1d (L=2, causal k=4) + silu ----------------
__global__ void conv1d_silu_kernel(const float* __restrict__ xz, const float* __restrict__ w,
                                   const float* __restrict__ bias, float* __restrict__ xs)
{
    int idx = blockIdx.x * blockDim.x + threadIdx.x;
    if (idx >= NB * DINNER) return;
    int b = idx >> 12, e = idx & 4095;
    float x0 = xz[(2 * b) * (2 * DINNER) + e];
    float x1 = xz[(2 * b + 1) * (2 * DINNER) + e];
    float w2 = w[e * 4 + 2], w3 = w[e * 4 + 3];
    float bv = bias[e];
    float v0 = x0 * w3 + bv;
    float v1 = x0 * w2 + x1 * w3 + bv;
    xs[(2 * b) * DINNER + e]     = v0 / (1.f + expf(-v0));
    xs[(2 * b + 1) * DINNER + e] = v1 / (1.f + expf(-v1));
}

// ---------------- selective scan (L=2, closed form) + D skip + silu(z) gating --------
__global__ void scan_kernel(const float* __restrict__ xz, const float* __restrict__ xs,
                            const float* __restrict__ xdbl, const float* __restrict__ dt,
                            const float* __restrict__ A_log, const float* __restrict__ Dv,
                            float* __restrict__ y)
{
    int idx = blockIdx.x * blockDim.x + threadIdx.x;
    if (idx >= NB * DINNER) return;
    int b = idx >> 12, e = idx & 4095;

    float dt0 = dt[(2 * b) * DINNER + e];
    float dt1 = dt[(2 * b + 1) * DINNER + e];
    float x0  = xs[(2 * b) * DINNER + e];
    float x1  = xs[(2 * b + 1) * DINNER + e];
    float z1  = xz[(2 * b + 1) * (2 * DINNER) + DINNER + e];

    const float* bc0 = xdbl + (2 * b) * 160;
    const float* bc1 = xdbl + (2 * b + 1) * 160;

    float acc = 0.f;
    #pragma unroll
    for (int n = 0; n < DSTATE; ++n) {
        float Ae = -expf(A_log[e * DSTATE + n]);
        float h = dt0 * bc0[DTRANK + n] * x0;
        h = h * expf(dt1 * Ae) + dt1 * bc1[DTRANK + n] * x1;
        acc += h * bc1[DTRANK + DSTATE + n];
    }
    float yv = acc + x1 * Dv[e];
    float sg = z1 / (1.f + expf(-z1));
    y[b * DINNER + e] = yv * sg;
}

// ---------------- output heads ----------------
__global__ void heads_kernel(const float* __restrict__ feat,
                             const float* __restrict__ wxyz, const float* __restrict__ bxyz,
                             const float* __restrict__ wpqr, const float* __restrict__ bpqr,
                             float* __restrict__ out)
{
    int b = blockIdx.x / 7, j = blockIdx.x % 7;
    const float* wrow = (j < 3) ? (wxyz + j * DMODEL) : (wpqr + (j - 3) * DMODEL);
    float bias = (j < 3) ? bxyz[j] : bpqr[j - 3];

    float s = 0.f;
    for (int i = threadIdx.x; i < DMODEL; i += 128)
        s += feat[b * DMODEL + i] * wrow[i];

    __shared__ float red[4];
    #pragma unroll
    for (int off = 16; off; off >>= 1) s += __shfl_down_sync(0xffffffffu, s, off);
    if ((threadIdx.x & 31) == 0) red[threadIdx.x >> 5] = s;
    __syncthreads();
    if (threadIdx.x == 0)
        out[b * 7 + j] = red[0] + red[1] + red[2] + red[3] + bias;
}

// ---------------- launcher ----------------
extern "C" void kernel_launch(void* const* d_in, const int* in_sizes, int n_in,
                              void* d_out, int out_size)
{
    const float* x       = (const float*)d_in[0];
    const float* conv_w  = (const float*)d_in[1];
    const float* conv_b  = (const float*)d_in[2];
    const float* fc_w    = (const float*)d_in[3];
    const float* fc_b    = (const float*)d_in[4];
    const float* W_in    = (const float*)d_in[5];
    const float* c1w     = (const float*)d_in[6];
    const float* c1b     = (const float*)d_in[7];
    const float* W_xproj = (const float*)d_in[8];
    const float* W_dt    = (const float*)d_in[9];
    const float* b_dt    = (const float*)d_in[10];
    const float* A_log   = (const float*)d_in[11];
    const float* Dv      = (const float*)d_in[12];
    const float* W_out   = (const float*)d_in[13];
    const float* wxyz    = (const float*)d_in[14];
    const float* bxyz    = (const float*)d_in[15];
    const float* wpqr    = (const float*)d_in[16];
    const float* bpqr    = (const float*)d_in[17];
    float* out = (float*)d_out;

    void* sp = nullptr;
    cudaGetSymbolAddress(&sp, g_scratch);
    float* S = (float*)sp;

    float* f     = S + OFF_F;
    float* u     = S + OFF_U;
    float* xz    = S + OFF_XZ;
    float* xs    = S + OFF_XS;
    float* xdbl  = S + OFF_XDBL;
    float* dtb   = S + OFF_DT;
    float* y     = S + OFF_Y;
    float* feat  = S + OFF_FEAT;
    uint2* wTp   = (uint2*)(S + OFF_WT);

    cudaFuncSetAttribute(conv_tc_kernel,
                         cudaFuncAttributeMaxDynamicSharedMemorySize,
                         CONV_SMEM_TOTAL);

    // (1) prep: weight pack + zero f, xdbl, feat, xz
    prep_zero_kernel<<<(PZ_TOT + 255) / 256, 256>>>(conv_w, S);
    // (2) conv + relu + spatial sum (tensor cores)
    conv_tc_kernel<<<dim3(49, 32), 128, CONV_SMEM_TOTAL>>>(x, wTp, conv_b, f);
    // (3) fc + build_u fused  (64 x 2048 x 512, BM=64, act=3 writes u)
    gemm_tc64_kernel<<<dim3(32, 1, 1), 256>>>(f, 512, fc_w, fc_b, 3,
                                              u, DMODEL, 64, 2048, 512, 0);
    // (4) xz = u @ W_in^T  (128 x 8192 x 2048) — split-K=2 atomic (profiled slot)
    gemm_tc_kernel<<<dim3(128, 1, 2), 256>>>(u, 2048, W_in, nullptr, 0,
                                             xz, 8192, 128, 8192, 2048, 1);
    // (5) depthwise conv1d + silu
    conv1d_silu_kernel<<<1024, 256>>>(xz, c1w, c1b, xs);
    // (6) x_dbl = xs @ W_xproj^T  (128 x 160 x 4096) — split-K=16 atomic
    gemm_tc_kernel<<<dim3(3, 1, 16), 256>>>(xs, 4096, W_xproj, nullptr, 0,
                                            xdbl, 160, 128, 160, 4096, 1);
    // (7) dt = softplus(x_dbl[:, :128] @ W_dt^T + b_dt)  (128 x 4096 x 128)
    gemm_tc_kernel<<<dim3(64, 1, 1), 256>>>(xdbl, 160, W_dt, b_dt, 2,
                                            dtb, 4096, 128, 4096, 128, 0);
    // (8) scan + gating -> y
    scan_kernel<<<1024, 256>>>(xz, xs, xdbl, dtb, A_log, Dv, y);
    // (9) feat = y @ W_out^T  (64 x 2048 x 4096, BM=64, split-K=4 atomic)
    gemm_tc64_kernel<<<dim3(32, 1, 4), 256>>>(y, 4096, W_out, nullptr, 0,
                                              feat, 2048, 64, 2048, 4096, 1);
    // (10) heads
    heads_kernel<<<448, 128>>>(feat, wxyz, bxyz, wpqr, bpqr, out);
}